// round 11
// baseline (speedup 1.0000x reference)
#include <cuda_runtime.h>
#include <mma.h>
#include <math.h>
#include <stdint.h>

using namespace nvcuda;

// Shapes: B=8, L=64, S=2048, D=1024, C=1024, H=16, HD=64

// ---------------- device scratch ----------------
__device__ float g_ctx_r[16384 * 1024];
__device__ float g_lat_r[512 * 1024];
__device__ float g_Wq[1024 * 1024];
__device__ float g_Wkv[2048 * 1024];
__device__ float g_bq[1024];
__device__ float g_bkv[2048];
__device__ float g_qh[512 * 1024];
__device__ float g_kv[16384 * 2048];
__device__ float g_scores[8192 * 2048];     // raw masked/scaled scores
__device__ float g_cstat[8192 * 32];        // per (row, chunk16): (max, sumexp)
__device__ float g_rowstat[8192 * 2];       // per row: (max, 1/sum)
__device__ float g_part[4 * 512 * 1024];
__device__ float g_attn[512 * 1024];
__device__ float g_x[512 * 1024];
__device__ float g_xr[512 * 1024];
__device__ float g_h1[512 * 4096];

__device__ __forceinline__ float gelu_exact(float x) {
    return 0.5f * x * (1.0f + erff(x * 0.70710678118654752f));
}
__device__ __forceinline__ float rtf(float x) {
    float y;
    asm("cvt.rna.tf32.f32 %0, %1;" : "=f"(y) : "f"(x));
    return y;
}
__device__ __forceinline__ void cp16(uint32_t dst, const void* src) {
    asm volatile("cp.async.cg.shared.global [%0], [%1], 16;\n" ::"r"(dst), "l"(src));
}
#define CP_COMMIT() asm volatile("cp.async.commit_group;\n" ::)
#define CP_WAIT(n) asm volatile("cp.async.wait_group %0;\n" ::"n"(n))

// ==================== PROLOGUE: round ctx+lat + fuse_bias (merged) ===================
// blocks [0, 16896): segmented rounding; [16896, 19968): fuse_bias
__global__ void prologue_kernel(
    const float4* context, float4* ctx_r,
    const float4* latents4, float4* lat_r,
    const float* in_wq, const float* q_b, const float* in_bq,
    const float* in_wk, const float* k_b, const float* in_bk,
    const float* in_wv, const float* v_b, const float* in_bv,
    float* bq, float* bkv) {
    __shared__ float red[256];
    int bx = blockIdx.x, tid = threadIdx.x;
    if (bx < 16896) {
        int i = bx * 256 + tid;
        const float4* s;
        float4* d;
        int off;
        if (i < 4194304) { s = context; d = ctx_r; off = i; }
        else { i -= 4194304; s = latents4; d = lat_r; off = i; }
        float4 v = s[off];
        v.x = rtf(v.x); v.y = rtf(v.y); v.z = rtf(v.z); v.w = rtf(v.w);
        d[off] = v;
    } else {
        int idx = bx - 16896;
        int z = idx >> 10, o = idx & 1023;
        const float* W = (z == 0) ? in_wq : (z == 1) ? in_wk : in_wv;
        const float* bin = (z == 0) ? q_b : (z == 1) ? k_b : v_b;
        const float* badd = (z == 0) ? in_bq : (z == 1) ? in_bk : in_bv;
        float* bout = (z == 0) ? bq : (z == 1) ? bkv : (bkv + 1024);
        float s = 0.f;
        for (int i = tid; i < 1024; i += 256) s += W[o * 1024 + i] * bin[i];
        red[tid] = s;
        __syncthreads();
        for (int st = 128; st > 0; st >>= 1) {
            if (tid < st) red[tid] += red[tid + st];
            __syncthreads();
        }
        if (tid == 0) bout[o] = red[0] + badd[o];
    }
}

// ==================== weight-fusion GEMM 128x128 NN (in-fragment cvt) ================
__device__ __forceinline__ void fuse_body(const float* __restrict__ A, const float* __restrict__ B,
                                          float* __restrict__ C, float* sm) {
    const int N = 1024, K = 1024;
    int tid = threadIdx.x;
    int wid = tid >> 5, lane = tid & 31;
    int warpRow = wid >> 2, warpCol = wid & 3;
    int bm = blockIdx.y * 128, bn = blockIdx.x * 128;

    uint32_t s_base = (uint32_t)__cvta_generic_to_shared(sm);
    int ra = tid >> 3, ca = (tid & 7) * 4;
    int kb = tid >> 5, cb = (tid & 31) * 4;

    wmma::fragment<wmma::accumulator, 16, 16, 8, float> acc[4][2];
#pragma unroll
    for (int i = 0; i < 4; ++i)
#pragma unroll
        for (int j = 0; j < 2; ++j) wmma::fill_fragment(acc[i][j], 0.0f);

    const int KT = K >> 5;
    auto issue = [&](int stage, int k0) {
        uint32_t as = s_base + (uint32_t)(stage * 4608) * 4;
        uint32_t bs = s_base + (uint32_t)(9216 + stage * 5120) * 4;
#pragma unroll
        for (int it = 0; it < 4; ++it) {
            int r = ra + it * 32;
            cp16(as + (uint32_t)(r * 36 + ca) * 4, A + (size_t)(bm + r) * K + k0 + ca);
        }
#pragma unroll
        for (int it = 0; it < 4; ++it) {
            int kk = kb + it * 8;
            cp16(bs + (uint32_t)(kk * 136 + cb) * 4, B + (size_t)(k0 + kk) * N + bn + cb);
        }
        CP_COMMIT();
    };

    issue(0, 0);
    for (int kt = 0; kt < KT; ++kt) {
        int stage = kt & 1;
        if (kt + 1 < KT) {
            issue(stage ^ 1, (kt + 1) * 32);
            CP_WAIT(1);
        } else {
            CP_WAIT(0);
        }
        __syncthreads();
        float* As = sm + stage * 4608;
        float* Bs = sm + 9216 + stage * 5120;
#pragma unroll
        for (int ks = 0; ks < 4; ++ks) {
            int kk = ks * 8;
            wmma::fragment<wmma::matrix_a, 16, 16, 8, wmma::precision::tf32, wmma::row_major> af[4];
#pragma unroll
            for (int i = 0; i < 4; ++i) {
                wmma::load_matrix_sync(af[i], &As[(warpRow * 64 + i * 16) * 36 + kk], 36);
#pragma unroll
                for (int t = 0; t < af[i].num_elements; ++t)
                    af[i].x[t] = wmma::__float_to_tf32(af[i].x[t]);
            }
            wmma::fragment<wmma::matrix_b, 16, 16, 8, wmma::precision::tf32, wmma::row_major> bf[2];
#pragma unroll
            for (int j = 0; j < 2; ++j) {
                wmma::load_matrix_sync(bf[j], &Bs[kk * 136 + warpCol * 32 + j * 16], 136);
#pragma unroll
                for (int t = 0; t < bf[j].num_elements; ++t)
                    bf[j].x[t] = wmma::__float_to_tf32(bf[j].x[t]);
            }
#pragma unroll
            for (int i = 0; i < 4; ++i)
#pragma unroll
                for (int j = 0; j < 2; ++j) wmma::mma_sync(acc[i][j], af[i], bf[j], acc[i][j]);
        }
        __syncthreads();
    }

    float* st = &sm[wid * 384];
#pragma unroll
    for (int i = 0; i < 4; ++i) {
#pragma unroll
        for (int j = 0; j < 2; ++j) {
            wmma::store_matrix_sync(st, acc[i][j], 24, wmma::mem_row_major);
            __syncwarp();
            int row0 = bm + warpRow * 64 + i * 16;
            int col0 = bn + warpCol * 32 + j * 16;
            int r = lane >> 1, c8 = (lane & 1) * 8;
            float4 v0 = *(float4*)&st[r * 24 + c8];
            float4 v1 = *(float4*)&st[r * 24 + c8 + 4];
            v0.x = rtf(v0.x); v0.y = rtf(v0.y); v0.z = rtf(v0.z); v0.w = rtf(v0.w);
            v1.x = rtf(v1.x); v1.y = rtf(v1.y); v1.z = rtf(v1.z); v1.w = rtf(v1.w);
            float* cp = C + (size_t)(row0 + r) * N + col0 + c8;
            *(float4*)cp = v0;
            *(float4*)(cp + 4) = v1;
            __syncwarp();
        }
    }
}

__global__ void __launch_bounds__(256, 2)
wmma_gemm_fuse3(const float* A0, const float* B0, float* C0,
                const float* A1, const float* B1, float* C1,
                const float* A2, const float* B2, float* C2) {
    extern __shared__ float sm[];
    if (blockIdx.z == 0) fuse_body(A0, B0, C0, sm);
    else if (blockIdx.z == 1) fuse_body(A1, B1, C1, sm);
    else fuse_body(A2, B2, C2, sm);
}

// ==================== small GEMM body: 64x128 NT, 3-stage, ld 36 =====================
// smem: A stages 3x2304 @0, B stages 3x4608 @6912 => 20736 fl = 82944 B
template <int EPI, int BIAS, int RND, int CVTB>
__device__ __forceinline__ void small_body(const float* __restrict__ A, const float* __restrict__ B,
                                           const float* __restrict__ bias, float* __restrict__ C,
                                           int N, int K, int bm, int bn, float* sm) {
    int tid = threadIdx.x;
    int wid = tid >> 5, lane = tid & 31;
    int warpRow = wid >> 2, warpCol = wid & 3;

    uint32_t s_base = (uint32_t)__cvta_generic_to_shared(sm);
    int ra = tid >> 3, ca = (tid & 7) * 4;

    wmma::fragment<wmma::accumulator, 16, 16, 8, float> acc[2][2];
#pragma unroll
    for (int i = 0; i < 2; ++i)
#pragma unroll
        for (int j = 0; j < 2; ++j) wmma::fill_fragment(acc[i][j], 0.0f);

    const int KT = K >> 5;
    auto issue = [&](int stage, int k0) {
        uint32_t as = s_base + (uint32_t)(stage * 2304) * 4;
        uint32_t bs = s_base + (uint32_t)(6912 + stage * 4608) * 4;
#pragma unroll
        for (int it = 0; it < 2; ++it) {
            int r = ra + it * 32;
            cp16(as + (uint32_t)(r * 36 + ca) * 4, A + (size_t)(bm + r) * K + k0 + ca);
        }
#pragma unroll
        for (int it = 0; it < 4; ++it) {
            int r = ra + it * 32;
            cp16(bs + (uint32_t)(r * 36 + ca) * 4, B + (size_t)(bn + r) * K + k0 + ca);
        }
        CP_COMMIT();
    };

    issue(0, 0);
    if (KT > 1) issue(1, 32);
    for (int kt = 0; kt < KT; ++kt) {
        if (kt + 1 < KT) CP_WAIT(1);
        else CP_WAIT(0);
        __syncthreads();
        if (kt + 2 < KT) issue((kt + 2) % 3, (kt + 2) * 32);
        int stage = kt % 3;
        float* As = sm + stage * 2304;
        float* Bs = sm + 6912 + stage * 4608;
#pragma unroll
        for (int ks = 0; ks < 4; ++ks) {
            int kk = ks * 8;
            wmma::fragment<wmma::matrix_a, 16, 16, 8, wmma::precision::tf32, wmma::row_major> af[2];
            wmma::fragment<wmma::matrix_b, 16, 16, 8, wmma::precision::tf32, wmma::col_major> bf[2];
#pragma unroll
            for (int i = 0; i < 2; ++i)
                wmma::load_matrix_sync(af[i], &As[(warpRow * 32 + i * 16) * 36 + kk], 36);
#pragma unroll
            for (int j = 0; j < 2; ++j) {
                wmma::load_matrix_sync(bf[j], &Bs[(warpCol * 32 + j * 16) * 36 + kk], 36);
                if (CVTB) {
#pragma unroll
                    for (int t = 0; t < bf[j].num_elements; ++t)
                        bf[j].x[t] = wmma::__float_to_tf32(bf[j].x[t]);
                }
            }
#pragma unroll
            for (int i = 0; i < 2; ++i)
#pragma unroll
                for (int j = 0; j < 2; ++j) wmma::mma_sync(acc[i][j], af[i], bf[j], acc[i][j]);
        }
    }
    __syncthreads();

    float* st = &sm[wid * 384];
#pragma unroll
    for (int i = 0; i < 2; ++i) {
#pragma unroll
        for (int j = 0; j < 2; ++j) {
            wmma::store_matrix_sync(st, acc[i][j], 24, wmma::mem_row_major);
            __syncwarp();
            int row0 = bm + warpRow * 32 + i * 16;
            int col0 = bn + warpCol * 32 + j * 16;
            int r = lane >> 1, c8 = (lane & 1) * 8;
            float4 v0 = *(float4*)&st[r * 24 + c8];
            float4 v1 = *(float4*)&st[r * 24 + c8 + 4];
            if (BIAS) {
                const float* bp = bias + col0 + c8;
                v0.x += bp[0]; v0.y += bp[1]; v0.z += bp[2]; v0.w += bp[3];
                v1.x += bp[4]; v1.y += bp[5]; v1.z += bp[6]; v1.w += bp[7];
            }
            if (EPI) {
                v0.x = gelu_exact(v0.x); v0.y = gelu_exact(v0.y);
                v0.z = gelu_exact(v0.z); v0.w = gelu_exact(v0.w);
                v1.x = gelu_exact(v1.x); v1.y = gelu_exact(v1.y);
                v1.z = gelu_exact(v1.z); v1.w = gelu_exact(v1.w);
            }
            if (RND) {
                v0.x = rtf(v0.x); v0.y = rtf(v0.y); v0.z = rtf(v0.z); v0.w = rtf(v0.w);
                v1.x = rtf(v1.x); v1.y = rtf(v1.y); v1.z = rtf(v1.z); v1.w = rtf(v1.w);
            }
            float* cp = C + (size_t)(row0 + r) * N + col0 + c8;
            *(float4*)cp = v0;
            *(float4*)(cp + 4) = v1;
            __syncwarp();
        }
    }
}

template <int EPI, int BIAS, int RND, int CVTB>
__global__ void __launch_bounds__(256, 2)
wmma_gemm_small(const float* __restrict__ A, const float* __restrict__ B,
                const float* __restrict__ bias, float* __restrict__ C,
                int M, int N, int K) {
    extern __shared__ float sm[];
    small_body<EPI, BIAS, RND, CVTB>(A, B, bias, C, N, K, blockIdx.y * 64, blockIdx.x * 128, sm);
}

// ==================== kv GEMM body: 128x256 NT, 3-stage, ld 36 =======================
// smem: A stages 3x4608 @0, B stages 3x9216 @13824 => 41472 fl = 165888 B
__device__ __forceinline__ void kv_body(const float* __restrict__ A, const float* __restrict__ B,
                                        const float* __restrict__ bias, float* __restrict__ C,
                                        int bm, int bn, float* sm) {
    const int N = 2048, K = 1024;
    int tid = threadIdx.x;
    int wid = tid >> 5, lane = tid & 31;
    int warpRow = wid >> 2, warpCol = wid & 3;

    uint32_t s_base = (uint32_t)__cvta_generic_to_shared(sm);
    int ra = tid >> 3, ca = (tid & 7) * 4;

    wmma::fragment<wmma::accumulator, 16, 16, 8, float> acc[4][4];
#pragma unroll
    for (int i = 0; i < 4; ++i)
#pragma unroll
        for (int j = 0; j < 4; ++j) wmma::fill_fragment(acc[i][j], 0.0f);

    const int KT = K >> 5;
    auto issue = [&](int stage, int k0) {
        uint32_t as = s_base + (uint32_t)(stage * 4608) * 4;
        uint32_t bs = s_base + (uint32_t)(13824 + stage * 9216) * 4;
#pragma unroll
        for (int it = 0; it < 4; ++it) {
            int r = ra + it * 32;
            cp16(as + (uint32_t)(r * 36 + ca) * 4, A + (size_t)(bm + r) * K + k0 + ca);
        }
#pragma unroll
        for (int it = 0; it < 8; ++it) {
            int r = ra + it * 32;
            cp16(bs + (uint32_t)(r * 36 + ca) * 4, B + (size_t)(bn + r) * K + k0 + ca);
        }
        CP_COMMIT();
    };

    issue(0, 0);
    issue(1, 32);
    for (int kt = 0; kt < KT; ++kt) {
        if (kt + 1 < KT) CP_WAIT(1);
        else CP_WAIT(0);
        __syncthreads();
        if (kt + 2 < KT) issue((kt + 2) % 3, (kt + 2) * 32);
        int stage = kt % 3;
        float* As = sm + stage * 4608;
        float* Bs = sm + 13824 + stage * 9216;
#pragma unroll
        for (int ks = 0; ks < 4; ++ks) {
            int kk = ks * 8;
            wmma::fragment<wmma::matrix_a, 16, 16, 8, wmma::precision::tf32, wmma::row_major> af[4];
            wmma::fragment<wmma::matrix_b, 16, 16, 8, wmma::precision::tf32, wmma::col_major> bf[4];
#pragma unroll
            for (int i = 0; i < 4; ++i)
                wmma::load_matrix_sync(af[i], &As[(warpRow * 64 + i * 16) * 36 + kk], 36);
#pragma unroll
            for (int j = 0; j < 4; ++j)
                wmma::load_matrix_sync(bf[j], &Bs[(warpCol * 64 + j * 16) * 36 + kk], 36);
#pragma unroll
            for (int i = 0; i < 4; ++i)
#pragma unroll
                for (int j = 0; j < 4; ++j) wmma::mma_sync(acc[i][j], af[i], bf[j], acc[i][j]);
        }
    }
    __syncthreads();

    float* st = &sm[wid * 384];
#pragma unroll
    for (int i = 0; i < 4; ++i) {
#pragma unroll
        for (int j = 0; j < 4; ++j) {
            wmma::store_matrix_sync(st, acc[i][j], 24, wmma::mem_row_major);
            __syncwarp();
            int row0 = bm + warpRow * 64 + i * 16;
            int col0 = bn + warpCol * 64 + j * 16;
            int r = lane >> 1, c8 = (lane & 1) * 8;
            float4 v0 = *(float4*)&st[r * 24 + c8];
            float4 v1 = *(float4*)&st[r * 24 + c8 + 4];
            const float* bp = bias + col0 + c8;
            v0.x = rtf(v0.x + bp[0]); v0.y = rtf(v0.y + bp[1]);
            v0.z = rtf(v0.z + bp[2]); v0.w = rtf(v0.w + bp[3]);
            v1.x = rtf(v1.x + bp[4]); v1.y = rtf(v1.y + bp[5]);
            v1.z = rtf(v1.z + bp[6]); v1.w = rtf(v1.w + bp[7]);
            float* cp = C + (size_t)(row0 + r) * N + col0 + c8;
            *(float4*)cp = v0;
            *(float4*)(cp + 4) = v1;
            __syncwarp();
        }
    }
}

// G1: kv GEMM (blocks 0..1023) + q projection (blocks 1024..1087)
__global__ void __launch_bounds__(256, 1)
g1_kernel(const float* ctx_r, const float* Wkv, const float* bkv, float* kvb,
          const float* lat_r, const float* Wq, const float* bq, float* qh) {
    extern __shared__ float sm[];
    int bx = blockIdx.x;
    if (bx < 1024) {
        kv_body(ctx_r, Wkv, bkv, kvb, (bx >> 3) * 128, (bx & 7) * 256, sm);
    } else {
        int idx = bx - 1024;
        small_body<0, 1, 1, 0>(lat_r, Wq, bq, qh, 1024, 1024, (idx >> 3) * 64, (idx & 7) * 128, sm);
    }
}

// ==================== scores: [64,128]-tile of Q K^T / 8, masked + chunk stats =======
__global__ void __launch_bounds__(256)
scores_wmma(const float* __restrict__ qh, const float* __restrict__ kv,
            const int* __restrict__ cmask, float* __restrict__ scores,
            float* __restrict__ cstat) {
    extern __shared__ float sm[];
    float* Qs = sm;
    float* Ks = sm + 4352;
    int bh = blockIdx.y;
    int b = bh >> 4, h = bh & 15;
    int s0 = blockIdx.x * 128;
    int tid = threadIdx.x, wid = tid >> 5, lane = tid & 31;

#pragma unroll
    for (int it = 0; it < 4; ++it) {
        int v = tid + it * 256;
        int r = v >> 4, c = (v & 15) * 4;
        *(float4*)&Qs[r * 68 + c] = *(const float4*)(qh + (size_t)(b * 64 + r) * 1024 + h * 64 + c);
    }
#pragma unroll
    for (int it = 0; it < 8; ++it) {
        int v = tid + it * 256;
        int r = v >> 4, c = (v & 15) * 4;
        *(float4*)&Ks[r * 68 + c] =
            *(const float4*)(kv + (size_t)(b * 2048 + s0 + r) * 2048 + h * 64 + c);
    }
    __syncthreads();

    int warpRow = wid >> 2, warpCol = wid & 3;
    wmma::fragment<wmma::accumulator, 16, 16, 8, float> acc[2][2];
#pragma unroll
    for (int i = 0; i < 2; ++i)
#pragma unroll
        for (int j = 0; j < 2; ++j) wmma::fill_fragment(acc[i][j], 0.0f);

#pragma unroll
    for (int ks = 0; ks < 8; ++ks) {
        int kk = ks * 8;
        wmma::fragment<wmma::matrix_a, 16, 16, 8, wmma::precision::tf32, wmma::row_major> af[2];
        wmma::fragment<wmma::matrix_b, 16, 16, 8, wmma::precision::tf32, wmma::col_major> bf[2];
#pragma unroll
        for (int i = 0; i < 2; ++i)
            wmma::load_matrix_sync(af[i], &Qs[(warpRow * 32 + i * 16) * 68 + kk], 68);
#pragma unroll
        for (int j = 0; j < 2; ++j)
            wmma::load_matrix_sync(bf[j], &Ks[(warpCol * 32 + j * 16) * 68 + kk], 68);
#pragma unroll
        for (int i = 0; i < 2; ++i)
#pragma unroll
            for (int j = 0; j < 2; ++j) wmma::mma_sync(acc[i][j], af[i], bf[j], acc[i][j]);
    }
    __syncthreads();

    const float NEG = __int_as_float(0xff800000);
    float* st = &sm[wid * 384];
    float* pm = sm + 3072;   // [64][4]
    float* ps = sm + 3328;   // [64][4]
#pragma unroll
    for (int i = 0; i < 2; ++i) {
        int r = lane >> 1, c8 = (lane & 1) * 8;
        int l = warpRow * 32 + i * 16 + r;
        float4 v0, v1, v2, v3;
        wmma::store_matrix_sync(st, acc[i][0], 24, wmma::mem_row_major);
        __syncwarp();
        v0 = *(float4*)&st[r * 24 + c8];
        v1 = *(float4*)&st[r * 24 + c8 + 4];
        __syncwarp();
        wmma::store_matrix_sync(st, acc[i][1], 24, wmma::mem_row_major);
        __syncwarp();
        v2 = *(float4*)&st[r * 24 + c8];
        v3 = *(float4*)&st[r * 24 + c8 + 4];
        __syncwarp();
        int sg0 = s0 + warpCol * 32 + c8;
        int sg1 = sg0 + 16;
        const int* mp0 = cmask + b * 2048 + sg0;
        const int* mp1 = cmask + b * 2048 + sg1;
        v0.x = mp0[0] ? v0.x * 0.125f : NEG;
        v0.y = mp0[1] ? v0.y * 0.125f : NEG;
        v0.z = mp0[2] ? v0.z * 0.125f : NEG;
        v0.w = mp0[3] ? v0.w * 0.125f : NEG;
        v1.x = mp0[4] ? v1.x * 0.125f : NEG;
        v1.y = mp0[5] ? v1.y * 0.125f : NEG;
        v1.z = mp0[6] ? v1.z * 0.125f : NEG;
        v1.w = mp0[7] ? v1.w * 0.125f : NEG;
        v2.x = mp1[0] ? v2.x * 0.125f : NEG;
        v2.y = mp1[1] ? v2.y * 0.125f : NEG;
        v2.z = mp1[2] ? v2.z * 0.125f : NEG;
        v2.w = mp1[3] ? v2.w * 0.125f : NEG;
        v3.x = mp1[4] ? v3.x * 0.125f : NEG;
        v3.y = mp1[5] ? v3.y * 0.125f : NEG;
        v3.z = mp1[6] ? v3.z * 0.125f : NEG;
        v3.w = mp1[7] ? v3.w * 0.125f : NEG;
        float* pp = scores + ((size_t)bh * 64 + l) * 2048 + sg0;
        *(float4*)pp = v0;
        *(float4*)(pp + 4) = v1;
        *(float4*)(pp + 16) = v2;
        *(float4*)(pp + 20) = v3;
        float mx = fmaxf(fmaxf(fmaxf(v0.x, v0.y), fmaxf(v0.z, v0.w)),
                         fmaxf(fmaxf(v1.x, v1.y), fmaxf(v1.z, v1.w)));
        mx = fmaxf(mx, fmaxf(fmaxf(fmaxf(v2.x, v2.y), fmaxf(v2.z, v2.w)),
                             fmaxf(fmaxf(v3.x, v3.y), fmaxf(v3.z, v3.w))));
        float m2 = fmaxf(mx, __shfl_xor_sync(0xffffffffu, mx, 1));
        float m2c = fmaxf(m2, -1e30f);
        float s = expf(v0.x - m2c) + expf(v0.y - m2c) + expf(v0.z - m2c) + expf(v0.w - m2c) +
                  expf(v1.x - m2c) + expf(v1.y - m2c) + expf(v1.z - m2c) + expf(v1.w - m2c) +
                  expf(v2.x - m2c) + expf(v2.y - m2c) + expf(v2.z - m2c) + expf(v2.w - m2c) +
                  expf(v3.x - m2c) + expf(v3.y - m2c) + expf(v3.z - m2c) + expf(v3.w - m2c);
        s += __shfl_xor_sync(0xffffffffu, s, 1);
        if ((lane & 1) == 0) {
            pm[l * 4 + warpCol] = m2;
            ps[l * 4 + warpCol] = s;
        }
    }
    __syncthreads();
    if (tid < 64) {
        float m0 = pm[tid * 4], m1 = pm[tid * 4 + 1], m2 = pm[tid * 4 + 2], m3 = pm[tid * 4 + 3];
        float m = fmaxf(fmaxf(m0, m1), fmaxf(m2, m3));
        float mc = fmaxf(m, -1e30f);
        float S = ps[tid * 4] * expf(m0 - mc) + ps[tid * 4 + 1] * expf(m1 - mc) +
                  ps[tid * 4 + 2] * expf(m2 - mc) + ps[tid * 4 + 3] * expf(m3 - mc);
        float2 o;
        o.x = m;
        o.y = S;
        *(float2*)&cstat[(((size_t)bh * 64 + tid) * 16 + blockIdx.x) * 2] = o;
    }
}

// ---------------- rowstat: fold 16 chunk stats -> (max, 1/sum) per row ----------------
__global__ void rowstat_kernel(const float* __restrict__ cstat, float* __restrict__ rowstat) {
    int row = blockIdx.x * 256 + threadIdx.x;
    const float2* c = (const float2*)cstat + row * 16;
    float M = __int_as_float(0xff800000);
#pragma unroll
    for (int k = 0; k < 16; ++k) M = fmaxf(M, c[k].x);
    float Mc = fmaxf(M, -1e30f);
    float S = 0.f;
#pragma unroll
    for (int k = 0; k < 16; ++k) S += c[k].y * expf(c[k].x - Mc);
    float2 o;
    o.x = Mc;
    o.y = 1.0f / S;
    ((float2*)rowstat)[row] = o;
}

// ==================== attn split-K body: inline softmax on staged P tile ==============
__device__ __forceinline__ void attn_body(const float* __restrict__ scores,
                                          const float* __restrict__ kv,
                                          const float* __restrict__ rowstat,
                                          float* __restrict__ part,
                                          int bh, int split, float* sm) {
    int b = bh >> 4, h = bh & 15;
    int base_s = split * 512;
    int tid = threadIdx.x, wid = tid >> 5, lane = tid & 31;
    int warpRow = wid >> 1, warpCol = wid & 1;

    uint32_t s_base = (uint32_t)__cvta_generic_to_shared(sm);
    int ra = tid >> 4, ca = (tid & 15) * 4;
    float* rs_m = sm + 26112;
    float* rs_i = sm + 26176;
    if (tid < 64) {
        float2 v = ((const float2*)rowstat)[bh * 64 + tid];
        rs_m[tid] = v.x;
        rs_i[tid] = v.y;
    }

    wmma::fragment<wmma::accumulator, 16, 16, 8, float> acc[2];
    wmma::fill_fragment(acc[0], 0.0f);
    wmma::fill_fragment(acc[1], 0.0f);

    auto issue = [&](int stage, int s0) {
        uint32_t ps = s_base + (uint32_t)(stage * 4352) * 4;
        uint32_t vs = s_base + (uint32_t)(13056 + stage * 4352) * 4;
#pragma unroll
        for (int it = 0; it < 4; ++it) {
            int r = ra + it * 16;
            cp16(ps + (uint32_t)(r * 68 + ca) * 4,
                 scores + ((size_t)bh * 64 + r) * 2048 + s0 + ca);
            cp16(vs + (uint32_t)(r * 68 + ca) * 4,
                 kv + (size_t)(b * 2048 + s0 + r) * 2048 + 1024 + h * 64 + ca);
        }
        CP_COMMIT();
    };

    issue(0, base_s);
    issue(1, base_s + 64);
    for (int kt = 0; kt < 8; ++kt) {
        if (kt + 1 < 8) CP_WAIT(1);
        else CP_WAIT(0);
        __syncthreads();
        int stage = kt % 3;
        float* Ps = sm + stage * 4352;
#pragma unroll
        for (int it = 0; it < 4; ++it) {
            int rr = ra + it * 16;
            float M = rs_m[rr], I = rs_i[rr];
            float4 v = *(float4*)&Ps[rr * 68 + ca];
            v.x = rtf(expf(v.x - M) * I);
            v.y = rtf(expf(v.y - M) * I);
            v.z = rtf(expf(v.z - M) * I);
            v.w = rtf(expf(v.w - M) * I);
            *(float4*)&Ps[rr * 68 + ca] = v;
        }
        __syncthreads();
        if (kt + 2 < 8) issue((kt + 2) % 3, base_s + (kt + 2) * 64);
        float* Vs = sm + 13056 + stage * 4352;
#pragma unroll
        for (int ks = 0; ks < 8; ++ks) {
            int kk = ks * 8;
            wmma::fragment<wmma::matrix_a, 16, 16, 8, wmma::precision::tf32, wmma::row_major> af;
            wmma::fragment<wmma::matrix_b, 16, 16, 8, wmma::precision::tf32, wmma::row_major> bf[2];
            wmma::load_matrix_sync(af, &Ps[(warpRow * 16) * 68 + kk], 68);
#pragma unroll
            for (int j = 0; j < 2; ++j)
                wmma::load_matrix_sync(bf[j], &Vs[kk * 68 + warpCol * 32 + j * 16], 68);
            wmma::mma_sync(acc[0], af, bf[0], acc[0]);
            wmma::mma_sync(acc[1], af, bf[1], acc[1]);
        }
    }
    __syncthreads();

    float* pout = part + (size_t)split * 524288;
    float* st = &sm[wid * 384];
#pragma unroll
    for (int j = 0; j < 2; ++j) {
        wmma::store_matrix_sync(st, acc[j], 24, wmma::mem_row_major);
        __syncwarp();
        int r = lane >> 1, c8 = (lane & 1) * 8;
        int l = warpRow * 16 + r;
        int d0 = warpCol * 32 + j * 16 + c8;
        float4 v0 = *(float4*)&st[r * 24 + c8];
        float4 v1 = *(float4*)&st[r * 24 + c8 + 4];
        float* ap = pout + (size_t)(b * 64 + l) * 1024 + h * 64 + d0;
        *(float4*)ap = v0;
        *(float4*)(ap + 4) = v1;
        __syncwarp();
    }
}

// A1: attn_part (blocks 0..511) + mean_heads with inline softmax (blocks 512..1535)
__global__ void __launch_bounds__(256, 2)
a1_kernel(const float* __restrict__ scores, const float* __restrict__ kv,
          const float* __restrict__ rowstat, float* __restrict__ part,
          float* __restrict__ aw) {
    extern __shared__ float sm[];
    int bx = blockIdx.x;
    if (bx < 512) {
        attn_body(scores, kv, rowstat, part, bx >> 2, bx & 3, sm);
    } else {
        int i = (bx - 512) * 256 + threadIdx.x;
        int s4 = i & 511;
        int l = (i >> 9) & 63;
        int b = i >> 15;
        float4 acc = {0.f, 0.f, 0.f, 0.f};
#pragma unroll
        for (int h = 0; h < 16; ++h) {
            size_t row = (size_t)(b * 16 + h) * 64 + l;
            float2 stt = ((const float2*)rowstat)[row];
            float4 x = *(const float4*)(scores + row * 2048 + s4 * 4);
            acc.x += expf(x.x - stt.x) * stt.y;
            acc.y += expf(x.y - stt.x) * stt.y;
            acc.z += expf(x.z - stt.x) * stt.y;
            acc.w += expf(x.w - stt.x) * stt.y;
        }
        const float inv = 1.0f / 16.0f;
        acc.x *= inv; acc.y *= inv; acc.z *= inv; acc.w *= inv;
        *(float4*)(aw + ((size_t)(b * 64 + l) * 2048) + s4 * 4) = acc;
    }
}

// reduce 4 partials -> attn (tf32-rounded)
__global__ void attn_reduce_kernel(const float* __restrict__ part, float* __restrict__ attn) {
    int i = blockIdx.x * 256 + threadIdx.x;
    float4 a = ((const float4*)part)[i];
    float4 b = ((const float4*)(part + 524288))[i];
    float4 c = ((const float4*)(part + 1048576))[i];
    float4 d = ((const float4*)(part + 1572864))[i];
    float4 o;
    o.x = rtf(((a.x + b.x) + (c.x + d.x)));
    o.y = rtf(((a.y + b.y) + (c.y + d.y)));
    o.z = rtf(((a.z + b.z) + (c.z + d.z)));
    o.w = rtf(((a.w + b.w) + (c.w + d.w)));
    ((float4*)attn)[i] = o;
}

// ---------------- residual add + LayerNorm (optional rounded copy) ----------------
template <int WR>
__global__ void add_ln_kernel(const float* __restrict__ a, const float* __restrict__ b2,
                              const float* __restrict__ g, const float* __restrict__ bet,
                              float* __restrict__ out, float* __restrict__ out_r) {
    int row = blockIdx.x, tid = threadIdx.x;
    const float4* a4 = (const float4*)(a + (size_t)row * 1024);
    const float4* b4 = (const float4*)(b2 + (size_t)row * 1024);
    float4 va = a4[tid], vb = b4[tid];
    float4 x;
    x.x = va.x + vb.x; x.y = va.y + vb.y; x.z = va.z + vb.z; x.w = va.w + vb.w;
    float s = (x.x + x.y) + (x.z + x.w);
    float sq = x.x * x.x + x.y * x.y + x.z * x.z + x.w * x.w;
    __shared__ float r1[256], r2[256];
    r1[tid] = s; r2[tid] = sq;
    __syncthreads();
    for (int st = 128; st > 0; st >>= 1) {
        if (tid < st) { r1[tid] += r1[tid + st]; r2[tid] += r2[tid + st]; }
        __syncthreads();
    }
    float mean = r1[0] * (1.0f / 1024.0f);
    float var = r2[0] * (1.0f / 1024.0f) - mean * mean;
    float rstd = rsqrtf(var + 1e-5f);
    float4 gg = ((const float4*)g)[tid], bb = ((const float4*)bet)[tid];
    float4 o;
    o.x = (x.x - mean) * rstd * gg.x + bb.x;
    o.y = (x.y - mean) * rstd * gg.y + bb.y;
    o.z = (x.z - mean) * rstd * gg.z + bb.z;
    o.w = (x.w - mean) * rstd * gg.w + bb.w;
    ((float4*)(out + (size_t)row * 1024))[tid] = o;
    if (WR) {
        float4 q;
        q.x = rtf(o.x); q.y = rtf(o.y); q.z = rtf(o.z); q.w = rtf(o.w);
        ((float4*)(out_r + (size_t)row * 1024))[tid] = q;
    }
}

// ---------------- launch ----------------
extern "C" void kernel_launch(void* const* d_in, const int* in_sizes, int n_in,
                              void* d_out, int out_size) {
    (void)in_sizes; (void)n_in; (void)out_size;
    const float* latents = (const float*)d_in[0];
    const float* context = (const float*)d_in[1];
    const int* cmask = (const int*)d_in[2];
    const float* q_w = (const float*)d_in[3];
    const float* q_b = (const float*)d_in[4];
    const float* k_w = (const float*)d_in[5];
    const float* k_b = (const float*)d_in[6];
    const float* v_w = (const float*)d_in[7];
    const float* v_b = (const float*)d_in[8];
    const float* in_wq = (const float*)d_in[9];
    const float* in_bq = (const float*)d_in[10];
    const float* in_wk = (const float*)d_in[11];
    const float* in_bk = (const float*)d_in[12];
    const float* in_wv = (const float*)d_in[13];
    const float* in_bv = (const float*)d_in[14];
    const float* out_w = (const float*)d_in[15];
    const float* out_b = (const float*)d_in[16];
    const float* ln1_g = (const float*)d_in[17];
    const float* ln1_b = (const float*)d_in[18];
    const float* ln2_g = (const float*)d_in[19];
    const float* ln2_b = (const float*)d_in[20];
    const float* ff_w1 = (const float*)d_in[21];
    const float* ff_b1 = (const float*)d_in[22];
    const float* ff_w2 = (const float*)d_in[23];
    const float* ff_b2 = (const float*)d_in[24];

    float* out = (float*)d_out;
    float* aw_out = out + 512 * 1024;

    void* p;
    cudaGetSymbolAddress(&p, g_ctx_r);   float* ctx_r = (float*)p;
    cudaGetSymbolAddress(&p, g_lat_r);   float* lat_r = (float*)p;
    cudaGetSymbolAddress(&p, g_Wq);      float* Wq = (float*)p;
    cudaGetSymbolAddress(&p, g_Wkv);     float* Wkv = (float*)p;
    cudaGetSymbolAddress(&p, g_bq);      float* bq = (float*)p;
    cudaGetSymbolAddress(&p, g_bkv);     float* bkv = (float*)p;
    cudaGetSymbolAddress(&p, g_qh);      float* qh = (float*)p;
    cudaGetSymbolAddress(&p, g_kv);      float* kvb = (float*)p;
    cudaGetSymbolAddress(&p, g_scores);  float* scores = (float*)p;
    cudaGetSymbolAddress(&p, g_cstat);   float* cstat = (float*)p;
    cudaGetSymbolAddress(&p, g_rowstat); float* rowstat = (float*)p;
    cudaGetSymbolAddress(&p, g_part);    float* part = (float*)p;
    cudaGetSymbolAddress(&p, g_attn);    float* attn = (float*)p;
    cudaGetSymbolAddress(&p, g_x);       float* xb = (float*)p;
    cudaGetSymbolAddress(&p, g_xr);      float* xr = (float*)p;
    cudaGetSymbolAddress(&p, g_h1);      float* h1 = (float*)p;

    cudaFuncSetAttribute(wmma_gemm_fuse3, cudaFuncAttributeMaxDynamicSharedMemorySize, 77824);
    cudaFuncSetAttribute(wmma_gemm_small<0, 1, 0, 1>, cudaFuncAttributeMaxDynamicSharedMemorySize, 82944);
    cudaFuncSetAttribute(wmma_gemm_small<1, 1, 1, 1>, cudaFuncAttributeMaxDynamicSharedMemorySize, 82944);
    cudaFuncSetAttribute(g1_kernel, cudaFuncAttributeMaxDynamicSharedMemorySize, 165888);
    cudaFuncSetAttribute(scores_wmma, cudaFuncAttributeMaxDynamicSharedMemorySize, 52224);
    cudaFuncSetAttribute(a1_kernel, cudaFuncAttributeMaxDynamicSharedMemorySize, 104960);

    // ---- merged prologue: round ctx+lat + fused biases ----
    prologue_kernel<<<19968, 256>>>(
        (const float4*)context, (float4*)ctx_r,
        (const float4*)latents, (float4*)lat_r,
        in_wq, q_b, in_bq, in_wk, k_b, in_bk, in_wv, v_b, in_bv, bq, bkv);

    // ---- fused weights (in-fragment tf32 cvt on raw inputs) ----
    const size_t MM = 1024 * 1024;
    wmma_gemm_fuse3<<<dim3(8, 8, 3), 256, 77824>>>(
        in_wq, q_w, Wq,
        in_wk, k_w, Wkv,
        in_wv, v_w, Wkv + MM);

    // ---- G1: kv projection + q projection (merged) ----
    g1_kernel<<<1088, 256, 165888>>>(ctx_r, Wkv, bkv, kvb, lat_r, Wq, bq, qh);

    // ---- attention: scores(+chunk stats), rowstat fold, split-K P.V w/ inline softmax --
    scores_wmma<<<dim3(16, 128), 256, 52224>>>(qh, kvb, cmask, scores, cstat);
    rowstat_kernel<<<32, 256>>>(cstat, rowstat);
    a1_kernel<<<1536, 256, 104960>>>(scores, kvb, rowstat, part, aw_out);
    attn_reduce_kernel<<<512, 256>>>(part, attn);

    // ---- out projection (in-fragment cvt of out_w; reuse qh for attn_out) ----
    wmma_gemm_small<0, 1, 0, 1><<<dim3(8, 8), 256, 82944>>>(attn, out_w, out_b, qh, 512, 1024, 1024);

    // ---- LN1 (exact + rounded copy) ----
    add_ln_kernel<1><<<512, 256>>>(latents, qh, ln1_g, ln1_b, xb, xr);

    // ---- FFN (in-fragment cvt of ff weights) ----
    wmma_gemm_small<1, 1, 1, 1><<<dim3(32, 8), 256, 82944>>>(xr, ff_w1, ff_b1, h1, 512, 4096, 1024);
    wmma_gemm_small<0, 1, 0, 1><<<dim3(8, 8), 256, 82944>>>(h1, ff_w2, ff_b2, attn, 512, 1024, 4096);

    // ---- LN2 -> out ----
    add_ln_kernel<0><<<512, 256>>>(xb, attn, ln2_g, ln2_b, out, nullptr);
}

// round 12
// speedup vs baseline: 1.3243x; 1.3243x over previous
#include <cuda_runtime.h>
#include <mma.h>
#include <math.h>
#include <stdint.h>

using namespace nvcuda;

// Shapes: B=8, L=64, S=2048, D=1024, C=1024, H=16, HD=64

// ---------------- device scratch ----------------
__device__ float g_ctx_r[16384 * 1024];
__device__ float g_lat_r[512 * 1024];
__device__ float g_Wq[1024 * 1024];
__device__ float g_Wkv[2048 * 1024];
__device__ float g_bq[1024];
__device__ float g_bkv[2048];
__device__ float g_qh[512 * 1024];
__device__ float g_kv[16384 * 2048];        // masked rows stay 0 forever (never read w/ weight>0)
__device__ float g_scores[8192 * 2048];
__device__ float g_cstat[8192 * 32];
__device__ float g_rowstat[8192 * 2];
__device__ float g_part[4 * 512 * 1024];
__device__ float g_attn[512 * 1024];
__device__ float g_x[512 * 1024];
__device__ float g_xr[512 * 1024];
__device__ float g_h1[512 * 4096];
__device__ int g_sidx[8 * 2048];            // per-batch compacted unmasked row indices (-1 pad)
__device__ int g_scnt[8];                   // per-batch padded count (multiple of 128)

__device__ __forceinline__ float gelu_exact(float x) {
    return 0.5f * x * (1.0f + erff(x * 0.70710678118654752f));
}
__device__ __forceinline__ float rtf(float x) {
    float y;
    asm("cvt.rna.tf32.f32 %0, %1;" : "=f"(y) : "f"(x));
    return y;
}
__device__ __forceinline__ void cp16(uint32_t dst, const void* src) {
    asm volatile("cp.async.cg.shared.global [%0], [%1], 16;\n" ::"r"(dst), "l"(src));
}
#define CP_COMMIT() asm volatile("cp.async.commit_group;\n" ::)
#define CP_WAIT(n) asm volatile("cp.async.wait_group %0;\n" ::"n"(n))

// ==================== PROLOGUE: round ctx+lat + fuse_bias + mask compaction ==========
// blocks [0, 16896): rounding; [16896, 19968): fuse_bias; [19968, 19976): compaction
__global__ void prologue_kernel(
    const float4* context, float4* ctx_r,
    const float4* latents4, float4* lat_r,
    const float* in_wq, const float* q_b, const float* in_bq,
    const float* in_wk, const float* k_b, const float* in_bk,
    const float* in_wv, const float* v_b, const float* in_bv,
    float* bq, float* bkv, const int* cmask, int* sidx, int* scnt) {
    __shared__ float red[256];
    __shared__ int sc[256];
    int bx = blockIdx.x, tid = threadIdx.x;
    if (bx < 16896) {
        int i = bx * 256 + tid;
        const float4* s;
        float4* d;
        int off;
        if (i < 4194304) { s = context; d = ctx_r; off = i; }
        else { i -= 4194304; s = latents4; d = lat_r; off = i; }
        float4 v = s[off];
        v.x = rtf(v.x); v.y = rtf(v.y); v.z = rtf(v.z); v.w = rtf(v.w);
        d[off] = v;
    } else if (bx < 19968) {
        int idx = bx - 16896;
        int z = idx >> 10, o = idx & 1023;
        const float* W = (z == 0) ? in_wq : (z == 1) ? in_wk : in_wv;
        const float* bin = (z == 0) ? q_b : (z == 1) ? k_b : v_b;
        const float* badd = (z == 0) ? in_bq : (z == 1) ? in_bk : in_bv;
        float* bout = (z == 0) ? bq : (z == 1) ? bkv : (bkv + 1024);
        float s = 0.f;
        for (int i = tid; i < 1024; i += 256) s += W[o * 1024 + i] * bin[i];
        red[tid] = s;
        __syncthreads();
        for (int st = 128; st > 0; st >>= 1) {
            if (tid < st) red[tid] += red[tid + st];
            __syncthreads();
        }
        if (tid == 0) bout[o] = red[0] + badd[o];
    } else {
        // compaction: one block per batch
        int bb = bx - 19968;
        const int* m = cmask + bb * 2048;
        int base_s = tid * 8;
        int mv[8];
        int cnt = 0;
#pragma unroll
        for (int j = 0; j < 8; ++j) {
            mv[j] = m[base_s + j];
            cnt += (mv[j] != 0);
        }
        sc[tid] = cnt;
        __syncthreads();
        for (int off = 1; off < 256; off <<= 1) {
            int v = (tid >= off) ? sc[tid - off] : 0;
            __syncthreads();
            sc[tid] += v;
            __syncthreads();
        }
        int pos = sc[tid] - cnt;
        int total = sc[255];
#pragma unroll
        for (int j = 0; j < 8; ++j)
            if (mv[j]) sidx[bb * 2048 + pos++] = base_s + j;
        int padded = (total + 127) & ~127;
        for (int i = total + tid; i < padded; i += 256) sidx[bb * 2048 + i] = -1;
        if (tid == 0) scnt[bb] = padded;
    }
}

// ==================== weight-fusion GEMM 128x128 NN (in-fragment cvt) ================
__device__ __forceinline__ void fuse_body(const float* __restrict__ A, const float* __restrict__ B,
                                          float* __restrict__ C, float* sm) {
    const int N = 1024, K = 1024;
    int tid = threadIdx.x;
    int wid = tid >> 5, lane = tid & 31;
    int warpRow = wid >> 2, warpCol = wid & 3;
    int bm = blockIdx.y * 128, bn = blockIdx.x * 128;

    uint32_t s_base = (uint32_t)__cvta_generic_to_shared(sm);
    int ra = tid >> 3, ca = (tid & 7) * 4;
    int kb = tid >> 5, cb = (tid & 31) * 4;

    wmma::fragment<wmma::accumulator, 16, 16, 8, float> acc[4][2];
#pragma unroll
    for (int i = 0; i < 4; ++i)
#pragma unroll
        for (int j = 0; j < 2; ++j) wmma::fill_fragment(acc[i][j], 0.0f);

    const int KT = K >> 5;
    auto issue = [&](int stage, int k0) {
        uint32_t as = s_base + (uint32_t)(stage * 4608) * 4;
        uint32_t bs = s_base + (uint32_t)(9216 + stage * 5120) * 4;
#pragma unroll
        for (int it = 0; it < 4; ++it) {
            int r = ra + it * 32;
            cp16(as + (uint32_t)(r * 36 + ca) * 4, A + (size_t)(bm + r) * K + k0 + ca);
        }
#pragma unroll
        for (int it = 0; it < 4; ++it) {
            int kk = kb + it * 8;
            cp16(bs + (uint32_t)(kk * 136 + cb) * 4, B + (size_t)(k0 + kk) * N + bn + cb);
        }
        CP_COMMIT();
    };

    issue(0, 0);
    for (int kt = 0; kt < KT; ++kt) {
        int stage = kt & 1;
        if (kt + 1 < KT) {
            issue(stage ^ 1, (kt + 1) * 32);
            CP_WAIT(1);
        } else {
            CP_WAIT(0);
        }
        __syncthreads();
        float* As = sm + stage * 4608;
        float* Bs = sm + 9216 + stage * 5120;
#pragma unroll
        for (int ks = 0; ks < 4; ++ks) {
            int kk = ks * 8;
            wmma::fragment<wmma::matrix_a, 16, 16, 8, wmma::precision::tf32, wmma::row_major> af[4];
#pragma unroll
            for (int i = 0; i < 4; ++i) {
                wmma::load_matrix_sync(af[i], &As[(warpRow * 64 + i * 16) * 36 + kk], 36);
#pragma unroll
                for (int t = 0; t < af[i].num_elements; ++t)
                    af[i].x[t] = wmma::__float_to_tf32(af[i].x[t]);
            }
            wmma::fragment<wmma::matrix_b, 16, 16, 8, wmma::precision::tf32, wmma::row_major> bf[2];
#pragma unroll
            for (int j = 0; j < 2; ++j) {
                wmma::load_matrix_sync(bf[j], &Bs[kk * 136 + warpCol * 32 + j * 16], 136);
#pragma unroll
                for (int t = 0; t < bf[j].num_elements; ++t)
                    bf[j].x[t] = wmma::__float_to_tf32(bf[j].x[t]);
            }
#pragma unroll
            for (int i = 0; i < 4; ++i)
#pragma unroll
                for (int j = 0; j < 2; ++j) wmma::mma_sync(acc[i][j], af[i], bf[j], acc[i][j]);
        }
        __syncthreads();
    }

    float* st = &sm[wid * 384];
#pragma unroll
    for (int i = 0; i < 4; ++i) {
#pragma unroll
        for (int j = 0; j < 2; ++j) {
            wmma::store_matrix_sync(st, acc[i][j], 24, wmma::mem_row_major);
            __syncwarp();
            int row0 = bm + warpRow * 64 + i * 16;
            int col0 = bn + warpCol * 32 + j * 16;
            int r = lane >> 1, c8 = (lane & 1) * 8;
            float4 v0 = *(float4*)&st[r * 24 + c8];
            float4 v1 = *(float4*)&st[r * 24 + c8 + 4];
            v0.x = rtf(v0.x); v0.y = rtf(v0.y); v0.z = rtf(v0.z); v0.w = rtf(v0.w);
            v1.x = rtf(v1.x); v1.y = rtf(v1.y); v1.z = rtf(v1.z); v1.w = rtf(v1.w);
            float* cp = C + (size_t)(row0 + r) * N + col0 + c8;
            *(float4*)cp = v0;
            *(float4*)(cp + 4) = v1;
            __syncwarp();
        }
    }
}

__global__ void __launch_bounds__(256, 2)
wmma_gemm_fuse3(const float* A0, const float* B0, float* C0,
                const float* A1, const float* B1, float* C1,
                const float* A2, const float* B2, float* C2) {
    extern __shared__ float sm[];
    if (blockIdx.z == 0) fuse_body(A0, B0, C0, sm);
    else if (blockIdx.z == 1) fuse_body(A1, B1, C1, sm);
    else fuse_body(A2, B2, C2, sm);
}

// ==================== small GEMM body: 64x128 NT, 3-stage, ld 36 =====================
template <int EPI, int BIAS, int RND, int CVTB>
__device__ __forceinline__ void small_body(const float* __restrict__ A, const float* __restrict__ B,
                                           const float* __restrict__ bias, float* __restrict__ C,
                                           int N, int K, int bm, int bn, float* sm) {
    int tid = threadIdx.x;
    int wid = tid >> 5, lane = tid & 31;
    int warpRow = wid >> 2, warpCol = wid & 3;

    uint32_t s_base = (uint32_t)__cvta_generic_to_shared(sm);
    int ra = tid >> 3, ca = (tid & 7) * 4;

    wmma::fragment<wmma::accumulator, 16, 16, 8, float> acc[2][2];
#pragma unroll
    for (int i = 0; i < 2; ++i)
#pragma unroll
        for (int j = 0; j < 2; ++j) wmma::fill_fragment(acc[i][j], 0.0f);

    const int KT = K >> 5;
    auto issue = [&](int stage, int k0) {
        uint32_t as = s_base + (uint32_t)(stage * 2304) * 4;
        uint32_t bs = s_base + (uint32_t)(6912 + stage * 4608) * 4;
#pragma unroll
        for (int it = 0; it < 2; ++it) {
            int r = ra + it * 32;
            cp16(as + (uint32_t)(r * 36 + ca) * 4, A + (size_t)(bm + r) * K + k0 + ca);
        }
#pragma unroll
        for (int it = 0; it < 4; ++it) {
            int r = ra + it * 32;
            cp16(bs + (uint32_t)(r * 36 + ca) * 4, B + (size_t)(bn + r) * K + k0 + ca);
        }
        CP_COMMIT();
    };

    issue(0, 0);
    if (KT > 1) issue(1, 32);
    for (int kt = 0; kt < KT; ++kt) {
        if (kt + 1 < KT) CP_WAIT(1);
        else CP_WAIT(0);
        __syncthreads();
        if (kt + 2 < KT) issue((kt + 2) % 3, (kt + 2) * 32);
        int stage = kt % 3;
        float* As = sm + stage * 2304;
        float* Bs = sm + 6912 + stage * 4608;
#pragma unroll
        for (int ks = 0; ks < 4; ++ks) {
            int kk = ks * 8;
            wmma::fragment<wmma::matrix_a, 16, 16, 8, wmma::precision::tf32, wmma::row_major> af[2];
            wmma::fragment<wmma::matrix_b, 16, 16, 8, wmma::precision::tf32, wmma::col_major> bf[2];
#pragma unroll
            for (int i = 0; i < 2; ++i)
                wmma::load_matrix_sync(af[i], &As[(warpRow * 32 + i * 16) * 36 + kk], 36);
#pragma unroll
            for (int j = 0; j < 2; ++j) {
                wmma::load_matrix_sync(bf[j], &Bs[(warpCol * 32 + j * 16) * 36 + kk], 36);
                if (CVTB) {
#pragma unroll
                    for (int t = 0; t < bf[j].num_elements; ++t)
                        bf[j].x[t] = wmma::__float_to_tf32(bf[j].x[t]);
                }
            }
#pragma unroll
            for (int i = 0; i < 2; ++i)
#pragma unroll
                for (int j = 0; j < 2; ++j) wmma::mma_sync(acc[i][j], af[i], bf[j], acc[i][j]);
        }
    }
    __syncthreads();

    float* st = &sm[wid * 384];
#pragma unroll
    for (int i = 0; i < 2; ++i) {
#pragma unroll
        for (int j = 0; j < 2; ++j) {
            wmma::store_matrix_sync(st, acc[i][j], 24, wmma::mem_row_major);
            __syncwarp();
            int row0 = bm + warpRow * 32 + i * 16;
            int col0 = bn + warpCol * 32 + j * 16;
            int r = lane >> 1, c8 = (lane & 1) * 8;
            float4 v0 = *(float4*)&st[r * 24 + c8];
            float4 v1 = *(float4*)&st[r * 24 + c8 + 4];
            if (BIAS) {
                const float* bp = bias + col0 + c8;
                v0.x += bp[0]; v0.y += bp[1]; v0.z += bp[2]; v0.w += bp[3];
                v1.x += bp[4]; v1.y += bp[5]; v1.z += bp[6]; v1.w += bp[7];
            }
            if (EPI) {
                v0.x = gelu_exact(v0.x); v0.y = gelu_exact(v0.y);
                v0.z = gelu_exact(v0.z); v0.w = gelu_exact(v0.w);
                v1.x = gelu_exact(v1.x); v1.y = gelu_exact(v1.y);
                v1.z = gelu_exact(v1.z); v1.w = gelu_exact(v1.w);
            }
            if (RND) {
                v0.x = rtf(v0.x); v0.y = rtf(v0.y); v0.z = rtf(v0.z); v0.w = rtf(v0.w);
                v1.x = rtf(v1.x); v1.y = rtf(v1.y); v1.z = rtf(v1.z); v1.w = rtf(v1.w);
            }
            float* cp = C + (size_t)(row0 + r) * N + col0 + c8;
            *(float4*)cp = v0;
            *(float4*)(cp + 4) = v1;
            __syncwarp();
        }
    }
}

template <int EPI, int BIAS, int RND, int CVTB>
__global__ void __launch_bounds__(256, 2)
wmma_gemm_small(const float* __restrict__ A, const float* __restrict__ B,
                const float* __restrict__ bias, float* __restrict__ C,
                int M, int N, int K) {
    extern __shared__ float sm[];
    small_body<EPI, BIAS, RND, CVTB>(A, B, bias, C, N, K, blockIdx.y * 64, blockIdx.x * 128, sm);
}

// ==================== kv GEMM body: 128x256 NT, 3-stage, ld 36, ROW-GATHERED ==========
// A rows gathered through sidx (compacted unmasked rows); outputs scattered back.
// smem: A stages 3x4608 @0, B stages 3x9216 @13824, row idx (int[128]) @41472
__device__ __forceinline__ void kv_body_m(const float* __restrict__ A, const float* __restrict__ B,
                                          const float* __restrict__ bias, float* __restrict__ C,
                                          int batch, int mt, int bn,
                                          const int* __restrict__ sidx, float* sm) {
    const int N = 2048, K = 1024;
    int tid = threadIdx.x;
    int wid = tid >> 5, lane = tid & 31;
    int warpRow = wid >> 2, warpCol = wid & 3;

    uint32_t s_base = (uint32_t)__cvta_generic_to_shared(sm);
    int ra = tid >> 3, ca = (tid & 7) * 4;
    int* idxs = (int*)(sm + 41472);
    if (tid < 128) idxs[tid] = sidx[batch * 2048 + mt * 128 + tid];
    __syncthreads();

    wmma::fragment<wmma::accumulator, 16, 16, 8, float> acc[4][4];
#pragma unroll
    for (int i = 0; i < 4; ++i)
#pragma unroll
        for (int j = 0; j < 4; ++j) wmma::fill_fragment(acc[i][j], 0.0f);

    const int KT = K >> 5;
    auto issue = [&](int stage, int k0) {
        uint32_t as = s_base + (uint32_t)(stage * 4608) * 4;
        uint32_t bs = s_base + (uint32_t)(13824 + stage * 9216) * 4;
#pragma unroll
        for (int it = 0; it < 4; ++it) {
            int r = ra + it * 32;
            int orig = idxs[r];
            orig = orig < 0 ? 0 : orig;
            cp16(as + (uint32_t)(r * 36 + ca) * 4,
                 A + ((size_t)batch * 2048 + orig) * 1024 + k0 + ca);
        }
#pragma unroll
        for (int it = 0; it < 8; ++it) {
            int r = ra + it * 32;
            cp16(bs + (uint32_t)(r * 36 + ca) * 4, B + (size_t)(bn + r) * K + k0 + ca);
        }
        CP_COMMIT();
    };

    issue(0, 0);
    issue(1, 32);
    for (int kt = 0; kt < KT; ++kt) {
        if (kt + 1 < KT) CP_WAIT(1);
        else CP_WAIT(0);
        __syncthreads();
        if (kt + 2 < KT) issue((kt + 2) % 3, (kt + 2) * 32);
        int stage = kt % 3;
        float* As = sm + stage * 4608;
        float* Bs = sm + 13824 + stage * 9216;
#pragma unroll
        for (int ks = 0; ks < 4; ++ks) {
            int kk = ks * 8;
            wmma::fragment<wmma::matrix_a, 16, 16, 8, wmma::precision::tf32, wmma::row_major> af[4];
            wmma::fragment<wmma::matrix_b, 16, 16, 8, wmma::precision::tf32, wmma::col_major> bf[4];
#pragma unroll
            for (int i = 0; i < 4; ++i)
                wmma::load_matrix_sync(af[i], &As[(warpRow * 64 + i * 16) * 36 + kk], 36);
#pragma unroll
            for (int j = 0; j < 4; ++j)
                wmma::load_matrix_sync(bf[j], &Bs[(warpCol * 64 + j * 16) * 36 + kk], 36);
#pragma unroll
            for (int i = 0; i < 4; ++i)
#pragma unroll
                for (int j = 0; j < 4; ++j) wmma::mma_sync(acc[i][j], af[i], bf[j], acc[i][j]);
        }
    }
    __syncthreads();

    float* st = &sm[wid * 384];
#pragma unroll
    for (int i = 0; i < 4; ++i) {
#pragma unroll
        for (int j = 0; j < 4; ++j) {
            wmma::store_matrix_sync(st, acc[i][j], 24, wmma::mem_row_major);
            __syncwarp();
            int r = lane >> 1, c8 = (lane & 1) * 8;
            int row_local = warpRow * 64 + i * 16 + r;
            int orig = idxs[row_local];
            int col0 = bn + warpCol * 64 + j * 16;
            if (orig >= 0) {
                float4 v0 = *(float4*)&st[r * 24 + c8];
                float4 v1 = *(float4*)&st[r * 24 + c8 + 4];
                const float* bp = bias + col0 + c8;
                v0.x = rtf(v0.x + bp[0]); v0.y = rtf(v0.y + bp[1]);
                v0.z = rtf(v0.z + bp[2]); v0.w = rtf(v0.w + bp[3]);
                v1.x = rtf(v1.x + bp[4]); v1.y = rtf(v1.y + bp[5]);
                v1.z = rtf(v1.z + bp[6]); v1.w = rtf(v1.w + bp[7]);
                float* cp = C + ((size_t)batch * 2048 + orig) * N + col0 + c8;
                *(float4*)cp = v0;
                *(float4*)(cp + 4) = v1;
            }
            __syncwarp();
        }
    }
}

// G1: masked kv GEMM (blocks 0..1023: batch=bx>>7, mt=(bx>>3)&15, n=(bx&7))
//     + q projection (blocks 1024..1087)
__global__ void __launch_bounds__(256, 1)
g1_kernel(const float* ctx_r, const float* Wkv, const float* bkv, float* kvb,
          const float* lat_r, const float* Wq, const float* bq, float* qh,
          const int* sidx, const int* scnt) {
    extern __shared__ float sm[];
    int bx = blockIdx.x;
    if (bx < 1024) {
        int batch = bx >> 7;
        int mt = (bx >> 3) & 15;
        if (mt * 128 >= scnt[batch]) return;
        kv_body_m(ctx_r, Wkv, bkv, kvb, batch, mt, (bx & 7) * 256, sidx, sm);
    } else {
        int idx = bx - 1024;
        small_body<0, 1, 1, 0>(lat_r, Wq, bq, qh, 1024, 1024, (idx >> 3) * 64, (idx & 7) * 128, sm);
    }
}

// ==================== scores: [64,128]-tile of Q K^T / 8, masked + chunk stats =======
__global__ void __launch_bounds__(256)
scores_wmma(const float* __restrict__ qh, const float* __restrict__ kv,
            const int* __restrict__ cmask, float* __restrict__ scores,
            float* __restrict__ cstat) {
    extern __shared__ float sm[];
    float* Qs = sm;
    float* Ks = sm + 4352;
    int bh = blockIdx.y;
    int b = bh >> 4, h = bh & 15;
    int s0 = blockIdx.x * 128;
    int tid = threadIdx.x, wid = tid >> 5, lane = tid & 31;

#pragma unroll
    for (int it = 0; it < 4; ++it) {
        int v = tid + it * 256;
        int r = v >> 4, c = (v & 15) * 4;
        *(float4*)&Qs[r * 68 + c] = *(const float4*)(qh + (size_t)(b * 64 + r) * 1024 + h * 64 + c);
    }
#pragma unroll
    for (int it = 0; it < 8; ++it) {
        int v = tid + it * 256;
        int r = v >> 4, c = (v & 15) * 4;
        *(float4*)&Ks[r * 68 + c] =
            *(const float4*)(kv + (size_t)(b * 2048 + s0 + r) * 2048 + h * 64 + c);
    }
    __syncthreads();

    int warpRow = wid >> 2, warpCol = wid & 3;
    wmma::fragment<wmma::accumulator, 16, 16, 8, float> acc[2][2];
#pragma unroll
    for (int i = 0; i < 2; ++i)
#pragma unroll
        for (int j = 0; j < 2; ++j) wmma::fill_fragment(acc[i][j], 0.0f);

#pragma unroll
    for (int ks = 0; ks < 8; ++ks) {
        int kk = ks * 8;
        wmma::fragment<wmma::matrix_a, 16, 16, 8, wmma::precision::tf32, wmma::row_major> af[2];
        wmma::fragment<wmma::matrix_b, 16, 16, 8, wmma::precision::tf32, wmma::col_major> bf[2];
#pragma unroll
        for (int i = 0; i < 2; ++i)
            wmma::load_matrix_sync(af[i], &Qs[(warpRow * 32 + i * 16) * 68 + kk], 68);
#pragma unroll
        for (int j = 0; j < 2; ++j)
            wmma::load_matrix_sync(bf[j], &Ks[(warpCol * 32 + j * 16) * 68 + kk], 68);
#pragma unroll
        for (int i = 0; i < 2; ++i)
#pragma unroll
            for (int j = 0; j < 2; ++j) wmma::mma_sync(acc[i][j], af[i], bf[j], acc[i][j]);
    }
    __syncthreads();

    const float NEG = __int_as_float(0xff800000);
    float* st = &sm[wid * 384];
    float* pm = sm + 3072;
    float* ps = sm + 3328;
#pragma unroll
    for (int i = 0; i < 2; ++i) {
        int r = lane >> 1, c8 = (lane & 1) * 8;
        int l = warpRow * 32 + i * 16 + r;
        float4 v0, v1, v2, v3;
        wmma::store_matrix_sync(st, acc[i][0], 24, wmma::mem_row_major);
        __syncwarp();
        v0 = *(float4*)&st[r * 24 + c8];
        v1 = *(float4*)&st[r * 24 + c8 + 4];
        __syncwarp();
        wmma::store_matrix_sync(st, acc[i][1], 24, wmma::mem_row_major);
        __syncwarp();
        v2 = *(float4*)&st[r * 24 + c8];
        v3 = *(float4*)&st[r * 24 + c8 + 4];
        __syncwarp();
        int sg0 = s0 + warpCol * 32 + c8;
        int sg1 = sg0 + 16;
        const int* mp0 = cmask + b * 2048 + sg0;
        const int* mp1 = cmask + b * 2048 + sg1;
        v0.x = mp0[0] ? v0.x * 0.125f : NEG;
        v0.y = mp0[1] ? v0.y * 0.125f : NEG;
        v0.z = mp0[2] ? v0.z * 0.125f : NEG;
        v0.w = mp0[3] ? v0.w * 0.125f : NEG;
        v1.x = mp0[4] ? v1.x * 0.125f : NEG;
        v1.y = mp0[5] ? v1.y * 0.125f : NEG;
        v1.z = mp0[6] ? v1.z * 0.125f : NEG;
        v1.w = mp0[7] ? v1.w * 0.125f : NEG;
        v2.x = mp1[0] ? v2.x * 0.125f : NEG;
        v2.y = mp1[1] ? v2.y * 0.125f : NEG;
        v2.z = mp1[2] ? v2.z * 0.125f : NEG;
        v2.w = mp1[3] ? v2.w * 0.125f : NEG;
        v3.x = mp1[4] ? v3.x * 0.125f : NEG;
        v3.y = mp1[5] ? v3.y * 0.125f : NEG;
        v3.z = mp1[6] ? v3.z * 0.125f : NEG;
        v3.w = mp1[7] ? v3.w * 0.125f : NEG;
        float* pp = scores + ((size_t)bh * 64 + l) * 2048 + sg0;
        *(float4*)pp = v0;
        *(float4*)(pp + 4) = v1;
        *(float4*)(pp + 16) = v2;
        *(float4*)(pp + 20) = v3;
        float mx = fmaxf(fmaxf(fmaxf(v0.x, v0.y), fmaxf(v0.z, v0.w)),
                         fmaxf(fmaxf(v1.x, v1.y), fmaxf(v1.z, v1.w)));
        mx = fmaxf(mx, fmaxf(fmaxf(fmaxf(v2.x, v2.y), fmaxf(v2.z, v2.w)),
                             fmaxf(fmaxf(v3.x, v3.y), fmaxf(v3.z, v3.w))));
        float m2 = fmaxf(mx, __shfl_xor_sync(0xffffffffu, mx, 1));
        float m2c = fmaxf(m2, -1e30f);
        float s = expf(v0.x - m2c) + expf(v0.y - m2c) + expf(v0.z - m2c) + expf(v0.w - m2c) +
                  expf(v1.x - m2c) + expf(v1.y - m2c) + expf(v1.z - m2c) + expf(v1.w - m2c) +
                  expf(v2.x - m2c) + expf(v2.y - m2c) + expf(v2.z - m2c) + expf(v2.w - m2c) +
                  expf(v3.x - m2c) + expf(v3.y - m2c) + expf(v3.z - m2c) + expf(v3.w - m2c);
        s += __shfl_xor_sync(0xffffffffu, s, 1);
        if ((lane & 1) == 0) {
            pm[l * 4 + warpCol] = m2;
            ps[l * 4 + warpCol] = s;
        }
    }
    __syncthreads();
    if (tid < 64) {
        float m0 = pm[tid * 4], m1 = pm[tid * 4 + 1], m2 = pm[tid * 4 + 2], m3 = pm[tid * 4 + 3];
        float m = fmaxf(fmaxf(m0, m1), fmaxf(m2, m3));
        float mc = fmaxf(m, -1e30f);
        float S = ps[tid * 4] * expf(m0 - mc) + ps[tid * 4 + 1] * expf(m1 - mc) +
                  ps[tid * 4 + 2] * expf(m2 - mc) + ps[tid * 4 + 3] * expf(m3 - mc);
        float2 o;
        o.x = m;
        o.y = S;
        *(float2*)&cstat[(((size_t)bh * 64 + tid) * 16 + blockIdx.x) * 2] = o;
    }
}

// ---------------- rowstat: fold 16 chunk stats -> (max, 1/sum) per row ----------------
__global__ void rowstat_kernel(const float* __restrict__ cstat, float* __restrict__ rowstat) {
    int row = blockIdx.x * 256 + threadIdx.x;
    const float2* c = (const float2*)cstat + row * 16;
    float M = __int_as_float(0xff800000);
#pragma unroll
    for (int k = 0; k < 16; ++k) M = fmaxf(M, c[k].x);
    float Mc = fmaxf(M, -1e30f);
    float S = 0.f;
#pragma unroll
    for (int k = 0; k < 16; ++k) S += c[k].y * expf(c[k].x - Mc);
    float2 o;
    o.x = Mc;
    o.y = 1.0f / S;
    ((float2*)rowstat)[row] = o;
}

// ==================== attn split-K body: inline softmax on staged P tile ==============
__device__ __forceinline__ void attn_body(const float* __restrict__ scores,
                                          const float* __restrict__ kv,
                                          const float* __restrict__ rowstat,
                                          float* __restrict__ part,
                                          int bh, int split, float* sm) {
    int b = bh >> 4, h = bh & 15;
    int base_s = split * 512;
    int tid = threadIdx.x, wid = tid >> 5, lane = tid & 31;
    int warpRow = wid >> 1, warpCol = wid & 1;

    uint32_t s_base = (uint32_t)__cvta_generic_to_shared(sm);
    int ra = tid >> 4, ca = (tid & 15) * 4;
    float* rs_m = sm + 26112;
    float* rs_i = sm + 26176;
    if (tid < 64) {
        float2 v = ((const float2*)rowstat)[bh * 64 + tid];
        rs_m[tid] = v.x;
        rs_i[tid] = v.y;
    }

    wmma::fragment<wmma::accumulator, 16, 16, 8, float> acc[2];
    wmma::fill_fragment(acc[0], 0.0f);
    wmma::fill_fragment(acc[1], 0.0f);

    auto issue = [&](int stage, int s0) {
        uint32_t ps = s_base + (uint32_t)(stage * 4352) * 4;
        uint32_t vs = s_base + (uint32_t)(13056 + stage * 4352) * 4;
#pragma unroll
        for (int it = 0; it < 4; ++it) {
            int r = ra + it * 16;
            cp16(ps + (uint32_t)(r * 68 + ca) * 4,
                 scores + ((size_t)bh * 64 + r) * 2048 + s0 + ca);
            cp16(vs + (uint32_t)(r * 68 + ca) * 4,
                 kv + (size_t)(b * 2048 + s0 + r) * 2048 + 1024 + h * 64 + ca);
        }
        CP_COMMIT();
    };

    issue(0, base_s);
    issue(1, base_s + 64);
    for (int kt = 0; kt < 8; ++kt) {
        if (kt + 1 < 8) CP_WAIT(1);
        else CP_WAIT(0);
        __syncthreads();
        int stage = kt % 3;
        float* Ps = sm + stage * 4352;
#pragma unroll
        for (int it = 0; it < 4; ++it) {
            int rr = ra + it * 16;
            float M = rs_m[rr], I = rs_i[rr];
            float4 v = *(float4*)&Ps[rr * 68 + ca];
            v.x = rtf(expf(v.x - M) * I);
            v.y = rtf(expf(v.y - M) * I);
            v.z = rtf(expf(v.z - M) * I);
            v.w = rtf(expf(v.w - M) * I);
            *(float4*)&Ps[rr * 68 + ca] = v;
        }
        __syncthreads();
        if (kt + 2 < 8) issue((kt + 2) % 3, base_s + (kt + 2) * 64);
        float* Vs = sm + 13056 + stage * 4352;
#pragma unroll
        for (int ks = 0; ks < 8; ++ks) {
            int kk = ks * 8;
            wmma::fragment<wmma::matrix_a, 16, 16, 8, wmma::precision::tf32, wmma::row_major> af;
            wmma::fragment<wmma::matrix_b, 16, 16, 8, wmma::precision::tf32, wmma::row_major> bf[2];
            wmma::load_matrix_sync(af, &Ps[(warpRow * 16) * 68 + kk], 68);
#pragma unroll
            for (int j = 0; j < 2; ++j)
                wmma::load_matrix_sync(bf[j], &Vs[kk * 68 + warpCol * 32 + j * 16], 68);
            wmma::mma_sync(acc[0], af, bf[0], acc[0]);
            wmma::mma_sync(acc[1], af, bf[1], acc[1]);
        }
    }
    __syncthreads();

    float* pout = part + (size_t)split * 524288;
    float* st = &sm[wid * 384];
#pragma unroll
    for (int j = 0; j < 2; ++j) {
        wmma::store_matrix_sync(st, acc[j], 24, wmma::mem_row_major);
        __syncwarp();
        int r = lane >> 1, c8 = (lane & 1) * 8;
        int l = warpRow * 16 + r;
        int d0 = warpCol * 32 + j * 16 + c8;
        float4 v0 = *(float4*)&st[r * 24 + c8];
        float4 v1 = *(float4*)&st[r * 24 + c8 + 4];
        float* ap = pout + (size_t)(b * 64 + l) * 1024 + h * 64 + d0;
        *(float4*)ap = v0;
        *(float4*)(ap + 4) = v1;
        __syncwarp();
    }
}

// A1: attn_part (blocks 0..511) + mean_heads with inline softmax (blocks 512..1535)
__global__ void __launch_bounds__(256, 2)
a1_kernel(const float* __restrict__ scores, const float* __restrict__ kv,
          const float* __restrict__ rowstat, float* __restrict__ part,
          float* __restrict__ aw) {
    extern __shared__ float sm[];
    int bx = blockIdx.x;
    if (bx < 512) {
        attn_body(scores, kv, rowstat, part, bx >> 2, bx & 3, sm);
    } else {
        int i = (bx - 512) * 256 + threadIdx.x;
        int s4 = i & 511;
        int l = (i >> 9) & 63;
        int b = i >> 15;
        float4 acc = {0.f, 0.f, 0.f, 0.f};
#pragma unroll
        for (int h = 0; h < 16; ++h) {
            size_t row = (size_t)(b * 16 + h) * 64 + l;
            float2 stt = ((const float2*)rowstat)[row];
            float4 x = *(const float4*)(scores + row * 2048 + s4 * 4);
            acc.x += expf(x.x - stt.x) * stt.y;
            acc.y += expf(x.y - stt.x) * stt.y;
            acc.z += expf(x.z - stt.x) * stt.y;
            acc.w += expf(x.w - stt.x) * stt.y;
        }
        const float inv = 1.0f / 16.0f;
        acc.x *= inv; acc.y *= inv; acc.z *= inv; acc.w *= inv;
        *(float4*)(aw + ((size_t)(b * 64 + l) * 2048) + s4 * 4) = acc;
    }
}

// reduce 4 partials -> attn (tf32-rounded)
__global__ void attn_reduce_kernel(const float* __restrict__ part, float* __restrict__ attn) {
    int i = blockIdx.x * 256 + threadIdx.x;
    float4 a = ((const float4*)part)[i];
    float4 b = ((const float4*)(part + 524288))[i];
    float4 c = ((const float4*)(part + 1048576))[i];
    float4 d = ((const float4*)(part + 1572864))[i];
    float4 o;
    o.x = rtf(((a.x + b.x) + (c.x + d.x)));
    o.y = rtf(((a.y + b.y) + (c.y + d.y)));
    o.z = rtf(((a.z + b.z) + (c.z + d.z)));
    o.w = rtf(((a.w + b.w) + (c.w + d.w)));
    ((float4*)attn)[i] = o;
}

// ---------------- residual add + LayerNorm (optional rounded copy) ----------------
template <int WR>
__global__ void add_ln_kernel(const float* __restrict__ a, const float* __restrict__ b2,
                              const float* __restrict__ g, const float* __restrict__ bet,
                              float* __restrict__ out, float* __restrict__ out_r) {
    int row = blockIdx.x, tid = threadIdx.x;
    const float4* a4 = (const float4*)(a + (size_t)row * 1024);
    const float4* b4 = (const float4*)(b2 + (size_t)row * 1024);
    float4 va = a4[tid], vb = b4[tid];
    float4 x;
    x.x = va.x + vb.x; x.y = va.y + vb.y; x.z = va.z + vb.z; x.w = va.w + vb.w;
    float s = (x.x + x.y) + (x.z + x.w);
    float sq = x.x * x.x + x.y * x.y + x.z * x.z + x.w * x.w;
    __shared__ float r1[256], r2[256];
    r1[tid] = s; r2[tid] = sq;
    __syncthreads();
    for (int st = 128; st > 0; st >>= 1) {
        if (tid < st) { r1[tid] += r1[tid + st]; r2[tid] += r2[tid + st]; }
        __syncthreads();
    }
    float mean = r1[0] * (1.0f / 1024.0f);
    float var = r2[0] * (1.0f / 1024.0f) - mean * mean;
    float rstd = rsqrtf(var + 1e-5f);
    float4 gg = ((const float4*)g)[tid], bb = ((const float4*)bet)[tid];
    float4 o;
    o.x = (x.x - mean) * rstd * gg.x + bb.x;
    o.y = (x.y - mean) * rstd * gg.y + bb.y;
    o.z = (x.z - mean) * rstd * gg.z + bb.z;
    o.w = (x.w - mean) * rstd * gg.w + bb.w;
    ((float4*)(out + (size_t)row * 1024))[tid] = o;
    if (WR) {
        float4 q;
        q.x = rtf(o.x); q.y = rtf(o.y); q.z = rtf(o.z); q.w = rtf(o.w);
        ((float4*)(out_r + (size_t)row * 1024))[tid] = q;
    }
}

// ---------------- launch ----------------
extern "C" void kernel_launch(void* const* d_in, const int* in_sizes, int n_in,
                              void* d_out, int out_size) {
    (void)in_sizes; (void)n_in; (void)out_size;
    const float* latents = (const float*)d_in[0];
    const float* context = (const float*)d_in[1];
    const int* cmask = (const int*)d_in[2];
    const float* q_w = (const float*)d_in[3];
    const float* q_b = (const float*)d_in[4];
    const float* k_w = (const float*)d_in[5];
    const float* k_b = (const float*)d_in[6];
    const float* v_w = (const float*)d_in[7];
    const float* v_b = (const float*)d_in[8];
    const float* in_wq = (const float*)d_in[9];
    const float* in_bq = (const float*)d_in[10];
    const float* in_wk = (const float*)d_in[11];
    const float* in_bk = (const float*)d_in[12];
    const float* in_wv = (const float*)d_in[13];
    const float* in_bv = (const float*)d_in[14];
    const float* out_w = (const float*)d_in[15];
    const float* out_b = (const float*)d_in[16];
    const float* ln1_g = (const float*)d_in[17];
    const float* ln1_b = (const float*)d_in[18];
    const float* ln2_g = (const float*)d_in[19];
    const float* ln2_b = (const float*)d_in[20];
    const float* ff_w1 = (const float*)d_in[21];
    const float* ff_b1 = (const float*)d_in[22];
    const float* ff_w2 = (const float*)d_in[23];
    const float* ff_b2 = (const float*)d_in[24];

    float* out = (float*)d_out;
    float* aw_out = out + 512 * 1024;

    void* p;
    cudaGetSymbolAddress(&p, g_ctx_r);   float* ctx_r = (float*)p;
    cudaGetSymbolAddress(&p, g_lat_r);   float* lat_r = (float*)p;
    cudaGetSymbolAddress(&p, g_Wq);      float* Wq = (float*)p;
    cudaGetSymbolAddress(&p, g_Wkv);     float* Wkv = (float*)p;
    cudaGetSymbolAddress(&p, g_bq);      float* bq = (float*)p;
    cudaGetSymbolAddress(&p, g_bkv);     float* bkv = (float*)p;
    cudaGetSymbolAddress(&p, g_qh);      float* qh = (float*)p;
    cudaGetSymbolAddress(&p, g_kv);      float* kvb = (float*)p;
    cudaGetSymbolAddress(&p, g_scores);  float* scores = (float*)p;
    cudaGetSymbolAddress(&p, g_cstat);   float* cstat = (float*)p;
    cudaGetSymbolAddress(&p, g_rowstat); float* rowstat = (float*)p;
    cudaGetSymbolAddress(&p, g_part);    float* part = (float*)p;
    cudaGetSymbolAddress(&p, g_attn);    float* attn = (float*)p;
    cudaGetSymbolAddress(&p, g_x);       float* xb = (float*)p;
    cudaGetSymbolAddress(&p, g_xr);      float* xr = (float*)p;
    cudaGetSymbolAddress(&p, g_h1);      float* h1 = (float*)p;
    cudaGetSymbolAddress(&p, g_sidx);    int* sidx = (int*)p;
    cudaGetSymbolAddress(&p, g_scnt);    int* scnt = (int*)p;

    cudaFuncSetAttribute(wmma_gemm_fuse3, cudaFuncAttributeMaxDynamicSharedMemorySize, 77824);
    cudaFuncSetAttribute(wmma_gemm_small<0, 1, 0, 1>, cudaFuncAttributeMaxDynamicSharedMemorySize, 82944);
    cudaFuncSetAttribute(wmma_gemm_small<1, 1, 1, 1>, cudaFuncAttributeMaxDynamicSharedMemorySize, 82944);
    cudaFuncSetAttribute(g1_kernel, cudaFuncAttributeMaxDynamicSharedMemorySize, 166400);
    cudaFuncSetAttribute(scores_wmma, cudaFuncAttributeMaxDynamicSharedMemorySize, 52224);
    cudaFuncSetAttribute(a1_kernel, cudaFuncAttributeMaxDynamicSharedMemorySize, 104960);

    // ---- merged prologue: round ctx+lat + fused biases + mask compaction ----
    prologue_kernel<<<19976, 256>>>(
        (const float4*)context, (float4*)ctx_r,
        (const float4*)latents, (float4*)lat_r,
        in_wq, q_b, in_bq, in_wk, k_b, in_bk, in_wv, v_b, in_bv, bq, bkv,
        cmask, sidx, scnt);

    // ---- fused weights (in-fragment tf32 cvt on raw inputs) ----
    const size_t MM = 1024 * 1024;
    wmma_gemm_fuse3<<<dim3(8, 8, 3), 256, 77824>>>(
        in_wq, q_w, Wq,
        in_wk, k_w, Wkv,
        in_wv, v_w, Wkv + MM);

    // ---- G1: masked-compacted kv projection + q projection (merged) ----
    g1_kernel<<<1088, 256, 166400>>>(ctx_r, Wkv, bkv, kvb, lat_r, Wq, bq, qh, sidx, scnt);

    // ---- attention: scores(+chunk stats), rowstat fold, split-K P.V w/ inline softmax --
    scores_wmma<<<dim3(16, 128), 256, 52224>>>(qh, kvb, cmask, scores, cstat);
    rowstat_kernel<<<32, 256>>>(cstat, rowstat);
    a1_kernel<<<1536, 256, 104960>>>(scores, kvb, rowstat, part, aw_out);
    attn_reduce_kernel<<<512, 256>>>(part, attn);

    // ---- out projection (in-fragment cvt of out_w; reuse qh for attn_out) ----
    wmma_gemm_small<0, 1, 0, 1><<<dim3(8, 8), 256, 82944>>>(attn, out_w, out_b, qh, 512, 1024, 1024);

    // ---- LN1 (exact + rounded copy) ----
    add_ln_kernel<1><<<512, 256>>>(latents, qh, ln1_g, ln1_b, xb, xr);

    // ---- FFN (in-fragment cvt of ff weights) ----
    wmma_gemm_small<1, 1, 1, 1><<<dim3(32, 8), 256, 82944>>>(xr, ff_w1, ff_b1, h1, 512, 4096, 1024);
    wmma_gemm_small<0, 1, 0, 1><<<dim3(8, 8), 256, 82944>>>(h1, ff_w2, ff_b2, attn, 512, 1024, 4096);

    // ---- LN2 -> out ----
    add_ln_kernel<0><<<512, 256>>>(xb, attn, ln2_g, ln2_b, out, nullptr);
}

// round 13
// speedup vs baseline: 1.3850x; 1.0458x over previous
#include <cuda_runtime.h>
#include <mma.h>
#include <math.h>
#include <stdint.h>

using namespace nvcuda;

// Shapes: B=8, L=64, S=2048, D=1024, C=1024, H=16, HD=64

// ---------------- device scratch ----------------
__device__ float g_ctx_r[16384 * 1024];
__device__ float g_lat_r[512 * 1024];
__device__ float g_Wq[1024 * 1024];
__device__ float g_Wkv[2048 * 1024];
__device__ float g_bq[1024];
__device__ float g_bkv[2048];
__device__ float g_qh[512 * 1024];
__device__ float g_kv[16384 * 2048];        // masked rows stay 0 (never observed)
__device__ float g_scores[8192 * 2048];     // COMPACTED columns per batch
__device__ float g_cstat[8192 * 32];
__device__ float g_rowstat[8192 * 2];
__device__ float g_part[4 * 512 * 1024];
__device__ float g_attn[512 * 1024];
__device__ float g_x[512 * 1024];
__device__ float g_xr[512 * 1024];
__device__ float g_h1[512 * 4096];
__device__ int g_sidx[8 * 2048];            // per-batch compacted unmasked indices (-1 pad)
__device__ int g_scnt[8];                   // per-batch padded count (multiple of 128)

__device__ __forceinline__ float gelu_exact(float x) {
    return 0.5f * x * (1.0f + erff(x * 0.70710678118654752f));
}
__device__ __forceinline__ float rtf(float x) {
    float y;
    asm("cvt.rna.tf32.f32 %0, %1;" : "=f"(y) : "f"(x));
    return y;
}
__device__ __forceinline__ void cp16(uint32_t dst, const void* src) {
    asm volatile("cp.async.cg.shared.global [%0], [%1], 16;\n" ::"r"(dst), "l"(src));
}
#define CP_COMMIT() asm volatile("cp.async.commit_group;\n" ::)
#define CP_WAIT(n) asm volatile("cp.async.wait_group %0;\n" ::"n"(n))

// ==================== PROLOGUE ====================
// [0,16896): round ctx+lat; [16896,19968): fuse_bias; [19968,19976): compaction;
// [19976,21000): zero aw (masked cols of attn_weights are exactly 0)
__global__ void prologue_kernel(
    const float4* context, float4* ctx_r,
    const float4* latents4, float4* lat_r,
    const float* in_wq, const float* q_b, const float* in_bq,
    const float* in_wk, const float* k_b, const float* in_bk,
    const float* in_wv, const float* v_b, const float* in_bv,
    float* bq, float* bkv, const int* cmask, int* sidx, int* scnt,
    float4* aw4) {
    __shared__ float red[256];
    __shared__ int sc[256];
    int bx = blockIdx.x, tid = threadIdx.x;
    if (bx < 16896) {
        int i = bx * 256 + tid;
        const float4* s;
        float4* d;
        int off;
        if (i < 4194304) { s = context; d = ctx_r; off = i; }
        else { i -= 4194304; s = latents4; d = lat_r; off = i; }
        float4 v = s[off];
        v.x = rtf(v.x); v.y = rtf(v.y); v.z = rtf(v.z); v.w = rtf(v.w);
        d[off] = v;
    } else if (bx < 19968) {
        int idx = bx - 16896;
        int z = idx >> 10, o = idx & 1023;
        const float* W = (z == 0) ? in_wq : (z == 1) ? in_wk : in_wv;
        const float* bin = (z == 0) ? q_b : (z == 1) ? k_b : v_b;
        const float* badd = (z == 0) ? in_bq : (z == 1) ? in_bk : in_bv;
        float* bout = (z == 0) ? bq : (z == 1) ? bkv : (bkv + 1024);
        float s = 0.f;
        for (int i = tid; i < 1024; i += 256) s += W[o * 1024 + i] * bin[i];
        red[tid] = s;
        __syncthreads();
        for (int st = 128; st > 0; st >>= 1) {
            if (tid < st) red[tid] += red[tid + st];
            __syncthreads();
        }
        if (tid == 0) bout[o] = red[0] + badd[o];
    } else if (bx < 19976) {
        int bb = bx - 19968;
        const int* m = cmask + bb * 2048;
        int base_s = tid * 8;
        int mv[8];
        int cnt = 0;
#pragma unroll
        for (int j = 0; j < 8; ++j) {
            mv[j] = m[base_s + j];
            cnt += (mv[j] != 0);
        }
        sc[tid] = cnt;
        __syncthreads();
        for (int off = 1; off < 256; off <<= 1) {
            int v = (tid >= off) ? sc[tid - off] : 0;
            __syncthreads();
            sc[tid] += v;
            __syncthreads();
        }
        int pos = sc[tid] - cnt;
        int total = sc[255];
#pragma unroll
        for (int j = 0; j < 8; ++j)
            if (mv[j]) sidx[bb * 2048 + pos++] = base_s + j;
        int padded = (total + 127) & ~127;
        for (int i = total + tid; i < padded; i += 256) sidx[bb * 2048 + i] = -1;
        if (tid == 0) scnt[bb] = padded;
    } else {
        int i = (bx - 19976) * 256 + tid;   // 262144 f4 = 1M floats
        float4 z = {0.f, 0.f, 0.f, 0.f};
        aw4[i] = z;
    }
}

// ==================== weight-fusion GEMM 128x128 NN (in-fragment cvt) ================
__device__ __forceinline__ void fuse_body(const float* __restrict__ A, const float* __restrict__ B,
                                          float* __restrict__ C, float* sm) {
    const int N = 1024, K = 1024;
    int tid = threadIdx.x;
    int wid = tid >> 5, lane = tid & 31;
    int warpRow = wid >> 2, warpCol = wid & 3;
    int bm = blockIdx.y * 128, bn = blockIdx.x * 128;

    uint32_t s_base = (uint32_t)__cvta_generic_to_shared(sm);
    int ra = tid >> 3, ca = (tid & 7) * 4;
    int kb = tid >> 5, cb = (tid & 31) * 4;

    wmma::fragment<wmma::accumulator, 16, 16, 8, float> acc[4][2];
#pragma unroll
    for (int i = 0; i < 4; ++i)
#pragma unroll
        for (int j = 0; j < 2; ++j) wmma::fill_fragment(acc[i][j], 0.0f);

    const int KT = K >> 5;
    auto issue = [&](int stage, int k0) {
        uint32_t as = s_base + (uint32_t)(stage * 4608) * 4;
        uint32_t bs = s_base + (uint32_t)(9216 + stage * 5120) * 4;
#pragma unroll
        for (int it = 0; it < 4; ++it) {
            int r = ra + it * 32;
            cp16(as + (uint32_t)(r * 36 + ca) * 4, A + (size_t)(bm + r) * K + k0 + ca);
        }
#pragma unroll
        for (int it = 0; it < 4; ++it) {
            int kk = kb + it * 8;
            cp16(bs + (uint32_t)(kk * 136 + cb) * 4, B + (size_t)(k0 + kk) * N + bn + cb);
        }
        CP_COMMIT();
    };

    issue(0, 0);
    for (int kt = 0; kt < KT; ++kt) {
        int stage = kt & 1;
        if (kt + 1 < KT) {
            issue(stage ^ 1, (kt + 1) * 32);
            CP_WAIT(1);
        } else {
            CP_WAIT(0);
        }
        __syncthreads();
        float* As = sm + stage * 4608;
        float* Bs = sm + 9216 + stage * 5120;
#pragma unroll
        for (int ks = 0; ks < 4; ++ks) {
            int kk = ks * 8;
            wmma::fragment<wmma::matrix_a, 16, 16, 8, wmma::precision::tf32, wmma::row_major> af[4];
#pragma unroll
            for (int i = 0; i < 4; ++i) {
                wmma::load_matrix_sync(af[i], &As[(warpRow * 64 + i * 16) * 36 + kk], 36);
#pragma unroll
                for (int t = 0; t < af[i].num_elements; ++t)
                    af[i].x[t] = wmma::__float_to_tf32(af[i].x[t]);
            }
            wmma::fragment<wmma::matrix_b, 16, 16, 8, wmma::precision::tf32, wmma::row_major> bf[2];
#pragma unroll
            for (int j = 0; j < 2; ++j) {
                wmma::load_matrix_sync(bf[j], &Bs[kk * 136 + warpCol * 32 + j * 16], 136);
#pragma unroll
                for (int t = 0; t < bf[j].num_elements; ++t)
                    bf[j].x[t] = wmma::__float_to_tf32(bf[j].x[t]);
            }
#pragma unroll
            for (int i = 0; i < 4; ++i)
#pragma unroll
                for (int j = 0; j < 2; ++j) wmma::mma_sync(acc[i][j], af[i], bf[j], acc[i][j]);
        }
        __syncthreads();
    }

    float* st = &sm[wid * 384];
#pragma unroll
    for (int i = 0; i < 4; ++i) {
#pragma unroll
        for (int j = 0; j < 2; ++j) {
            wmma::store_matrix_sync(st, acc[i][j], 24, wmma::mem_row_major);
            __syncwarp();
            int row0 = bm + warpRow * 64 + i * 16;
            int col0 = bn + warpCol * 32 + j * 16;
            int r = lane >> 1, c8 = (lane & 1) * 8;
            float4 v0 = *(float4*)&st[r * 24 + c8];
            float4 v1 = *(float4*)&st[r * 24 + c8 + 4];
            v0.x = rtf(v0.x); v0.y = rtf(v0.y); v0.z = rtf(v0.z); v0.w = rtf(v0.w);
            v1.x = rtf(v1.x); v1.y = rtf(v1.y); v1.z = rtf(v1.z); v1.w = rtf(v1.w);
            float* cp = C + (size_t)(row0 + r) * N + col0 + c8;
            *(float4*)cp = v0;
            *(float4*)(cp + 4) = v1;
            __syncwarp();
        }
    }
}

__global__ void __launch_bounds__(256, 2)
wmma_gemm_fuse3(const float* A0, const float* B0, float* C0,
                const float* A1, const float* B1, float* C1,
                const float* A2, const float* B2, float* C2) {
    extern __shared__ float sm[];
    if (blockIdx.z == 0) fuse_body(A0, B0, C0, sm);
    else if (blockIdx.z == 1) fuse_body(A1, B1, C1, sm);
    else fuse_body(A2, B2, C2, sm);
}

// ==================== small GEMM body: 64x128 NT, 3-stage, ld 36 =====================
template <int EPI, int BIAS, int RND, int CVTB>
__device__ __forceinline__ void small_body(const float* __restrict__ A, const float* __restrict__ B,
                                           const float* __restrict__ bias, float* __restrict__ C,
                                           int N, int K, int bm, int bn, float* sm) {
    int tid = threadIdx.x;
    int wid = tid >> 5, lane = tid & 31;
    int warpRow = wid >> 2, warpCol = wid & 3;

    uint32_t s_base = (uint32_t)__cvta_generic_to_shared(sm);
    int ra = tid >> 3, ca = (tid & 7) * 4;

    wmma::fragment<wmma::accumulator, 16, 16, 8, float> acc[2][2];
#pragma unroll
    for (int i = 0; i < 2; ++i)
#pragma unroll
        for (int j = 0; j < 2; ++j) wmma::fill_fragment(acc[i][j], 0.0f);

    const int KT = K >> 5;
    auto issue = [&](int stage, int k0) {
        uint32_t as = s_base + (uint32_t)(stage * 2304) * 4;
        uint32_t bs = s_base + (uint32_t)(6912 + stage * 4608) * 4;
#pragma unroll
        for (int it = 0; it < 2; ++it) {
            int r = ra + it * 32;
            cp16(as + (uint32_t)(r * 36 + ca) * 4, A + (size_t)(bm + r) * K + k0 + ca);
        }
#pragma unroll
        for (int it = 0; it < 4; ++it) {
            int r = ra + it * 32;
            cp16(bs + (uint32_t)(r * 36 + ca) * 4, B + (size_t)(bn + r) * K + k0 + ca);
        }
        CP_COMMIT();
    };

    issue(0, 0);
    if (KT > 1) issue(1, 32);
    for (int kt = 0; kt < KT; ++kt) {
        if (kt + 1 < KT) CP_WAIT(1);
        else CP_WAIT(0);
        __syncthreads();
        if (kt + 2 < KT) issue((kt + 2) % 3, (kt + 2) * 32);
        int stage = kt % 3;
        float* As = sm + stage * 2304;
        float* Bs = sm + 6912 + stage * 4608;
#pragma unroll
        for (int ks = 0; ks < 4; ++ks) {
            int kk = ks * 8;
            wmma::fragment<wmma::matrix_a, 16, 16, 8, wmma::precision::tf32, wmma::row_major> af[2];
            wmma::fragment<wmma::matrix_b, 16, 16, 8, wmma::precision::tf32, wmma::col_major> bf[2];
#pragma unroll
            for (int i = 0; i < 2; ++i)
                wmma::load_matrix_sync(af[i], &As[(warpRow * 32 + i * 16) * 36 + kk], 36);
#pragma unroll
            for (int j = 0; j < 2; ++j) {
                wmma::load_matrix_sync(bf[j], &Bs[(warpCol * 32 + j * 16) * 36 + kk], 36);
                if (CVTB) {
#pragma unroll
                    for (int t = 0; t < bf[j].num_elements; ++t)
                        bf[j].x[t] = wmma::__float_to_tf32(bf[j].x[t]);
                }
            }
#pragma unroll
            for (int i = 0; i < 2; ++i)
#pragma unroll
                for (int j = 0; j < 2; ++j) wmma::mma_sync(acc[i][j], af[i], bf[j], acc[i][j]);
        }
    }
    __syncthreads();

    float* st = &sm[wid * 384];
#pragma unroll
    for (int i = 0; i < 2; ++i) {
#pragma unroll
        for (int j = 0; j < 2; ++j) {
            wmma::store_matrix_sync(st, acc[i][j], 24, wmma::mem_row_major);
            __syncwarp();
            int row0 = bm + warpRow * 32 + i * 16;
            int col0 = bn + warpCol * 32 + j * 16;
            int r = lane >> 1, c8 = (lane & 1) * 8;
            float4 v0 = *(float4*)&st[r * 24 + c8];
            float4 v1 = *(float4*)&st[r * 24 + c8 + 4];
            if (BIAS) {
                const float* bp = bias + col0 + c8;
                v0.x += bp[0]; v0.y += bp[1]; v0.z += bp[2]; v0.w += bp[3];
                v1.x += bp[4]; v1.y += bp[5]; v1.z += bp[6]; v1.w += bp[7];
            }
            if (EPI) {
                v0.x = gelu_exact(v0.x); v0.y = gelu_exact(v0.y);
                v0.z = gelu_exact(v0.z); v0.w = gelu_exact(v0.w);
                v1.x = gelu_exact(v1.x); v1.y = gelu_exact(v1.y);
                v1.z = gelu_exact(v1.z); v1.w = gelu_exact(v1.w);
            }
            if (RND) {
                v0.x = rtf(v0.x); v0.y = rtf(v0.y); v0.z = rtf(v0.z); v0.w = rtf(v0.w);
                v1.x = rtf(v1.x); v1.y = rtf(v1.y); v1.z = rtf(v1.z); v1.w = rtf(v1.w);
            }
            float* cp = C + (size_t)(row0 + r) * N + col0 + c8;
            *(float4*)cp = v0;
            *(float4*)(cp + 4) = v1;
            __syncwarp();
        }
    }
}

template <int EPI, int BIAS, int RND, int CVTB>
__global__ void __launch_bounds__(256, 2)
wmma_gemm_small(const float* __restrict__ A, const float* __restrict__ B,
                const float* __restrict__ bias, float* __restrict__ C,
                int M, int N, int K) {
    extern __shared__ float sm[];
    small_body<EPI, BIAS, RND, CVTB>(A, B, bias, C, N, K, blockIdx.y * 64, blockIdx.x * 128, sm);
}

// ==================== kv GEMM body: 128x256 NT, 3-stage, ld 36, ROW-GATHERED ==========
__device__ __forceinline__ void kv_body_m(const float* __restrict__ A, const float* __restrict__ B,
                                          const float* __restrict__ bias, float* __restrict__ C,
                                          int batch, int mt, int bn,
                                          const int* __restrict__ sidx, float* sm) {
    const int N = 2048, K = 1024;
    int tid = threadIdx.x;
    int wid = tid >> 5, lane = tid & 31;
    int warpRow = wid >> 2, warpCol = wid & 3;

    uint32_t s_base = (uint32_t)__cvta_generic_to_shared(sm);
    int ra = tid >> 3, ca = (tid & 7) * 4;
    int* idxs = (int*)(sm + 41472);
    if (tid < 128) idxs[tid] = sidx[batch * 2048 + mt * 128 + tid];
    __syncthreads();

    wmma::fragment<wmma::accumulator, 16, 16, 8, float> acc[4][4];
#pragma unroll
    for (int i = 0; i < 4; ++i)
#pragma unroll
        for (int j = 0; j < 4; ++j) wmma::fill_fragment(acc[i][j], 0.0f);

    const int KT = K >> 5;
    auto issue = [&](int stage, int k0) {
        uint32_t as = s_base + (uint32_t)(stage * 4608) * 4;
        uint32_t bs = s_base + (uint32_t)(13824 + stage * 9216) * 4;
#pragma unroll
        for (int it = 0; it < 4; ++it) {
            int r = ra + it * 32;
            int orig = idxs[r];
            orig = orig < 0 ? 0 : orig;
            cp16(as + (uint32_t)(r * 36 + ca) * 4,
                 A + ((size_t)batch * 2048 + orig) * 1024 + k0 + ca);
        }
#pragma unroll
        for (int it = 0; it < 8; ++it) {
            int r = ra + it * 32;
            cp16(bs + (uint32_t)(r * 36 + ca) * 4, B + (size_t)(bn + r) * K + k0 + ca);
        }
        CP_COMMIT();
    };

    issue(0, 0);
    issue(1, 32);
    for (int kt = 0; kt < KT; ++kt) {
        if (kt + 1 < KT) CP_WAIT(1);
        else CP_WAIT(0);
        __syncthreads();
        if (kt + 2 < KT) issue((kt + 2) % 3, (kt + 2) * 32);
        int stage = kt % 3;
        float* As = sm + stage * 4608;
        float* Bs = sm + 13824 + stage * 9216;
#pragma unroll
        for (int ks = 0; ks < 4; ++ks) {
            int kk = ks * 8;
            wmma::fragment<wmma::matrix_a, 16, 16, 8, wmma::precision::tf32, wmma::row_major> af[4];
            wmma::fragment<wmma::matrix_b, 16, 16, 8, wmma::precision::tf32, wmma::col_major> bf[4];
#pragma unroll
            for (int i = 0; i < 4; ++i)
                wmma::load_matrix_sync(af[i], &As[(warpRow * 64 + i * 16) * 36 + kk], 36);
#pragma unroll
            for (int j = 0; j < 4; ++j)
                wmma::load_matrix_sync(bf[j], &Bs[(warpCol * 64 + j * 16) * 36 + kk], 36);
#pragma unroll
            for (int i = 0; i < 4; ++i)
#pragma unroll
                for (int j = 0; j < 4; ++j) wmma::mma_sync(acc[i][j], af[i], bf[j], acc[i][j]);
        }
    }
    __syncthreads();

    float* st = &sm[wid * 384];
#pragma unroll
    for (int i = 0; i < 4; ++i) {
#pragma unroll
        for (int j = 0; j < 4; ++j) {
            wmma::store_matrix_sync(st, acc[i][j], 24, wmma::mem_row_major);
            __syncwarp();
            int r = lane >> 1, c8 = (lane & 1) * 8;
            int row_local = warpRow * 64 + i * 16 + r;
            int orig = idxs[row_local];
            int col0 = bn + warpCol * 64 + j * 16;
            if (orig >= 0) {
                float4 v0 = *(float4*)&st[r * 24 + c8];
                float4 v1 = *(float4*)&st[r * 24 + c8 + 4];
                const float* bp = bias + col0 + c8;
                v0.x = rtf(v0.x + bp[0]); v0.y = rtf(v0.y + bp[1]);
                v0.z = rtf(v0.z + bp[2]); v0.w = rtf(v0.w + bp[3]);
                v1.x = rtf(v1.x + bp[4]); v1.y = rtf(v1.y + bp[5]);
                v1.z = rtf(v1.z + bp[6]); v1.w = rtf(v1.w + bp[7]);
                float* cp = C + ((size_t)batch * 2048 + orig) * N + col0 + c8;
                *(float4*)cp = v0;
                *(float4*)(cp + 4) = v1;
            }
            __syncwarp();
        }
    }
}

// G1: masked kv GEMM + q projection
__global__ void __launch_bounds__(256, 1)
g1_kernel(const float* ctx_r, const float* Wkv, const float* bkv, float* kvb,
          const float* lat_r, const float* Wq, const float* bq, float* qh,
          const int* sidx, const int* scnt) {
    extern __shared__ float sm[];
    int bx = blockIdx.x;
    if (bx < 1024) {
        int batch = bx >> 7;
        int mt = (bx >> 3) & 15;
        if (mt * 128 >= scnt[batch]) return;
        kv_body_m(ctx_r, Wkv, bkv, kvb, batch, mt, (bx & 7) * 256, sidx, sm);
    } else {
        int idx = bx - 1024;
        small_body<0, 1, 1, 0>(lat_r, Wq, bq, qh, 1024, 1024, (idx >> 3) * 64, (idx & 7) * 128, sm);
    }
}

// ==================== scores (COMPACTED columns): 64 x 128-chunk + chunk stats ========
// Smem: Qs 64x68 @0, Ks 128x68 @4352, sidx chunk (int[128]) @13056. 52736 B.
__global__ void __launch_bounds__(256)
scores_wmma(const float* __restrict__ qh, const float* __restrict__ kv,
            const int* __restrict__ sidx, const int* __restrict__ scnt,
            float* __restrict__ scores, float* __restrict__ cstat) {
    extern __shared__ float sm[];
    float* Qs = sm;
    float* Ks = sm + 4352;
    int* sx = (int*)(sm + 13056);
    int bh = blockIdx.y;
    int b = bh >> 4, h = bh & 15;
    int s0 = blockIdx.x * 128;
    if (s0 >= scnt[b]) return;
    int tid = threadIdx.x, wid = tid >> 5, lane = tid & 31;

#pragma unroll
    for (int it = 0; it < 4; ++it) {
        int v = tid + it * 256;
        int r = v >> 4, c = (v & 15) * 4;
        *(float4*)&Qs[r * 68 + c] = *(const float4*)(qh + (size_t)(b * 64 + r) * 1024 + h * 64 + c);
    }
#pragma unroll
    for (int it = 0; it < 8; ++it) {
        int v = tid + it * 256;
        int r = v >> 4, c = (v & 15) * 4;
        int orig = sidx[b * 2048 + s0 + r];
        if ((v & 15) == 0) sx[r] = orig;
        int og = orig < 0 ? 0 : orig;
        *(float4*)&Ks[r * 68 + c] =
            *(const float4*)(kv + (size_t)(b * 2048 + og) * 2048 + h * 64 + c);
    }
    __syncthreads();

    int warpRow = wid >> 2, warpCol = wid & 3;
    wmma::fragment<wmma::accumulator, 16, 16, 8, float> acc[2][2];
#pragma unroll
    for (int i = 0; i < 2; ++i)
#pragma unroll
        for (int j = 0; j < 2; ++j) wmma::fill_fragment(acc[i][j], 0.0f);

#pragma unroll
    for (int ks = 0; ks < 8; ++ks) {
        int kk = ks * 8;
        wmma::fragment<wmma::matrix_a, 16, 16, 8, wmma::precision::tf32, wmma::row_major> af[2];
        wmma::fragment<wmma::matrix_b, 16, 16, 8, wmma::precision::tf32, wmma::col_major> bf[2];
#pragma unroll
        for (int i = 0; i < 2; ++i)
            wmma::load_matrix_sync(af[i], &Qs[(warpRow * 32 + i * 16) * 68 + kk], 68);
#pragma unroll
        for (int j = 0; j < 2; ++j)
            wmma::load_matrix_sync(bf[j], &Ks[(warpCol * 32 + j * 16) * 68 + kk], 68);
#pragma unroll
        for (int i = 0; i < 2; ++i)
#pragma unroll
            for (int j = 0; j < 2; ++j) wmma::mma_sync(acc[i][j], af[i], bf[j], acc[i][j]);
    }
    __syncthreads();

    const float NEG = __int_as_float(0xff800000);
    float* st = &sm[wid * 384];
    float* pm = sm + 3072;
    float* ps = sm + 3328;
#pragma unroll
    for (int i = 0; i < 2; ++i) {
        int r = lane >> 1, c8 = (lane & 1) * 8;
        int l = warpRow * 32 + i * 16 + r;
        float4 v0, v1, v2, v3;
        wmma::store_matrix_sync(st, acc[i][0], 24, wmma::mem_row_major);
        __syncwarp();
        v0 = *(float4*)&st[r * 24 + c8];
        v1 = *(float4*)&st[r * 24 + c8 + 4];
        __syncwarp();
        wmma::store_matrix_sync(st, acc[i][1], 24, wmma::mem_row_major);
        __syncwarp();
        v2 = *(float4*)&st[r * 24 + c8];
        v3 = *(float4*)&st[r * 24 + c8 + 4];
        __syncwarp();
        int lc0 = warpCol * 32 + c8;       // local compacted col base (v0/v1)
        int lc1 = lc0 + 16;                // (v2/v3)
        v0.x = sx[lc0 + 0] >= 0 ? v0.x * 0.125f : NEG;
        v0.y = sx[lc0 + 1] >= 0 ? v0.y * 0.125f : NEG;
        v0.z = sx[lc0 + 2] >= 0 ? v0.z * 0.125f : NEG;
        v0.w = sx[lc0 + 3] >= 0 ? v0.w * 0.125f : NEG;
        v1.x = sx[lc0 + 4] >= 0 ? v1.x * 0.125f : NEG;
        v1.y = sx[lc0 + 5] >= 0 ? v1.y * 0.125f : NEG;
        v1.z = sx[lc0 + 6] >= 0 ? v1.z * 0.125f : NEG;
        v1.w = sx[lc0 + 7] >= 0 ? v1.w * 0.125f : NEG;
        v2.x = sx[lc1 + 0] >= 0 ? v2.x * 0.125f : NEG;
        v2.y = sx[lc1 + 1] >= 0 ? v2.y * 0.125f : NEG;
        v2.z = sx[lc1 + 2] >= 0 ? v2.z * 0.125f : NEG;
        v2.w = sx[lc1 + 3] >= 0 ? v2.w * 0.125f : NEG;
        v3.x = sx[lc1 + 4] >= 0 ? v3.x * 0.125f : NEG;
        v3.y = sx[lc1 + 5] >= 0 ? v3.y * 0.125f : NEG;
        v3.z = sx[lc1 + 6] >= 0 ? v3.z * 0.125f : NEG;
        v3.w = sx[lc1 + 7] >= 0 ? v3.w * 0.125f : NEG;
        float* pp = scores + ((size_t)bh * 64 + l) * 2048 + s0 + lc0;
        *(float4*)pp = v0;
        *(float4*)(pp + 4) = v1;
        *(float4*)(pp + 16) = v2;
        *(float4*)(pp + 20) = v3;
        float mx = fmaxf(fmaxf(fmaxf(v0.x, v0.y), fmaxf(v0.z, v0.w)),
                         fmaxf(fmaxf(v1.x, v1.y), fmaxf(v1.z, v1.w)));
        mx = fmaxf(mx, fmaxf(fmaxf(fmaxf(v2.x, v2.y), fmaxf(v2.z, v2.w)),
                             fmaxf(fmaxf(v3.x, v3.y), fmaxf(v3.z, v3.w))));
        float m2 = fmaxf(mx, __shfl_xor_sync(0xffffffffu, mx, 1));
        float m2c = fmaxf(m2, -1e30f);
        float s = expf(v0.x - m2c) + expf(v0.y - m2c) + expf(v0.z - m2c) + expf(v0.w - m2c) +
                  expf(v1.x - m2c) + expf(v1.y - m2c) + expf(v1.z - m2c) + expf(v1.w - m2c) +
                  expf(v2.x - m2c) + expf(v2.y - m2c) + expf(v2.z - m2c) + expf(v2.w - m2c) +
                  expf(v3.x - m2c) + expf(v3.y - m2c) + expf(v3.z - m2c) + expf(v3.w - m2c);
        s += __shfl_xor_sync(0xffffffffu, s, 1);
        if ((lane & 1) == 0) {
            pm[l * 4 + warpCol] = m2;
            ps[l * 4 + warpCol] = s;
        }
    }
    __syncthreads();
    if (tid < 64) {
        float m0 = pm[tid * 4], m1 = pm[tid * 4 + 1], m2 = pm[tid * 4 + 2], m3 = pm[tid * 4 + 3];
        float m = fmaxf(fmaxf(m0, m1), fmaxf(m2, m3));
        float mc = fmaxf(m, -1e30f);
        float S = ps[tid * 4] * expf(m0 - mc) + ps[tid * 4 + 1] * expf(m1 - mc) +
                  ps[tid * 4 + 2] * expf(m2 - mc) + ps[tid * 4 + 3] * expf(m3 - mc);
        float2 o;
        o.x = m;
        o.y = S;
        *(float2*)&cstat[(((size_t)bh * 64 + tid) * 16 + blockIdx.x) * 2] = o;
    }
}

// ---------------- rowstat: fold ACTIVE chunk stats -> (max, 1/sum) per row ------------
__global__ void rowstat_kernel(const float* __restrict__ cstat, const int* __restrict__ scnt,
                               float* __restrict__ rowstat) {
    int row = blockIdx.x * 256 + threadIdx.x;
    int b = row >> 10;
    int nch = scnt[b] >> 7;
    const float2* c = (const float2*)cstat + row * 16;
    float M = __int_as_float(0xff800000);
    for (int k = 0; k < nch; ++k) M = fmaxf(M, c[k].x);
    float Mc = fmaxf(M, -1e30f);
    float S = 0.f;
    for (int k = 0; k < nch; ++k) S += c[k].y * expf(c[k].x - Mc);
    float2 o;
    o.x = Mc;
    o.y = 1.0f / S;
    ((float2*)rowstat)[row] = o;
}

// ==================== attn split-K (COMPACTED): inline softmax, V gathered ============
__device__ __forceinline__ void attn_body(const float* __restrict__ scores,
                                          const float* __restrict__ kv,
                                          const float* __restrict__ rowstat,
                                          const int* __restrict__ sidx,
                                          float* __restrict__ part,
                                          int bh, int split, int cnt, float* sm) {
    int b = bh >> 4, h = bh & 15;
    int base_s = split * 512;
    int ktmax = cnt - base_s;
    ktmax = (ktmax > 512 ? 512 : ktmax) >> 6;   // chunks of 64 (cnt multiple of 128 => >=2)
    int tid = threadIdx.x, wid = tid >> 5, lane = tid & 31;
    int warpRow = wid >> 1, warpCol = wid & 1;

    uint32_t s_base = (uint32_t)__cvta_generic_to_shared(sm);
    int ra = tid >> 4, ca = (tid & 15) * 4;
    float* rs_m = sm + 26112;
    float* rs_i = sm + 26176;
    if (tid < 64) {
        float2 v = ((const float2*)rowstat)[bh * 64 + tid];
        rs_m[tid] = v.x;
        rs_i[tid] = v.y;
    }

    wmma::fragment<wmma::accumulator, 16, 16, 8, float> acc[2];
    wmma::fill_fragment(acc[0], 0.0f);
    wmma::fill_fragment(acc[1], 0.0f);

    auto issue = [&](int stage, int s0) {
        uint32_t ps = s_base + (uint32_t)(stage * 4352) * 4;
        uint32_t vs = s_base + (uint32_t)(13056 + stage * 4352) * 4;
#pragma unroll
        for (int it = 0; it < 4; ++it) {
            int r = ra + it * 16;
            cp16(ps + (uint32_t)(r * 68 + ca) * 4,
                 scores + ((size_t)bh * 64 + r) * 2048 + s0 + ca);
            int orig = sidx[b * 2048 + s0 + r];
            orig = orig < 0 ? 0 : orig;
            cp16(vs + (uint32_t)(r * 68 + ca) * 4,
                 kv + (size_t)(b * 2048 + orig) * 2048 + 1024 + h * 64 + ca);
        }
        CP_COMMIT();
    };

    issue(0, base_s);
    if (ktmax > 1) issue(1, base_s + 64);
    for (int kt = 0; kt < ktmax; ++kt) {
        if (kt + 1 < ktmax) CP_WAIT(1);
        else CP_WAIT(0);
        __syncthreads();
        int stage = kt % 3;
        float* Ps = sm + stage * 4352;
#pragma unroll
        for (int it = 0; it < 4; ++it) {
            int rr = ra + it * 16;
            float M = rs_m[rr], I = rs_i[rr];
            float4 v = *(float4*)&Ps[rr * 68 + ca];
            v.x = rtf(expf(v.x - M) * I);
            v.y = rtf(expf(v.y - M) * I);
            v.z = rtf(expf(v.z - M) * I);
            v.w = rtf(expf(v.w - M) * I);
            *(float4*)&Ps[rr * 68 + ca] = v;
        }
        __syncthreads();
        if (kt + 2 < ktmax) issue((kt + 2) % 3, base_s + (kt + 2) * 64);
        float* Vs = sm + 13056 + stage * 4352;
#pragma unroll
        for (int ks = 0; ks < 8; ++ks) {
            int kk = ks * 8;
            wmma::fragment<wmma::matrix_a, 16, 16, 8, wmma::precision::tf32, wmma::row_major> af;
            wmma::fragment<wmma::matrix_b, 16, 16, 8, wmma::precision::tf32, wmma::row_major> bf[2];
            wmma::load_matrix_sync(af, &Ps[(warpRow * 16) * 68 + kk], 68);
#pragma unroll
            for (int j = 0; j < 2; ++j)
                wmma::load_matrix_sync(bf[j], &Vs[kk * 68 + warpCol * 32 + j * 16], 68);
            wmma::mma_sync(acc[0], af, bf[0], acc[0]);
            wmma::mma_sync(acc[1], af, bf[1], acc[1]);
        }
    }
    __syncthreads();

    float* pout = part + (size_t)split * 524288;
    float* st = &sm[wid * 384];
#pragma unroll
    for (int j = 0; j < 2; ++j) {
        wmma::store_matrix_sync(st, acc[j], 24, wmma::mem_row_major);
        __syncwarp();
        int r = lane >> 1, c8 = (lane & 1) * 8;
        int l = warpRow * 16 + r;
        int d0 = warpCol * 32 + j * 16 + c8;
        float4 v0 = *(float4*)&st[r * 24 + c8];
        float4 v1 = *(float4*)&st[r * 24 + c8 + 4];
        float* ap = pout + (size_t)(b * 64 + l) * 1024 + h * 64 + d0;
        *(float4*)ap = v0;
        *(float4*)(ap + 4) = v1;
        __syncwarp();
    }
}

// A1: attn_part (blocks 0..511) + mean_heads scatter (blocks 512..1535)
__global__ void __launch_bounds__(256, 2)
a1_kernel(const float* __restrict__ scores, const float* __restrict__ kv,
          const float* __restrict__ rowstat, const int* __restrict__ sidx,
          const int* __restrict__ scnt, float* __restrict__ part,
          float* __restrict__ aw) {
    extern __shared__ float sm[];
    int bx = blockIdx.x;
    if (bx < 512) {
        int bh = bx >> 2, split = bx & 3;
        int cnt = scnt[bh >> 4];
        if (split * 512 >= cnt) return;
        attn_body(scores, kv, rowstat, sidx, part, bh, split, cnt, sm);
    } else {
        int i = (bx - 512) * 256 + threadIdx.x;
        int s4 = i & 511;          // compacted f4 column index
        int l = (i >> 9) & 63;
        int b = i >> 15;
        if (s4 * 4 >= scnt[b]) return;
        int4 orig = *(const int4*)&sidx[b * 2048 + s4 * 4];
        float4 acc = {0.f, 0.f, 0.f, 0.f};
#pragma unroll
        for (int h = 0; h < 16; ++h) {
            size_t row = (size_t)(b * 16 + h) * 64 + l;
            float2 stt = ((const float2*)rowstat)[row];
            float4 x = *(const float4*)(scores + row * 2048 + s4 * 4);
            acc.x += expf(x.x - stt.x) * stt.y;
            acc.y += expf(x.y - stt.x) * stt.y;
            acc.z += expf(x.z - stt.x) * stt.y;
            acc.w += expf(x.w - stt.x) * stt.y;
        }
        const float inv = 1.0f / 16.0f;
        float* arow = aw + (size_t)(b * 64 + l) * 2048;
        if (orig.x >= 0) arow[orig.x] = acc.x * inv;
        if (orig.y >= 0) arow[orig.y] = acc.y * inv;
        if (orig.z >= 0) arow[orig.z] = acc.z * inv;
        if (orig.w >= 0) arow[orig.w] = acc.w * inv;
    }
}

// reduce ACTIVE partials -> attn (tf32-rounded)
__global__ void attn_reduce_kernel(const float* __restrict__ part, const int* __restrict__ scnt,
                                   float* __restrict__ attn) {
    int i = blockIdx.x * 256 + threadIdx.x;   // f4 units, 131072
    int b = i >> 14;
    int ns = (scnt[b] + 511) >> 9;
    float4 a = ((const float4*)part)[i];
    float4 o = a;
    if (ns > 1) {
        float4 v = ((const float4*)(part + 524288))[i];
        o.x += v.x; o.y += v.y; o.z += v.z; o.w += v.w;
    }
    if (ns > 2) {
        float4 v = ((const float4*)(part + 1048576))[i];
        o.x += v.x; o.y += v.y; o.z += v.z; o.w += v.w;
    }
    if (ns > 3) {
        float4 v = ((const float4*)(part + 1572864))[i];
        o.x += v.x; o.y += v.y; o.z += v.z; o.w += v.w;
    }
    o.x = rtf(o.x); o.y = rtf(o.y); o.z = rtf(o.z); o.w = rtf(o.w);
    ((float4*)attn)[i] = o;
}

// ---------------- residual add + LayerNorm (optional rounded copy) ----------------
template <int WR>
__global__ void add_ln_kernel(const float* __restrict__ a, const float* __restrict__ b2,
                              const float* __restrict__ g, const float* __restrict__ bet,
                              float* __restrict__ out, float* __restrict__ out_r) {
    int row = blockIdx.x, tid = threadIdx.x;
    const float4* a4 = (const float4*)(a + (size_t)row * 1024);
    const float4* b4 = (const float4*)(b2 + (size_t)row * 1024);
    float4 va = a4[tid], vb = b4[tid];
    float4 x;
    x.x = va.x + vb.x; x.y = va.y + vb.y; x.z = va.z + vb.z; x.w = va.w + vb.w;
    float s = (x.x + x.y) + (x.z + x.w);
    float sq = x.x * x.x + x.y * x.y + x.z * x.z + x.w * x.w;
    __shared__ float r1[256], r2[256];
    r1[tid] = s; r2[tid] = sq;
    __syncthreads();
    for (int st = 128; st > 0; st >>= 1) {
        if (tid < st) { r1[tid] += r1[tid + st]; r2[tid] += r2[tid + st]; }
        __syncthreads();
    }
    float mean = r1[0] * (1.0f / 1024.0f);
    float var = r2[0] * (1.0f / 1024.0f) - mean * mean;
    float rstd = rsqrtf(var + 1e-5f);
    float4 gg = ((const float4*)g)[tid], bb = ((const float4*)bet)[tid];
    float4 o;
    o.x = (x.x - mean) * rstd * gg.x + bb.x;
    o.y = (x.y - mean) * rstd * gg.y + bb.y;
    o.z = (x.z - mean) * rstd * gg.z + bb.z;
    o.w = (x.w - mean) * rstd * gg.w + bb.w;
    ((float4*)(out + (size_t)row * 1024))[tid] = o;
    if (WR) {
        float4 q;
        q.x = rtf(o.x); q.y = rtf(o.y); q.z = rtf(o.z); q.w = rtf(o.w);
        ((float4*)(out_r + (size_t)row * 1024))[tid] = q;
    }
}

// ---------------- launch ----------------
extern "C" void kernel_launch(void* const* d_in, const int* in_sizes, int n_in,
                              void* d_out, int out_size) {
    (void)in_sizes; (void)n_in; (void)out_size;
    const float* latents = (const float*)d_in[0];
    const float* context = (const float*)d_in[1];
    const int* cmask = (const int*)d_in[2];
    const float* q_w = (const float*)d_in[3];
    const float* q_b = (const float*)d_in[4];
    const float* k_w = (const float*)d_in[5];
    const float* k_b = (const float*)d_in[6];
    const float* v_w = (const float*)d_in[7];
    const float* v_b = (const float*)d_in[8];
    const float* in_wq = (const float*)d_in[9];
    const float* in_bq = (const float*)d_in[10];
    const float* in_wk = (const float*)d_in[11];
    const float* in_bk = (const float*)d_in[12];
    const float* in_wv = (const float*)d_in[13];
    const float* in_bv = (const float*)d_in[14];
    const float* out_w = (const float*)d_in[15];
    const float* out_b = (const float*)d_in[16];
    const float* ln1_g = (const float*)d_in[17];
    const float* ln1_b = (const float*)d_in[18];
    const float* ln2_g = (const float*)d_in[19];
    const float* ln2_b = (const float*)d_in[20];
    const float* ff_w1 = (const float*)d_in[21];
    const float* ff_b1 = (const float*)d_in[22];
    const float* ff_w2 = (const float*)d_in[23];
    const float* ff_b2 = (const float*)d_in[24];

    float* out = (float*)d_out;
    float* aw_out = out + 512 * 1024;

    void* p;
    cudaGetSymbolAddress(&p, g_ctx_r);   float* ctx_r = (float*)p;
    cudaGetSymbolAddress(&p, g_lat_r);   float* lat_r = (float*)p;
    cudaGetSymbolAddress(&p, g_Wq);      float* Wq = (float*)p;
    cudaGetSymbolAddress(&p, g_Wkv);     float* Wkv = (float*)p;
    cudaGetSymbolAddress(&p, g_bq);      float* bq = (float*)p;
    cudaGetSymbolAddress(&p, g_bkv);     float* bkv = (float*)p;
    cudaGetSymbolAddress(&p, g_qh);      float* qh = (float*)p;
    cudaGetSymbolAddress(&p, g_kv);      float* kvb = (float*)p;
    cudaGetSymbolAddress(&p, g_scores);  float* scores = (float*)p;
    cudaGetSymbolAddress(&p, g_cstat);   float* cstat = (float*)p;
    cudaGetSymbolAddress(&p, g_rowstat); float* rowstat = (float*)p;
    cudaGetSymbolAddress(&p, g_part);    float* part = (float*)p;
    cudaGetSymbolAddress(&p, g_attn);    float* attn = (float*)p;
    cudaGetSymbolAddress(&p, g_x);       float* xb = (float*)p;
    cudaGetSymbolAddress(&p, g_xr);      float* xr = (float*)p;
    cudaGetSymbolAddress(&p, g_h1);      float* h1 = (float*)p;
    cudaGetSymbolAddress(&p, g_sidx);    int* sidx = (int*)p;
    cudaGetSymbolAddress(&p, g_scnt);    int* scnt = (int*)p;

    cudaFuncSetAttribute(wmma_gemm_fuse3, cudaFuncAttributeMaxDynamicSharedMemorySize, 77824);
    cudaFuncSetAttribute(wmma_gemm_small<0, 1, 0, 1>, cudaFuncAttributeMaxDynamicSharedMemorySize, 82944);
    cudaFuncSetAttribute(wmma_gemm_small<1, 1, 1, 1>, cudaFuncAttributeMaxDynamicSharedMemorySize, 82944);
    cudaFuncSetAttribute(g1_kernel, cudaFuncAttributeMaxDynamicSharedMemorySize, 166400);
    cudaFuncSetAttribute(scores_wmma, cudaFuncAttributeMaxDynamicSharedMemorySize, 52736);
    cudaFuncSetAttribute(a1_kernel, cudaFuncAttributeMaxDynamicSharedMemorySize, 104960);

    // ---- merged prologue: round ctx+lat + fused biases + compaction + aw zero ----
    prologue_kernel<<<21000, 256>>>(
        (const float4*)context, (float4*)ctx_r,
        (const float4*)latents, (float4*)lat_r,
        in_wq, q_b, in_bq, in_wk, k_b, in_bk, in_wv, v_b, in_bv, bq, bkv,
        cmask, sidx, scnt, (float4*)aw_out);

    // ---- fused weights (in-fragment tf32 cvt on raw inputs) ----
    const size_t MM = 1024 * 1024;
    wmma_gemm_fuse3<<<dim3(8, 8, 3), 256, 77824>>>(
        in_wq, q_w, Wq,
        in_wk, k_w, Wkv,
        in_wv, v_w, Wkv + MM);

    // ---- G1: masked-compacted kv projection + q projection (merged) ----
    g1_kernel<<<1088, 256, 166400>>>(ctx_r, Wkv, bkv, kvb, lat_r, Wq, bq, qh, sidx, scnt);

    // ---- attention on compacted columns ----
    scores_wmma<<<dim3(16, 128), 256, 52736>>>(qh, kvb, sidx, scnt, scores, cstat);
    rowstat_kernel<<<32, 256>>>(cstat, scnt, rowstat);
    a1_kernel<<<1536, 256, 104960>>>(scores, kvb, rowstat, sidx, scnt, part, aw_out);
    attn_reduce_kernel<<<512, 256>>>(part, scnt, attn);

    // ---- out projection (in-fragment cvt of out_w; reuse qh for attn_out) ----
    wmma_gemm_small<0, 1, 0, 1><<<dim3(8, 8), 256, 82944>>>(attn, out_w, out_b, qh, 512, 1024, 1024);

    // ---- LN1 (exact + rounded copy) ----
    add_ln_kernel<1><<<512, 256>>>(latents, qh, ln1_g, ln1_b, xb, xr);

    // ---- FFN (in-fragment cvt of ff weights) ----
    wmma_gemm_small<1, 1, 1, 1><<<dim3(32, 8), 256, 82944>>>(xr, ff_w1, ff_b1, h1, 512, 4096, 1024);
    wmma_gemm_small<0, 1, 0, 1><<<dim3(8, 8), 256, 82944>>>(h1, ff_w2, ff_b2, attn, 512, 1024, 4096);

    // ---- LN2 -> out ----
    add_ln_kernel<0><<<512, 256>>>(xb, attn, ln2_g, ln2_b, out, nullptr);
}

// round 14
// speedup vs baseline: 1.4405x; 1.0401x over previous
#include <cuda_runtime.h>
#include <mma.h>
#include <math.h>
#include <stdint.h>

using namespace nvcuda;

// Shapes: B=8, L=64, S=2048, D=1024, C=1024, H=16, HD=64

// ---------------- device scratch ----------------
__device__ float g_ctx_r[16384 * 1024];
__device__ float g_lat_r[512 * 1024];
__device__ float g_Wq[1024 * 1024];
__device__ float g_Wkv[2048 * 1024];
__device__ float g_bq[1024];
__device__ float g_bkv[2048];
__device__ float g_qh[512 * 1024];
__device__ float g_kv[16384 * 2048];        // masked rows stay 0 (never observed)
__device__ float g_scores[8192 * 2048];     // COMPACTED columns per batch
__device__ float g_cstat[8192 * 32];
__device__ float g_rowstat[8192 * 2];
__device__ float g_part[4 * 512 * 1024];    // attn split-K partials; later GEMM split-K
__device__ float g_attn[512 * 1024];
__device__ float g_x[512 * 1024];
__device__ float g_xr[512 * 1024];
__device__ float g_h1[512 * 4096];
__device__ int g_sidx[8 * 2048];
__device__ int g_scnt[8];

__device__ __forceinline__ float gelu_exact(float x) {
    return 0.5f * x * (1.0f + erff(x * 0.70710678118654752f));
}
__device__ __forceinline__ float rtf(float x) {
    float y;
    asm("cvt.rna.tf32.f32 %0, %1;" : "=f"(y) : "f"(x));
    return y;
}
__device__ __forceinline__ void cp16(uint32_t dst, const void* src) {
    asm volatile("cp.async.cg.shared.global [%0], [%1], 16;\n" ::"r"(dst), "l"(src));
}
#define CP_COMMIT() asm volatile("cp.async.commit_group;\n" ::)
#define CP_WAIT(n) asm volatile("cp.async.wait_group %0;\n" ::"n"(n))

// ==================== weight-fusion GEMM body 128x128 NN (in-fragment cvt) ===========
__device__ __forceinline__ void fuse_body(const float* __restrict__ A, const float* __restrict__ B,
                                          float* __restrict__ C, int bm, int bn, float* sm) {
    const int N = 1024, K = 1024;
    int tid = threadIdx.x;
    int wid = tid >> 5, lane = tid & 31;
    int warpRow = wid >> 2, warpCol = wid & 3;

    uint32_t s_base = (uint32_t)__cvta_generic_to_shared(sm);
    int ra = tid >> 3, ca = (tid & 7) * 4;
    int kb = tid >> 5, cb = (tid & 31) * 4;

    wmma::fragment<wmma::accumulator, 16, 16, 8, float> acc[4][2];
#pragma unroll
    for (int i = 0; i < 4; ++i)
#pragma unroll
        for (int j = 0; j < 2; ++j) wmma::fill_fragment(acc[i][j], 0.0f);

    const int KT = K >> 5;
    auto issue = [&](int stage, int k0) {
        uint32_t as = s_base + (uint32_t)(stage * 4608) * 4;
        uint32_t bs = s_base + (uint32_t)(9216 + stage * 5120) * 4;
#pragma unroll
        for (int it = 0; it < 4; ++it) {
            int r = ra + it * 32;
            cp16(as + (uint32_t)(r * 36 + ca) * 4, A + (size_t)(bm + r) * K + k0 + ca);
        }
#pragma unroll
        for (int it = 0; it < 4; ++it) {
            int kk = kb + it * 8;
            cp16(bs + (uint32_t)(kk * 136 + cb) * 4, B + (size_t)(k0 + kk) * N + bn + cb);
        }
        CP_COMMIT();
    };

    issue(0, 0);
    for (int kt = 0; kt < KT; ++kt) {
        int stage = kt & 1;
        if (kt + 1 < KT) {
            issue(stage ^ 1, (kt + 1) * 32);
            CP_WAIT(1);
        } else {
            CP_WAIT(0);
        }
        __syncthreads();
        float* As = sm + stage * 4608;
        float* Bs = sm + 9216 + stage * 5120;
#pragma unroll
        for (int ks = 0; ks < 4; ++ks) {
            int kk = ks * 8;
            wmma::fragment<wmma::matrix_a, 16, 16, 8, wmma::precision::tf32, wmma::row_major> af[4];
#pragma unroll
            for (int i = 0; i < 4; ++i) {
                wmma::load_matrix_sync(af[i], &As[(warpRow * 64 + i * 16) * 36 + kk], 36);
#pragma unroll
                for (int t = 0; t < af[i].num_elements; ++t)
                    af[i].x[t] = wmma::__float_to_tf32(af[i].x[t]);
            }
            wmma::fragment<wmma::matrix_b, 16, 16, 8, wmma::precision::tf32, wmma::row_major> bf[2];
#pragma unroll
            for (int j = 0; j < 2; ++j) {
                wmma::load_matrix_sync(bf[j], &Bs[kk * 136 + warpCol * 32 + j * 16], 136);
#pragma unroll
                for (int t = 0; t < bf[j].num_elements; ++t)
                    bf[j].x[t] = wmma::__float_to_tf32(bf[j].x[t]);
            }
#pragma unroll
            for (int i = 0; i < 4; ++i)
#pragma unroll
                for (int j = 0; j < 2; ++j) wmma::mma_sync(acc[i][j], af[i], bf[j], acc[i][j]);
        }
        __syncthreads();
    }

    float* st = &sm[wid * 384];
#pragma unroll
    for (int i = 0; i < 4; ++i) {
#pragma unroll
        for (int j = 0; j < 2; ++j) {
            wmma::store_matrix_sync(st, acc[i][j], 24, wmma::mem_row_major);
            __syncwarp();
            int row0 = bm + warpRow * 64 + i * 16;
            int col0 = bn + warpCol * 32 + j * 16;
            int r = lane >> 1, c8 = (lane & 1) * 8;
            float4 v0 = *(float4*)&st[r * 24 + c8];
            float4 v1 = *(float4*)&st[r * 24 + c8 + 4];
            v0.x = rtf(v0.x); v0.y = rtf(v0.y); v0.z = rtf(v0.z); v0.w = rtf(v0.w);
            v1.x = rtf(v1.x); v1.y = rtf(v1.y); v1.z = rtf(v1.z); v1.w = rtf(v1.w);
            float* cp = C + (size_t)(row0 + r) * N + col0 + c8;
            *(float4*)cp = v0;
            *(float4*)(cp + 4) = v1;
            __syncwarp();
        }
    }
}

// ==================== MEGA PROLOGUE: fuse3 + rounding + biases + compaction + aw zero =
// blocks [0,192): weight-fusion GEMMs (z=bx/64); [192,17088): rounding;
// [17088,20160): fuse_bias; [20160,20168): compaction; [20168,21192): aw zero
__global__ void __launch_bounds__(256)
mega_prologue(
    const float* in_wq, const float* q_w, float* Wq,
    const float* in_wk, const float* k_w, float* Wkv0,
    const float* in_wv, const float* v_w, float* Wkv1,
    const float4* context, float4* ctx_r,
    const float4* latents4, float4* lat_r,
    const float* q_b, const float* in_bq,
    const float* k_b, const float* in_bk,
    const float* v_b, const float* in_bv,
    float* bq, float* bkv, const int* cmask, int* sidx, int* scnt,
    float4* aw4) {
    extern __shared__ float sm[];
    __shared__ float red[256];
    __shared__ int sc[256];
    int bx = blockIdx.x, tid = threadIdx.x;
    if (bx < 192) {
        int z = bx >> 6, t = bx & 63;
        int bm = (t >> 3) * 128, bn = (t & 7) * 128;
        if (z == 0) fuse_body(in_wq, q_w, Wq, bm, bn, sm);
        else if (z == 1) fuse_body(in_wk, k_w, Wkv0, bm, bn, sm);
        else fuse_body(in_wv, v_w, Wkv1, bm, bn, sm);
    } else if (bx < 17088) {
        int i = (bx - 192) * 256 + tid;
        const float4* s;
        float4* d;
        int off;
        if (i < 4194304) { s = context; d = ctx_r; off = i; }
        else { i -= 4194304; s = latents4; d = lat_r; off = i; }
        float4 v = s[off];
        v.x = rtf(v.x); v.y = rtf(v.y); v.z = rtf(v.z); v.w = rtf(v.w);
        d[off] = v;
    } else if (bx < 20160) {
        int idx = bx - 17088;
        int z = idx >> 10, o = idx & 1023;
        const float* W = (z == 0) ? in_wq : (z == 1) ? in_wk : in_wv;
        const float* bin = (z == 0) ? q_b : (z == 1) ? k_b : v_b;
        const float* badd = (z == 0) ? in_bq : (z == 1) ? in_bk : in_bv;
        float* bout = (z == 0) ? bq : (z == 1) ? bkv : (bkv + 1024);
        float s = 0.f;
        for (int i = tid; i < 1024; i += 256) s += W[o * 1024 + i] * bin[i];
        red[tid] = s;
        __syncthreads();
        for (int st = 128; st > 0; st >>= 1) {
            if (tid < st) red[tid] += red[tid + st];
            __syncthreads();
        }
        if (tid == 0) bout[o] = red[0] + badd[o];
    } else if (bx < 20168) {
        int bb = bx - 20160;
        const int* m = cmask + bb * 2048;
        int base_s = tid * 8;
        int mv[8];
        int cnt = 0;
#pragma unroll
        for (int j = 0; j < 8; ++j) {
            mv[j] = m[base_s + j];
            cnt += (mv[j] != 0);
        }
        sc[tid] = cnt;
        __syncthreads();
        for (int off = 1; off < 256; off <<= 1) {
            int v = (tid >= off) ? sc[tid - off] : 0;
            __syncthreads();
            sc[tid] += v;
            __syncthreads();
        }
        int pos = sc[tid] - cnt;
        int total = sc[255];
#pragma unroll
        for (int j = 0; j < 8; ++j)
            if (mv[j]) sidx[bb * 2048 + pos++] = base_s + j;
        int padded = (total + 127) & ~127;
        for (int i = total + tid; i < padded; i += 256) sidx[bb * 2048 + i] = -1;
        if (tid == 0) scnt[bb] = padded;
    } else {
        int i = (bx - 20168) * 256 + tid;
        float4 z = {0.f, 0.f, 0.f, 0.f};
        aw4[i] = z;
    }
}

// ==================== small GEMM body: 64x128 NT, 3-stage, ld 36, generic K ==========
// A/B row stride = lda; loop over ksz (A,B pre-offset for split-K).
template <int EPI, int BIAS, int RND, int CVTB>
__device__ __forceinline__ void small_body(const float* __restrict__ A, const float* __restrict__ B,
                                           const float* __restrict__ bias, float* __restrict__ C,
                                           int N, int lda, int ksz, int bm, int bn, float* sm) {
    int tid = threadIdx.x;
    int wid = tid >> 5, lane = tid & 31;
    int warpRow = wid >> 2, warpCol = wid & 3;

    uint32_t s_base = (uint32_t)__cvta_generic_to_shared(sm);
    int ra = tid >> 3, ca = (tid & 7) * 4;

    wmma::fragment<wmma::accumulator, 16, 16, 8, float> acc[2][2];
#pragma unroll
    for (int i = 0; i < 2; ++i)
#pragma unroll
        for (int j = 0; j < 2; ++j) wmma::fill_fragment(acc[i][j], 0.0f);

    const int KT = ksz >> 5;
    auto issue = [&](int stage, int k0) {
        uint32_t as = s_base + (uint32_t)(stage * 2304) * 4;
        uint32_t bs = s_base + (uint32_t)(6912 + stage * 4608) * 4;
#pragma unroll
        for (int it = 0; it < 2; ++it) {
            int r = ra + it * 32;
            cp16(as + (uint32_t)(r * 36 + ca) * 4, A + (size_t)(bm + r) * lda + k0 + ca);
        }
#pragma unroll
        for (int it = 0; it < 4; ++it) {
            int r = ra + it * 32;
            cp16(bs + (uint32_t)(r * 36 + ca) * 4, B + (size_t)(bn + r) * lda + k0 + ca);
        }
        CP_COMMIT();
    };

    issue(0, 0);
    if (KT > 1) issue(1, 32);
    for (int kt = 0; kt < KT; ++kt) {
        if (kt + 1 < KT) CP_WAIT(1);
        else CP_WAIT(0);
        __syncthreads();
        if (kt + 2 < KT) issue((kt + 2) % 3, (kt + 2) * 32);
        int stage = kt % 3;
        float* As = sm + stage * 2304;
        float* Bs = sm + 6912 + stage * 4608;
#pragma unroll
        for (int ks = 0; ks < 4; ++ks) {
            int kk = ks * 8;
            wmma::fragment<wmma::matrix_a, 16, 16, 8, wmma::precision::tf32, wmma::row_major> af[2];
            wmma::fragment<wmma::matrix_b, 16, 16, 8, wmma::precision::tf32, wmma::col_major> bf[2];
#pragma unroll
            for (int i = 0; i < 2; ++i)
                wmma::load_matrix_sync(af[i], &As[(warpRow * 32 + i * 16) * 36 + kk], 36);
#pragma unroll
            for (int j = 0; j < 2; ++j) {
                wmma::load_matrix_sync(bf[j], &Bs[(warpCol * 32 + j * 16) * 36 + kk], 36);
                if (CVTB) {
#pragma unroll
                    for (int t = 0; t < bf[j].num_elements; ++t)
                        bf[j].x[t] = wmma::__float_to_tf32(bf[j].x[t]);
                }
            }
#pragma unroll
            for (int i = 0; i < 2; ++i)
#pragma unroll
                for (int j = 0; j < 2; ++j) wmma::mma_sync(acc[i][j], af[i], bf[j], acc[i][j]);
        }
    }
    __syncthreads();

    float* st = &sm[wid * 384];
#pragma unroll
    for (int i = 0; i < 2; ++i) {
#pragma unroll
        for (int j = 0; j < 2; ++j) {
            wmma::store_matrix_sync(st, acc[i][j], 24, wmma::mem_row_major);
            __syncwarp();
            int row0 = bm + warpRow * 32 + i * 16;
            int col0 = bn + warpCol * 32 + j * 16;
            int r = lane >> 1, c8 = (lane & 1) * 8;
            float4 v0 = *(float4*)&st[r * 24 + c8];
            float4 v1 = *(float4*)&st[r * 24 + c8 + 4];
            if (BIAS) {
                const float* bp = bias + col0 + c8;
                v0.x += bp[0]; v0.y += bp[1]; v0.z += bp[2]; v0.w += bp[3];
                v1.x += bp[4]; v1.y += bp[5]; v1.z += bp[6]; v1.w += bp[7];
            }
            if (EPI) {
                v0.x = gelu_exact(v0.x); v0.y = gelu_exact(v0.y);
                v0.z = gelu_exact(v0.z); v0.w = gelu_exact(v0.w);
                v1.x = gelu_exact(v1.x); v1.y = gelu_exact(v1.y);
                v1.z = gelu_exact(v1.z); v1.w = gelu_exact(v1.w);
            }
            if (RND) {
                v0.x = rtf(v0.x); v0.y = rtf(v0.y); v0.z = rtf(v0.z); v0.w = rtf(v0.w);
                v1.x = rtf(v1.x); v1.y = rtf(v1.y); v1.z = rtf(v1.z); v1.w = rtf(v1.w);
            }
            float* cp = C + (size_t)(row0 + r) * N + col0 + c8;
            *(float4*)cp = v0;
            *(float4*)(cp + 4) = v1;
            __syncwarp();
        }
    }
}

template <int EPI, int BIAS, int RND, int CVTB>
__global__ void __launch_bounds__(256, 2)
wmma_gemm_small(const float* __restrict__ A, const float* __restrict__ B,
                const float* __restrict__ bias, float* __restrict__ C,
                int N, int lda, int ksz) {
    extern __shared__ float sm[];
    small_body<EPI, BIAS, RND, CVTB>(A, B, bias, C, N, lda, ksz,
                                     blockIdx.y * 64, blockIdx.x * 128, sm);
}

// split-K partial GEMM: z = split, A/B offset by z*ksz, raw partial into part+z*524288
template <int CVTB>
__global__ void __launch_bounds__(256, 2)
wmma_gemm_splitk(const float* __restrict__ A, const float* __restrict__ B,
                 float* __restrict__ part, int lda, int ksz) {
    extern __shared__ float sm[];
    int z = blockIdx.z;
    small_body<0, 0, 0, CVTB>(A + (size_t)z * ksz, B + (size_t)z * ksz, nullptr,
                              part + (size_t)z * 524288, 1024, lda, ksz,
                              blockIdx.y * 64, blockIdx.x * 128, sm);
}

// reduce NS split-K partials + bias -> dst [512,1024]
template <int NS>
__global__ void splitk_reduce_kernel(const float* __restrict__ part,
                                     const float* __restrict__ bias, float* __restrict__ dst) {
    int i = blockIdx.x * 256 + threadIdx.x;   // f4 units, 131072
    float4 o = ((const float4*)part)[i];
#pragma unroll
    for (int s = 1; s < NS; ++s) {
        float4 v = ((const float4*)(part + (size_t)s * 524288))[i];
        o.x += v.x; o.y += v.y; o.z += v.z; o.w += v.w;
    }
    int col = (i & 255) * 4;
    const float* bp = bias + col;
    o.x += bp[0]; o.y += bp[1]; o.z += bp[2]; o.w += bp[3];
    ((float4*)dst)[i] = o;
}

// ==================== kv GEMM body: 128x256 NT, 3-stage, ld 36, ROW-GATHERED ==========
__device__ __forceinline__ void kv_body_m(const float* __restrict__ A, const float* __restrict__ B,
                                          const float* __restrict__ bias, float* __restrict__ C,
                                          int batch, int mt, int bn,
                                          const int* __restrict__ sidx, float* sm) {
    const int N = 2048, K = 1024;
    int tid = threadIdx.x;
    int wid = tid >> 5, lane = tid & 31;
    int warpRow = wid >> 2, warpCol = wid & 3;

    uint32_t s_base = (uint32_t)__cvta_generic_to_shared(sm);
    int ra = tid >> 3, ca = (tid & 7) * 4;
    int* idxs = (int*)(sm + 41472);
    if (tid < 128) idxs[tid] = sidx[batch * 2048 + mt * 128 + tid];
    __syncthreads();

    wmma::fragment<wmma::accumulator, 16, 16, 8, float> acc[4][4];
#pragma unroll
    for (int i = 0; i < 4; ++i)
#pragma unroll
        for (int j = 0; j < 4; ++j) wmma::fill_fragment(acc[i][j], 0.0f);

    const int KT = K >> 5;
    auto issue = [&](int stage, int k0) {
        uint32_t as = s_base + (uint32_t)(stage * 4608) * 4;
        uint32_t bs = s_base + (uint32_t)(13824 + stage * 9216) * 4;
#pragma unroll
        for (int it = 0; it < 4; ++it) {
            int r = ra + it * 32;
            int orig = idxs[r];
            orig = orig < 0 ? 0 : orig;
            cp16(as + (uint32_t)(r * 36 + ca) * 4,
                 A + ((size_t)batch * 2048 + orig) * 1024 + k0 + ca);
        }
#pragma unroll
        for (int it = 0; it < 8; ++it) {
            int r = ra + it * 32;
            cp16(bs + (uint32_t)(r * 36 + ca) * 4, B + (size_t)(bn + r) * K + k0 + ca);
        }
        CP_COMMIT();
    };

    issue(0, 0);
    issue(1, 32);
    for (int kt = 0; kt < KT; ++kt) {
        if (kt + 1 < KT) CP_WAIT(1);
        else CP_WAIT(0);
        __syncthreads();
        if (kt + 2 < KT) issue((kt + 2) % 3, (kt + 2) * 32);
        int stage = kt % 3;
        float* As = sm + stage * 4608;
        float* Bs = sm + 13824 + stage * 9216;
#pragma unroll
        for (int ks = 0; ks < 4; ++ks) {
            int kk = ks * 8;
            wmma::fragment<wmma::matrix_a, 16, 16, 8, wmma::precision::tf32, wmma::row_major> af[4];
            wmma::fragment<wmma::matrix_b, 16, 16, 8, wmma::precision::tf32, wmma::col_major> bf[4];
#pragma unroll
            for (int i = 0; i < 4; ++i)
                wmma::load_matrix_sync(af[i], &As[(warpRow * 64 + i * 16) * 36 + kk], 36);
#pragma unroll
            for (int j = 0; j < 4; ++j)
                wmma::load_matrix_sync(bf[j], &Bs[(warpCol * 64 + j * 16) * 36 + kk], 36);
#pragma unroll
            for (int i = 0; i < 4; ++i)
#pragma unroll
                for (int j = 0; j < 4; ++j) wmma::mma_sync(acc[i][j], af[i], bf[j], acc[i][j]);
        }
    }
    __syncthreads();

    float* st = &sm[wid * 384];
#pragma unroll
    for (int i = 0; i < 4; ++i) {
#pragma unroll
        for (int j = 0; j < 4; ++j) {
            wmma::store_matrix_sync(st, acc[i][j], 24, wmma::mem_row_major);
            __syncwarp();
            int r = lane >> 1, c8 = (lane & 1) * 8;
            int row_local = warpRow * 64 + i * 16 + r;
            int orig = idxs[row_local];
            int col0 = bn + warpCol * 64 + j * 16;
            if (orig >= 0) {
                float4 v0 = *(float4*)&st[r * 24 + c8];
                float4 v1 = *(float4*)&st[r * 24 + c8 + 4];
                const float* bp = bias + col0 + c8;
                v0.x = rtf(v0.x + bp[0]); v0.y = rtf(v0.y + bp[1]);
                v0.z = rtf(v0.z + bp[2]); v0.w = rtf(v0.w + bp[3]);
                v1.x = rtf(v1.x + bp[4]); v1.y = rtf(v1.y + bp[5]);
                v1.z = rtf(v1.z + bp[6]); v1.w = rtf(v1.w + bp[7]);
                float* cp = C + ((size_t)batch * 2048 + orig) * N + col0 + c8;
                *(float4*)cp = v0;
                *(float4*)(cp + 4) = v1;
            }
            __syncwarp();
        }
    }
}

// G1: masked kv GEMM + q projection
__global__ void __launch_bounds__(256, 1)
g1_kernel(const float* ctx_r, const float* Wkv, const float* bkv, float* kvb,
          const float* lat_r, const float* Wq, const float* bq, float* qh,
          const int* sidx, const int* scnt) {
    extern __shared__ float sm[];
    int bx = blockIdx.x;
    if (bx < 1024) {
        int batch = bx >> 7;
        int mt = (bx >> 3) & 15;
        if (mt * 128 >= scnt[batch]) return;
        kv_body_m(ctx_r, Wkv, bkv, kvb, batch, mt, (bx & 7) * 256, sidx, sm);
    } else {
        int idx = bx - 1024;
        small_body<0, 1, 1, 0>(lat_r, Wq, bq, qh, 1024, 1024, 1024,
                               (idx >> 3) * 64, (idx & 7) * 128, sm);
    }
}

// ==================== scores (COMPACTED columns) + chunk stats ========================
__global__ void __launch_bounds__(256)
scores_wmma(const float* __restrict__ qh, const float* __restrict__ kv,
            const int* __restrict__ sidx, const int* __restrict__ scnt,
            float* __restrict__ scores, float* __restrict__ cstat) {
    extern __shared__ float sm[];
    float* Qs = sm;
    float* Ks = sm + 4352;
    int* sx = (int*)(sm + 13056);
    int bh = blockIdx.y;
    int b = bh >> 4, h = bh & 15;
    int s0 = blockIdx.x * 128;
    if (s0 >= scnt[b]) return;
    int tid = threadIdx.x, wid = tid >> 5, lane = tid & 31;

#pragma unroll
    for (int it = 0; it < 4; ++it) {
        int v = tid + it * 256;
        int r = v >> 4, c = (v & 15) * 4;
        *(float4*)&Qs[r * 68 + c] = *(const float4*)(qh + (size_t)(b * 64 + r) * 1024 + h * 64 + c);
    }
#pragma unroll
    for (int it = 0; it < 8; ++it) {
        int v = tid + it * 256;
        int r = v >> 4, c = (v & 15) * 4;
        int orig = sidx[b * 2048 + s0 + r];
        if ((v & 15) == 0) sx[r] = orig;
        int og = orig < 0 ? 0 : orig;
        *(float4*)&Ks[r * 68 + c] =
            *(const float4*)(kv + (size_t)(b * 2048 + og) * 2048 + h * 64 + c);
    }
    __syncthreads();

    int warpRow = wid >> 2, warpCol = wid & 3;
    wmma::fragment<wmma::accumulator, 16, 16, 8, float> acc[2][2];
#pragma unroll
    for (int i = 0; i < 2; ++i)
#pragma unroll
        for (int j = 0; j < 2; ++j) wmma::fill_fragment(acc[i][j], 0.0f);

#pragma unroll
    for (int ks = 0; ks < 8; ++ks) {
        int kk = ks * 8;
        wmma::fragment<wmma::matrix_a, 16, 16, 8, wmma::precision::tf32, wmma::row_major> af[2];
        wmma::fragment<wmma::matrix_b, 16, 16, 8, wmma::precision::tf32, wmma::col_major> bf[2];
#pragma unroll
        for (int i = 0; i < 2; ++i)
            wmma::load_matrix_sync(af[i], &Qs[(warpRow * 32 + i * 16) * 68 + kk], 68);
#pragma unroll
        for (int j = 0; j < 2; ++j)
            wmma::load_matrix_sync(bf[j], &Ks[(warpCol * 32 + j * 16) * 68 + kk], 68);
#pragma unroll
        for (int i = 0; i < 2; ++i)
#pragma unroll
            for (int j = 0; j < 2; ++j) wmma::mma_sync(acc[i][j], af[i], bf[j], acc[i][j]);
    }
    __syncthreads();

    const float NEG = __int_as_float(0xff800000);
    float* st = &sm[wid * 384];
    float* pm = sm + 3072;
    float* ps = sm + 3328;
#pragma unroll
    for (int i = 0; i < 2; ++i) {
        int r = lane >> 1, c8 = (lane & 1) * 8;
        int l = warpRow * 32 + i * 16 + r;
        float4 v0, v1, v2, v3;
        wmma::store_matrix_sync(st, acc[i][0], 24, wmma::mem_row_major);
        __syncwarp();
        v0 = *(float4*)&st[r * 24 + c8];
        v1 = *(float4*)&st[r * 24 + c8 + 4];
        __syncwarp();
        wmma::store_matrix_sync(st, acc[i][1], 24, wmma::mem_row_major);
        __syncwarp();
        v2 = *(float4*)&st[r * 24 + c8];
        v3 = *(float4*)&st[r * 24 + c8 + 4];
        __syncwarp();
        int lc0 = warpCol * 32 + c8;
        int lc1 = lc0 + 16;
        v0.x = sx[lc0 + 0] >= 0 ? v0.x * 0.125f : NEG;
        v0.y = sx[lc0 + 1] >= 0 ? v0.y * 0.125f : NEG;
        v0.z = sx[lc0 + 2] >= 0 ? v0.z * 0.125f : NEG;
        v0.w = sx[lc0 + 3] >= 0 ? v0.w * 0.125f : NEG;
        v1.x = sx[lc0 + 4] >= 0 ? v1.x * 0.125f : NEG;
        v1.y = sx[lc0 + 5] >= 0 ? v1.y * 0.125f : NEG;
        v1.z = sx[lc0 + 6] >= 0 ? v1.z * 0.125f : NEG;
        v1.w = sx[lc0 + 7] >= 0 ? v1.w * 0.125f : NEG;
        v2.x = sx[lc1 + 0] >= 0 ? v2.x * 0.125f : NEG;
        v2.y = sx[lc1 + 1] >= 0 ? v2.y * 0.125f : NEG;
        v2.z = sx[lc1 + 2] >= 0 ? v2.z * 0.125f : NEG;
        v2.w = sx[lc1 + 3] >= 0 ? v2.w * 0.125f : NEG;
        v3.x = sx[lc1 + 4] >= 0 ? v3.x * 0.125f : NEG;
        v3.y = sx[lc1 + 5] >= 0 ? v3.y * 0.125f : NEG;
        v3.z = sx[lc1 + 6] >= 0 ? v3.z * 0.125f : NEG;
        v3.w = sx[lc1 + 7] >= 0 ? v3.w * 0.125f : NEG;
        float* pp = scores + ((size_t)bh * 64 + l) * 2048 + s0 + lc0;
        *(float4*)pp = v0;
        *(float4*)(pp + 4) = v1;
        *(float4*)(pp + 16) = v2;
        *(float4*)(pp + 20) = v3;
        float mx = fmaxf(fmaxf(fmaxf(v0.x, v0.y), fmaxf(v0.z, v0.w)),
                         fmaxf(fmaxf(v1.x, v1.y), fmaxf(v1.z, v1.w)));
        mx = fmaxf(mx, fmaxf(fmaxf(fmaxf(v2.x, v2.y), fmaxf(v2.z, v2.w)),
                             fmaxf(fmaxf(v3.x, v3.y), fmaxf(v3.z, v3.w))));
        float m2 = fmaxf(mx, __shfl_xor_sync(0xffffffffu, mx, 1));
        float m2c = fmaxf(m2, -1e30f);
        float s = expf(v0.x - m2c) + expf(v0.y - m2c) + expf(v0.z - m2c) + expf(v0.w - m2c) +
                  expf(v1.x - m2c) + expf(v1.y - m2c) + expf(v1.z - m2c) + expf(v1.w - m2c) +
                  expf(v2.x - m2c) + expf(v2.y - m2c) + expf(v2.z - m2c) + expf(v2.w - m2c) +
                  expf(v3.x - m2c) + expf(v3.y - m2c) + expf(v3.z - m2c) + expf(v3.w - m2c);
        s += __shfl_xor_sync(0xffffffffu, s, 1);
        if ((lane & 1) == 0) {
            pm[l * 4 + warpCol] = m2;
            ps[l * 4 + warpCol] = s;
        }
    }
    __syncthreads();
    if (tid < 64) {
        float m0 = pm[tid * 4], m1 = pm[tid * 4 + 1], m2 = pm[tid * 4 + 2], m3 = pm[tid * 4 + 3];
        float m = fmaxf(fmaxf(m0, m1), fmaxf(m2, m3));
        float mc = fmaxf(m, -1e30f);
        float S = ps[tid * 4] * expf(m0 - mc) + ps[tid * 4 + 1] * expf(m1 - mc) +
                  ps[tid * 4 + 2] * expf(m2 - mc) + ps[tid * 4 + 3] * expf(m3 - mc);
        float2 o;
        o.x = m;
        o.y = S;
        *(float2*)&cstat[(((size_t)bh * 64 + tid) * 16 + blockIdx.x) * 2] = o;
    }
}

// ---------------- rowstat: fold ACTIVE chunk stats -> (max, 1/sum) per row ------------
__global__ void rowstat_kernel(const float* __restrict__ cstat, const int* __restrict__ scnt,
                               float* __restrict__ rowstat) {
    int row = blockIdx.x * 256 + threadIdx.x;
    int b = row >> 10;
    int nch = scnt[b] >> 7;
    const float2* c = (const float2*)cstat + row * 16;
    float M = __int_as_float(0xff800000);
    for (int k = 0; k < nch; ++k) M = fmaxf(M, c[k].x);
    float Mc = fmaxf(M, -1e30f);
    float S = 0.f;
    for (int k = 0; k < nch; ++k) S += c[k].y * expf(c[k].x - Mc);
    float2 o;
    o.x = Mc;
    o.y = 1.0f / S;
    ((float2*)rowstat)[row] = o;
}

// ==================== attn split-K (COMPACTED): inline softmax, V gathered ============
__device__ __forceinline__ void attn_body(const float* __restrict__ scores,
                                          const float* __restrict__ kv,
                                          const float* __restrict__ rowstat,
                                          const int* __restrict__ sidx,
                                          float* __restrict__ part,
                                          int bh, int split, int cnt, float* sm) {
    int b = bh >> 4, h = bh & 15;
    int base_s = split * 512;
    int ktmax = cnt - base_s;
    ktmax = (ktmax > 512 ? 512 : ktmax) >> 6;
    int tid = threadIdx.x, wid = tid >> 5, lane = tid & 31;
    int warpRow = wid >> 1, warpCol = wid & 1;

    uint32_t s_base = (uint32_t)__cvta_generic_to_shared(sm);
    int ra = tid >> 4, ca = (tid & 15) * 4;
    float* rs_m = sm + 26112;
    float* rs_i = sm + 26176;
    if (tid < 64) {
        float2 v = ((const float2*)rowstat)[bh * 64 + tid];
        rs_m[tid] = v.x;
        rs_i[tid] = v.y;
    }

    wmma::fragment<wmma::accumulator, 16, 16, 8, float> acc[2];
    wmma::fill_fragment(acc[0], 0.0f);
    wmma::fill_fragment(acc[1], 0.0f);

    auto issue = [&](int stage, int s0) {
        uint32_t ps = s_base + (uint32_t)(stage * 4352) * 4;
        uint32_t vs = s_base + (uint32_t)(13056 + stage * 4352) * 4;
#pragma unroll
        for (int it = 0; it < 4; ++it) {
            int r = ra + it * 16;
            cp16(ps + (uint32_t)(r * 68 + ca) * 4,
                 scores + ((size_t)bh * 64 + r) * 2048 + s0 + ca);
            int orig = sidx[b * 2048 + s0 + r];
            orig = orig < 0 ? 0 : orig;
            cp16(vs + (uint32_t)(r * 68 + ca) * 4,
                 kv + (size_t)(b * 2048 + orig) * 2048 + 1024 + h * 64 + ca);
        }
        CP_COMMIT();
    };

    issue(0, base_s);
    if (ktmax > 1) issue(1, base_s + 64);
    for (int kt = 0; kt < ktmax; ++kt) {
        if (kt + 1 < ktmax) CP_WAIT(1);
        else CP_WAIT(0);
        __syncthreads();
        int stage = kt % 3;
        float* Ps = sm + stage * 4352;
#pragma unroll
        for (int it = 0; it < 4; ++it) {
            int rr = ra + it * 16;
            float M = rs_m[rr], I = rs_i[rr];
            float4 v = *(float4*)&Ps[rr * 68 + ca];
            v.x = rtf(expf(v.x - M) * I);
            v.y = rtf(expf(v.y - M) * I);
            v.z = rtf(expf(v.z - M) * I);
            v.w = rtf(expf(v.w - M) * I);
            *(float4*)&Ps[rr * 68 + ca] = v;
        }
        __syncthreads();
        if (kt + 2 < ktmax) issue((kt + 2) % 3, base_s + (kt + 2) * 64);
        float* Vs = sm + 13056 + stage * 4352;
#pragma unroll
        for (int ks = 0; ks < 8; ++ks) {
            int kk = ks * 8;
            wmma::fragment<wmma::matrix_a, 16, 16, 8, wmma::precision::tf32, wmma::row_major> af;
            wmma::fragment<wmma::matrix_b, 16, 16, 8, wmma::precision::tf32, wmma::row_major> bf[2];
            wmma::load_matrix_sync(af, &Ps[(warpRow * 16) * 68 + kk], 68);
#pragma unroll
            for (int j = 0; j < 2; ++j)
                wmma::load_matrix_sync(bf[j], &Vs[kk * 68 + warpCol * 32 + j * 16], 68);
            wmma::mma_sync(acc[0], af, bf[0], acc[0]);
            wmma::mma_sync(acc[1], af, bf[1], acc[1]);
        }
    }
    __syncthreads();

    float* pout = part + (size_t)split * 524288;
    float* st = &sm[wid * 384];
#pragma unroll
    for (int j = 0; j < 2; ++j) {
        wmma::store_matrix_sync(st, acc[j], 24, wmma::mem_row_major);
        __syncwarp();
        int r = lane >> 1, c8 = (lane & 1) * 8;
        int l = warpRow * 16 + r;
        int d0 = warpCol * 32 + j * 16 + c8;
        float4 v0 = *(float4*)&st[r * 24 + c8];
        float4 v1 = *(float4*)&st[r * 24 + c8 + 4];
        float* ap = pout + (size_t)(b * 64 + l) * 1024 + h * 64 + d0;
        *(float4*)ap = v0;
        *(float4*)(ap + 4) = v1;
        __syncwarp();
    }
}

// A1: attn_part (blocks 0..511) + mean_heads scatter (blocks 512..1535)
__global__ void __launch_bounds__(256, 2)
a1_kernel(const float* __restrict__ scores, const float* __restrict__ kv,
          const float* __restrict__ rowstat, const int* __restrict__ sidx,
          const int* __restrict__ scnt, float* __restrict__ part,
          float* __restrict__ aw) {
    extern __shared__ float sm[];
    int bx = blockIdx.x;
    if (bx < 512) {
        int bh = bx >> 2, split = bx & 3;
        int cnt = scnt[bh >> 4];
        if (split * 512 >= cnt) return;
        attn_body(scores, kv, rowstat, sidx, part, bh, split, cnt, sm);
    } else {
        int i = (bx - 512) * 256 + threadIdx.x;
        int s4 = i & 511;
        int l = (i >> 9) & 63;
        int b = i >> 15;
        if (s4 * 4 >= scnt[b]) return;
        int4 orig = *(const int4*)&sidx[b * 2048 + s4 * 4];
        float4 acc = {0.f, 0.f, 0.f, 0.f};
#pragma unroll
        for (int h = 0; h < 16; ++h) {
            size_t row = (size_t)(b * 16 + h) * 64 + l;
            float2 stt = ((const float2*)rowstat)[row];
            float4 x = *(const float4*)(scores + row * 2048 + s4 * 4);
            acc.x += expf(x.x - stt.x) * stt.y;
            acc.y += expf(x.y - stt.x) * stt.y;
            acc.z += expf(x.z - stt.x) * stt.y;
            acc.w += expf(x.w - stt.x) * stt.y;
        }
        const float inv = 1.0f / 16.0f;
        float* arow = aw + (size_t)(b * 64 + l) * 2048;
        if (orig.x >= 0) arow[orig.x] = acc.x * inv;
        if (orig.y >= 0) arow[orig.y] = acc.y * inv;
        if (orig.z >= 0) arow[orig.z] = acc.z * inv;
        if (orig.w >= 0) arow[orig.w] = acc.w * inv;
    }
}

// reduce ACTIVE partials -> attn (tf32-rounded)
__global__ void attn_reduce_kernel(const float* __restrict__ part, const int* __restrict__ scnt,
                                   float* __restrict__ attn) {
    int i = blockIdx.x * 256 + threadIdx.x;
    int b = i >> 14;
    int ns = (scnt[b] + 511) >> 9;
    float4 o = ((const float4*)part)[i];
    if (ns > 1) {
        float4 v = ((const float4*)(part + 524288))[i];
        o.x += v.x; o.y += v.y; o.z += v.z; o.w += v.w;
    }
    if (ns > 2) {
        float4 v = ((const float4*)(part + 1048576))[i];
        o.x += v.x; o.y += v.y; o.z += v.z; o.w += v.w;
    }
    if (ns > 3) {
        float4 v = ((const float4*)(part + 1572864))[i];
        o.x += v.x; o.y += v.y; o.z += v.z; o.w += v.w;
    }
    o.x = rtf(o.x); o.y = rtf(o.y); o.z = rtf(o.z); o.w = rtf(o.w);
    ((float4*)attn)[i] = o;
}

// ---------------- residual add + LayerNorm (optional rounded copy) ----------------
template <int WR>
__global__ void add_ln_kernel(const float* __restrict__ a, const float* __restrict__ b2,
                              const float* __restrict__ g, const float* __restrict__ bet,
                              float* __restrict__ out, float* __restrict__ out_r) {
    int row = blockIdx.x, tid = threadIdx.x;
    const float4* a4 = (const float4*)(a + (size_t)row * 1024);
    const float4* b4 = (const float4*)(b2 + (size_t)row * 1024);
    float4 va = a4[tid], vb = b4[tid];
    float4 x;
    x.x = va.x + vb.x; x.y = va.y + vb.y; x.z = va.z + vb.z; x.w = va.w + vb.w;
    float s = (x.x + x.y) + (x.z + x.w);
    float sq = x.x * x.x + x.y * x.y + x.z * x.z + x.w * x.w;
    __shared__ float r1[256], r2[256];
    r1[tid] = s; r2[tid] = sq;
    __syncthreads();
    for (int st = 128; st > 0; st >>= 1) {
        if (tid < st) { r1[tid] += r1[tid + st]; r2[tid] += r2[tid + st]; }
        __syncthreads();
    }
    float mean = r1[0] * (1.0f / 1024.0f);
    float var = r2[0] * (1.0f / 1024.0f) - mean * mean;
    float rstd = rsqrtf(var + 1e-5f);
    float4 gg = ((const float4*)g)[tid], bb = ((const float4*)bet)[tid];
    float4 o;
    o.x = (x.x - mean) * rstd * gg.x + bb.x;
    o.y = (x.y - mean) * rstd * gg.y + bb.y;
    o.z = (x.z - mean) * rstd * gg.z + bb.z;
    o.w = (x.w - mean) * rstd * gg.w + bb.w;
    ((float4*)(out + (size_t)row * 1024))[tid] = o;
    if (WR) {
        float4 q;
        q.x = rtf(o.x); q.y = rtf(o.y); q.z = rtf(o.z); q.w = rtf(o.w);
        ((float4*)(out_r + (size_t)row * 1024))[tid] = q;
    }
}

// ---------------- launch ----------------
extern "C" void kernel_launch(void* const* d_in, const int* in_sizes, int n_in,
                              void* d_out, int out_size) {
    (void)in_sizes; (void)n_in; (void)out_size;
    const float* latents = (const float*)d_in[0];
    const float* context = (const float*)d_in[1];
    const int* cmask = (const int*)d_in[2];
    const float* q_w = (const float*)d_in[3];
    const float* q_b = (const float*)d_in[4];
    const float* k_w = (const float*)d_in[5];
    const float* k_b = (const float*)d_in[6];
    const float* v_w = (const float*)d_in[7];
    const float* v_b = (const float*)d_in[8];
    const float* in_wq = (const float*)d_in[9];
    const float* in_bq = (const float*)d_in[10];
    const float* in_wk = (const float*)d_in[11];
    const float* in_bk = (const float*)d_in[12];
    const float* in_wv = (const float*)d_in[13];
    const float* in_bv = (const float*)d_in[14];
    const float* out_w = (const float*)d_in[15];
    const float* out_b = (const float*)d_in[16];
    const float* ln1_g = (const float*)d_in[17];
    const float* ln1_b = (const float*)d_in[18];
    const float* ln2_g = (const float*)d_in[19];
    const float* ln2_b = (const float*)d_in[20];
    const float* ff_w1 = (const float*)d_in[21];
    const float* ff_b1 = (const float*)d_in[22];
    const float* ff_w2 = (const float*)d_in[23];
    const float* ff_b2 = (const float*)d_in[24];

    float* out = (float*)d_out;
    float* aw_out = out + 512 * 1024;

    void* p;
    cudaGetSymbolAddress(&p, g_ctx_r);   float* ctx_r = (float*)p;
    cudaGetSymbolAddress(&p, g_lat_r);   float* lat_r = (float*)p;
    cudaGetSymbolAddress(&p, g_Wq);      float* Wq = (float*)p;
    cudaGetSymbolAddress(&p, g_Wkv);     float* Wkv = (float*)p;
    cudaGetSymbolAddress(&p, g_bq);      float* bq = (float*)p;
    cudaGetSymbolAddress(&p, g_bkv);     float* bkv = (float*)p;
    cudaGetSymbolAddress(&p, g_qh);      float* qh = (float*)p;
    cudaGetSymbolAddress(&p, g_kv);      float* kvb = (float*)p;
    cudaGetSymbolAddress(&p, g_scores);  float* scores = (float*)p;
    cudaGetSymbolAddress(&p, g_cstat);   float* cstat = (float*)p;
    cudaGetSymbolAddress(&p, g_rowstat); float* rowstat = (float*)p;
    cudaGetSymbolAddress(&p, g_part);    float* part = (float*)p;
    cudaGetSymbolAddress(&p, g_attn);    float* attn = (float*)p;
    cudaGetSymbolAddress(&p, g_x);       float* xb = (float*)p;
    cudaGetSymbolAddress(&p, g_xr);      float* xr = (float*)p;
    cudaGetSymbolAddress(&p, g_h1);      float* h1 = (float*)p;
    cudaGetSymbolAddress(&p, g_sidx);    int* sidx = (int*)p;
    cudaGetSymbolAddress(&p, g_scnt);    int* scnt = (int*)p;

    cudaFuncSetAttribute(mega_prologue, cudaFuncAttributeMaxDynamicSharedMemorySize, 77824);
    cudaFuncSetAttribute(wmma_gemm_small<1, 1, 1, 1>, cudaFuncAttributeMaxDynamicSharedMemorySize, 82944);
    cudaFuncSetAttribute(wmma_gemm_splitk<1>, cudaFuncAttributeMaxDynamicSharedMemorySize, 82944);
    cudaFuncSetAttribute(g1_kernel, cudaFuncAttributeMaxDynamicSharedMemorySize, 166400);
    cudaFuncSetAttribute(scores_wmma, cudaFuncAttributeMaxDynamicSharedMemorySize, 52736);
    cudaFuncSetAttribute(a1_kernel, cudaFuncAttributeMaxDynamicSharedMemorySize, 104960);

    // ---- mega prologue: fuse GEMMs + rounding + biases + compaction + aw zero ----
    mega_prologue<<<21192, 256, 77824>>>(
        in_wq, q_w, Wq,
        in_wk, k_w, Wkv,
        in_wv, v_w, Wkv + 1024 * 1024,
        (const float4*)context, (float4*)ctx_r,
        (const float4*)latents, (float4*)lat_r,
        q_b, in_bq, k_b, in_bk, v_b, in_bv,
        bq, bkv, cmask, sidx, scnt, (float4*)aw_out);

    // ---- G1: masked-compacted kv projection + q projection (merged) ----
    g1_kernel<<<1088, 256, 166400>>>(ctx_r, Wkv, bkv, kvb, lat_r, Wq, bq, qh, sidx, scnt);

    // ---- attention on compacted columns ----
    scores_wmma<<<dim3(16, 128), 256, 52736>>>(qh, kvb, sidx, scnt, scores, cstat);
    rowstat_kernel<<<32, 256>>>(cstat, scnt, rowstat);
    a1_kernel<<<1536, 256, 104960>>>(scores, kvb, rowstat, sidx, scnt, part, aw_out);
    attn_reduce_kernel<<<512, 256>>>(part, scnt, attn);

    // ---- out projection: split-K=2 (K=512 each), reduce adds bias -> qh ----
    wmma_gemm_splitk<1><<<dim3(8, 8, 2), 256, 82944>>>(attn, out_w, part, 1024, 512);
    splitk_reduce_kernel<2><<<512, 256>>>(part, out_b, qh);

    // ---- LN1 (exact + rounded copy) ----
    add_ln_kernel<1><<<512, 256>>>(latents, qh, ln1_g, ln1_b, xb, xr);

    // ---- FFN: ff1 full; ff2 split-K=4 (K=1024 each), reduce adds bias -> attn ----
    wmma_gemm_small<1, 1, 1, 1><<<dim3(32, 8), 256, 82944>>>(xr, ff_w1, ff_b1, h1, 4096, 1024, 1024);
    wmma_gemm_splitk<1><<<dim3(8, 8, 4), 256, 82944>>>(h1, ff_w2, part, 4096, 1024);
    splitk_reduce_kernel<4><<<512, 256>>>(part, ff_b2, attn);

    // ---- LN2 -> out ----
    add_ln_kernel<0><<<512, 256>>>(xb, attn, ln2_g, ln2_b, out, nullptr);
}

// round 15
// speedup vs baseline: 1.4888x; 1.0335x over previous
#include <cuda_runtime.h>
#include <mma.h>
#include <math.h>
#include <stdint.h>

using namespace nvcuda;

// Shapes: B=8, L=64, S=2048, D=1024, C=1024, H=16, HD=64

// ---------------- device scratch ----------------
__device__ float g_ctx_r[16384 * 1024];
__device__ float g_lat_r[512 * 1024];
__device__ float g_Wq[1024 * 1024];
__device__ float g_Wkv[2048 * 1024];
__device__ float g_bq[1024];
__device__ float g_bkv[2048];
__device__ float g_qh[512 * 1024];
__device__ float g_kv[16384 * 2048];        // masked rows stay 0 (never observed)
__device__ float g_scores[8192 * 2048];     // COMPACTED columns per batch
__device__ float g_cstat[8192 * 32];
__device__ float g_rowstat[8192 * 2];
__device__ float g_part[4 * 512 * 1024];    // attn split-K partials; later GEMM split-K
__device__ float g_attn[512 * 1024];
__device__ float g_x[512 * 1024];
__device__ float g_xr[512 * 1024];
__device__ float g_h1[512 * 4096];
__device__ int g_sidx[8 * 2048];
__device__ int g_scnt[8];

__device__ __forceinline__ float gelu_exact(float x) {
    return 0.5f * x * (1.0f + erff(x * 0.70710678118654752f));
}
__device__ __forceinline__ float rtf(float x) {
    float y;
    asm("cvt.rna.tf32.f32 %0, %1;" : "=f"(y) : "f"(x));
    return y;
}
__device__ __forceinline__ void cp16(uint32_t dst, const void* src) {
    asm volatile("cp.async.cg.shared.global [%0], [%1], 16;\n" ::"r"(dst), "l"(src));
}
#define CP_COMMIT() asm volatile("cp.async.commit_group;\n" ::)
#define CP_WAIT(n) asm volatile("cp.async.wait_group %0;\n" ::"n"(n))

// ==================== weight-fusion GEMM body 128x128 NN (in-fragment cvt) ===========
__device__ __forceinline__ void fuse_body(const float* __restrict__ A, const float* __restrict__ B,
                                          float* __restrict__ C, int bm, int bn, float* sm) {
    const int N = 1024, K = 1024;
    int tid = threadIdx.x;
    int wid = tid >> 5, lane = tid & 31;
    int warpRow = wid >> 2, warpCol = wid & 3;

    uint32_t s_base = (uint32_t)__cvta_generic_to_shared(sm);
    int ra = tid >> 3, ca = (tid & 7) * 4;
    int kb = tid >> 5, cb = (tid & 31) * 4;

    wmma::fragment<wmma::accumulator, 16, 16, 8, float> acc[4][2];
#pragma unroll
    for (int i = 0; i < 4; ++i)
#pragma unroll
        for (int j = 0; j < 2; ++j) wmma::fill_fragment(acc[i][j], 0.0f);

    const int KT = K >> 5;
    auto issue = [&](int stage, int k0) {
        uint32_t as = s_base + (uint32_t)(stage * 4608) * 4;
        uint32_t bs = s_base + (uint32_t)(9216 + stage * 5120) * 4;
#pragma unroll
        for (int it = 0; it < 4; ++it) {
            int r = ra + it * 32;
            cp16(as + (uint32_t)(r * 36 + ca) * 4, A + (size_t)(bm + r) * K + k0 + ca);
        }
#pragma unroll
        for (int it = 0; it < 4; ++it) {
            int kk = kb + it * 8;
            cp16(bs + (uint32_t)(kk * 136 + cb) * 4, B + (size_t)(k0 + kk) * N + bn + cb);
        }
        CP_COMMIT();
    };

    issue(0, 0);
    for (int kt = 0; kt < KT; ++kt) {
        int stage = kt & 1;
        if (kt + 1 < KT) {
            issue(stage ^ 1, (kt + 1) * 32);
            CP_WAIT(1);
        } else {
            CP_WAIT(0);
        }
        __syncthreads();
        float* As = sm + stage * 4608;
        float* Bs = sm + 9216 + stage * 5120;
#pragma unroll
        for (int ks = 0; ks < 4; ++ks) {
            int kk = ks * 8;
            wmma::fragment<wmma::matrix_a, 16, 16, 8, wmma::precision::tf32, wmma::row_major> af[4];
#pragma unroll
            for (int i = 0; i < 4; ++i) {
                wmma::load_matrix_sync(af[i], &As[(warpRow * 64 + i * 16) * 36 + kk], 36);
#pragma unroll
                for (int t = 0; t < af[i].num_elements; ++t)
                    af[i].x[t] = wmma::__float_to_tf32(af[i].x[t]);
            }
            wmma::fragment<wmma::matrix_b, 16, 16, 8, wmma::precision::tf32, wmma::row_major> bf[2];
#pragma unroll
            for (int j = 0; j < 2; ++j) {
                wmma::load_matrix_sync(bf[j], &Bs[kk * 136 + warpCol * 32 + j * 16], 136);
#pragma unroll
                for (int t = 0; t < bf[j].num_elements; ++t)
                    bf[j].x[t] = wmma::__float_to_tf32(bf[j].x[t]);
            }
#pragma unroll
            for (int i = 0; i < 4; ++i)
#pragma unroll
                for (int j = 0; j < 2; ++j) wmma::mma_sync(acc[i][j], af[i], bf[j], acc[i][j]);
        }
        __syncthreads();
    }

    float* st = &sm[wid * 384];
#pragma unroll
    for (int i = 0; i < 4; ++i) {
#pragma unroll
        for (int j = 0; j < 2; ++j) {
            wmma::store_matrix_sync(st, acc[i][j], 24, wmma::mem_row_major);
            __syncwarp();
            int row0 = bm + warpRow * 64 + i * 16;
            int col0 = bn + warpCol * 32 + j * 16;
            int r = lane >> 1, c8 = (lane & 1) * 8;
            float4 v0 = *(float4*)&st[r * 24 + c8];
            float4 v1 = *(float4*)&st[r * 24 + c8 + 4];
            v0.x = rtf(v0.x); v0.y = rtf(v0.y); v0.z = rtf(v0.z); v0.w = rtf(v0.w);
            v1.x = rtf(v1.x); v1.y = rtf(v1.y); v1.z = rtf(v1.z); v1.w = rtf(v1.w);
            float* cp = C + (size_t)(row0 + r) * N + col0 + c8;
            *(float4*)cp = v0;
            *(float4*)(cp + 4) = v1;
            __syncwarp();
        }
    }
}

// ==================== MEGA PROLOGUE ====================
// [0,192): weight-fusion GEMMs; [192,2304): grid-strided rounding (8 f4/thread);
// [2304,5376): fuse_bias; [5376,5384): compaction; [5384,6408): aw zero
__global__ void __launch_bounds__(256)
mega_prologue(
    const float* in_wq, const float* q_w, float* Wq,
    const float* in_wk, const float* k_w, float* Wkv0,
    const float* in_wv, const float* v_w, float* Wkv1,
    const float4* context, float4* ctx_r,
    const float4* latents4, float4* lat_r,
    const float* q_b, const float* in_bq,
    const float* k_b, const float* in_bk,
    const float* v_b, const float* in_bv,
    float* bq, float* bkv, const int* cmask, int* sidx, int* scnt,
    float4* aw4) {
    extern __shared__ float sm[];
    __shared__ float red[256];
    __shared__ int sc[256];
    int bx = blockIdx.x, tid = threadIdx.x;
    if (bx < 192) {
        int z = bx >> 6, t = bx & 63;
        int bm = (t >> 3) * 128, bn = (t & 7) * 128;
        if (z == 0) fuse_body(in_wq, q_w, Wq, bm, bn, sm);
        else if (z == 1) fuse_body(in_wk, k_w, Wkv0, bm, bn, sm);
        else fuse_body(in_wv, v_w, Wkv1, bm, bn, sm);
    } else if (bx < 2304) {
        // 2112 blocks x 2048 f4 each; 8 independent f4 per thread for MLP
        int base = (bx - 192) * 2048;
#pragma unroll
        for (int j = 0; j < 8; ++j) {
            int i = base + j * 256 + tid;
            const float4* s;
            float4* d;
            int off;
            if (i < 4194304) { s = context; d = ctx_r; off = i; }
            else { off = i - 4194304; s = latents4; d = lat_r; }
            float4 v = s[off];
            v.x = rtf(v.x); v.y = rtf(v.y); v.z = rtf(v.z); v.w = rtf(v.w);
            d[off] = v;
        }
    } else if (bx < 5376) {
        int idx = bx - 2304;
        int z = idx >> 10, o = idx & 1023;
        const float* W = (z == 0) ? in_wq : (z == 1) ? in_wk : in_wv;
        const float* bin = (z == 0) ? q_b : (z == 1) ? k_b : v_b;
        const float* badd = (z == 0) ? in_bq : (z == 1) ? in_bk : in_bv;
        float* bout = (z == 0) ? bq : (z == 1) ? bkv : (bkv + 1024);
        float s = 0.f;
        for (int i = tid; i < 1024; i += 256) s += W[o * 1024 + i] * bin[i];
        red[tid] = s;
        __syncthreads();
        for (int st = 128; st > 0; st >>= 1) {
            if (tid < st) red[tid] += red[tid + st];
            __syncthreads();
        }
        if (tid == 0) bout[o] = red[0] + badd[o];
    } else if (bx < 5384) {
        int bb = bx - 5376;
        const int* m = cmask + bb * 2048;
        int base_s = tid * 8;
        int mv[8];
        int cnt = 0;
#pragma unroll
        for (int j = 0; j < 8; ++j) {
            mv[j] = m[base_s + j];
            cnt += (mv[j] != 0);
        }
        sc[tid] = cnt;
        __syncthreads();
        for (int off = 1; off < 256; off <<= 1) {
            int v = (tid >= off) ? sc[tid - off] : 0;
            __syncthreads();
            sc[tid] += v;
            __syncthreads();
        }
        int pos = sc[tid] - cnt;
        int total = sc[255];
#pragma unroll
        for (int j = 0; j < 8; ++j)
            if (mv[j]) sidx[bb * 2048 + pos++] = base_s + j;
        int padded = (total + 127) & ~127;
        for (int i = total + tid; i < padded; i += 256) sidx[bb * 2048 + i] = -1;
        if (tid == 0) scnt[bb] = padded;
    } else {
        int i = (bx - 5384) * 256 + tid;
        float4 z = {0.f, 0.f, 0.f, 0.f};
        aw4[i] = z;
    }
}

// ==================== small GEMM body: 64x128 NT, 3-stage, ld 36, generic K ==========
template <int EPI, int BIAS, int RND, int CVTB>
__device__ __forceinline__ void small_body(const float* __restrict__ A, const float* __restrict__ B,
                                           const float* __restrict__ bias, float* __restrict__ C,
                                           int N, int lda, int ksz, int bm, int bn, float* sm) {
    int tid = threadIdx.x;
    int wid = tid >> 5, lane = tid & 31;
    int warpRow = wid >> 2, warpCol = wid & 3;

    uint32_t s_base = (uint32_t)__cvta_generic_to_shared(sm);
    int ra = tid >> 3, ca = (tid & 7) * 4;

    wmma::fragment<wmma::accumulator, 16, 16, 8, float> acc[2][2];
#pragma unroll
    for (int i = 0; i < 2; ++i)
#pragma unroll
        for (int j = 0; j < 2; ++j) wmma::fill_fragment(acc[i][j], 0.0f);

    const int KT = ksz >> 5;
    auto issue = [&](int stage, int k0) {
        uint32_t as = s_base + (uint32_t)(stage * 2304) * 4;
        uint32_t bs = s_base + (uint32_t)(6912 + stage * 4608) * 4;
#pragma unroll
        for (int it = 0; it < 2; ++it) {
            int r = ra + it * 32;
            cp16(as + (uint32_t)(r * 36 + ca) * 4, A + (size_t)(bm + r) * lda + k0 + ca);
        }
#pragma unroll
        for (int it = 0; it < 4; ++it) {
            int r = ra + it * 32;
            cp16(bs + (uint32_t)(r * 36 + ca) * 4, B + (size_t)(bn + r) * lda + k0 + ca);
        }
        CP_COMMIT();
    };

    issue(0, 0);
    if (KT > 1) issue(1, 32);
    for (int kt = 0; kt < KT; ++kt) {
        if (kt + 1 < KT) CP_WAIT(1);
        else CP_WAIT(0);
        __syncthreads();
        if (kt + 2 < KT) issue((kt + 2) % 3, (kt + 2) * 32);
        int stage = kt % 3;
        float* As = sm + stage * 2304;
        float* Bs = sm + 6912 + stage * 4608;
#pragma unroll
        for (int ks = 0; ks < 4; ++ks) {
            int kk = ks * 8;
            wmma::fragment<wmma::matrix_a, 16, 16, 8, wmma::precision::tf32, wmma::row_major> af[2];
            wmma::fragment<wmma::matrix_b, 16, 16, 8, wmma::precision::tf32, wmma::col_major> bf[2];
#pragma unroll
            for (int i = 0; i < 2; ++i)
                wmma::load_matrix_sync(af[i], &As[(warpRow * 32 + i * 16) * 36 + kk], 36);
#pragma unroll
            for (int j = 0; j < 2; ++j) {
                wmma::load_matrix_sync(bf[j], &Bs[(warpCol * 32 + j * 16) * 36 + kk], 36);
                if (CVTB) {
#pragma unroll
                    for (int t = 0; t < bf[j].num_elements; ++t)
                        bf[j].x[t] = wmma::__float_to_tf32(bf[j].x[t]);
                }
            }
#pragma unroll
            for (int i = 0; i < 2; ++i)
#pragma unroll
                for (int j = 0; j < 2; ++j) wmma::mma_sync(acc[i][j], af[i], bf[j], acc[i][j]);
        }
    }
    __syncthreads();

    float* st = &sm[wid * 384];
#pragma unroll
    for (int i = 0; i < 2; ++i) {
#pragma unroll
        for (int j = 0; j < 2; ++j) {
            wmma::store_matrix_sync(st, acc[i][j], 24, wmma::mem_row_major);
            __syncwarp();
            int row0 = bm + warpRow * 32 + i * 16;
            int col0 = bn + warpCol * 32 + j * 16;
            int r = lane >> 1, c8 = (lane & 1) * 8;
            float4 v0 = *(float4*)&st[r * 24 + c8];
            float4 v1 = *(float4*)&st[r * 24 + c8 + 4];
            if (BIAS) {
                const float* bp = bias + col0 + c8;
                v0.x += bp[0]; v0.y += bp[1]; v0.z += bp[2]; v0.w += bp[3];
                v1.x += bp[4]; v1.y += bp[5]; v1.z += bp[6]; v1.w += bp[7];
            }
            if (EPI) {
                v0.x = gelu_exact(v0.x); v0.y = gelu_exact(v0.y);
                v0.z = gelu_exact(v0.z); v0.w = gelu_exact(v0.w);
                v1.x = gelu_exact(v1.x); v1.y = gelu_exact(v1.y);
                v1.z = gelu_exact(v1.z); v1.w = gelu_exact(v1.w);
            }
            if (RND) {
                v0.x = rtf(v0.x); v0.y = rtf(v0.y); v0.z = rtf(v0.z); v0.w = rtf(v0.w);
                v1.x = rtf(v1.x); v1.y = rtf(v1.y); v1.z = rtf(v1.z); v1.w = rtf(v1.w);
            }
            float* cp = C + (size_t)(row0 + r) * N + col0 + c8;
            *(float4*)cp = v0;
            *(float4*)(cp + 4) = v1;
            __syncwarp();
        }
    }
}

template <int EPI, int BIAS, int RND, int CVTB>
__global__ void __launch_bounds__(256, 2)
wmma_gemm_small(const float* __restrict__ A, const float* __restrict__ B,
                const float* __restrict__ bias, float* __restrict__ C,
                int N, int lda, int ksz) {
    extern __shared__ float sm[];
    small_body<EPI, BIAS, RND, CVTB>(A, B, bias, C, N, lda, ksz,
                                     blockIdx.y * 64, blockIdx.x * 128, sm);
}

// split-K partial GEMM
template <int CVTB>
__global__ void __launch_bounds__(256, 2)
wmma_gemm_splitk(const float* __restrict__ A, const float* __restrict__ B,
                 float* __restrict__ part, int lda, int ksz) {
    extern __shared__ float sm[];
    int z = blockIdx.z;
    small_body<0, 0, 0, CVTB>(A + (size_t)z * ksz, B + (size_t)z * ksz, nullptr,
                              part + (size_t)z * 524288, 1024, lda, ksz,
                              blockIdx.y * 64, blockIdx.x * 128, sm);
}

// fused: reduce NS split-K partials + bias -> residual add + LayerNorm
template <int NS, int WR>
__global__ void reduce_ln_kernel(const float* __restrict__ part, const float* __restrict__ bias,
                                 const float* __restrict__ res, const float* __restrict__ g,
                                 const float* __restrict__ bet, float* __restrict__ out,
                                 float* __restrict__ out_r) {
    int row = blockIdx.x, tid = threadIdx.x;
    int i = row * 256 + tid;   // f4 unit
    float4 o = ((const float4*)part)[i];
#pragma unroll
    for (int s = 1; s < NS; ++s) {
        float4 v = ((const float4*)(part + (size_t)s * 524288))[i];
        o.x += v.x; o.y += v.y; o.z += v.z; o.w += v.w;
    }
    const float* bp = bias + tid * 4;
    o.x += bp[0]; o.y += bp[1]; o.z += bp[2]; o.w += bp[3];
    float4 vr = ((const float4*)(res + (size_t)row * 1024))[tid];
    float4 x;
    x.x = vr.x + o.x; x.y = vr.y + o.y; x.z = vr.z + o.z; x.w = vr.w + o.w;
    float s = (x.x + x.y) + (x.z + x.w);
    float sq = x.x * x.x + x.y * x.y + x.z * x.z + x.w * x.w;
    __shared__ float r1[256], r2[256];
    r1[tid] = s; r2[tid] = sq;
    __syncthreads();
    for (int st = 128; st > 0; st >>= 1) {
        if (tid < st) { r1[tid] += r1[tid + st]; r2[tid] += r2[tid + st]; }
        __syncthreads();
    }
    float mean = r1[0] * (1.0f / 1024.0f);
    float var = r2[0] * (1.0f / 1024.0f) - mean * mean;
    float rstd = rsqrtf(var + 1e-5f);
    float4 gg = ((const float4*)g)[tid], bb = ((const float4*)bet)[tid];
    float4 oo;
    oo.x = (x.x - mean) * rstd * gg.x + bb.x;
    oo.y = (x.y - mean) * rstd * gg.y + bb.y;
    oo.z = (x.z - mean) * rstd * gg.z + bb.z;
    oo.w = (x.w - mean) * rstd * gg.w + bb.w;
    ((float4*)(out + (size_t)row * 1024))[tid] = oo;
    if (WR) {
        float4 q;
        q.x = rtf(oo.x); q.y = rtf(oo.y); q.z = rtf(oo.z); q.w = rtf(oo.w);
        ((float4*)(out_r + (size_t)row * 1024))[tid] = q;
    }
}

// ==================== kv GEMM body: 128x256 NT, 3-stage, ld 36, ROW-GATHERED ==========
__device__ __forceinline__ void kv_body_m(const float* __restrict__ A, const float* __restrict__ B,
                                          const float* __restrict__ bias, float* __restrict__ C,
                                          int batch, int mt, int bn,
                                          const int* __restrict__ sidx, float* sm) {
    const int N = 2048, K = 1024;
    int tid = threadIdx.x;
    int wid = tid >> 5, lane = tid & 31;
    int warpRow = wid >> 2, warpCol = wid & 3;

    uint32_t s_base = (uint32_t)__cvta_generic_to_shared(sm);
    int ra = tid >> 3, ca = (tid & 7) * 4;
    int* idxs = (int*)(sm + 41472);
    if (tid < 128) idxs[tid] = sidx[batch * 2048 + mt * 128 + tid];
    __syncthreads();

    wmma::fragment<wmma::accumulator, 16, 16, 8, float> acc[4][4];
#pragma unroll
    for (int i = 0; i < 4; ++i)
#pragma unroll
        for (int j = 0; j < 4; ++j) wmma::fill_fragment(acc[i][j], 0.0f);

    const int KT = K >> 5;
    auto issue = [&](int stage, int k0) {
        uint32_t as = s_base + (uint32_t)(stage * 4608) * 4;
        uint32_t bs = s_base + (uint32_t)(13824 + stage * 9216) * 4;
#pragma unroll
        for (int it = 0; it < 4; ++it) {
            int r = ra + it * 32;
            int orig = idxs[r];
            orig = orig < 0 ? 0 : orig;
            cp16(as + (uint32_t)(r * 36 + ca) * 4,
                 A + ((size_t)batch * 2048 + orig) * 1024 + k0 + ca);
        }
#pragma unroll
        for (int it = 0; it < 8; ++it) {
            int r = ra + it * 32;
            cp16(bs + (uint32_t)(r * 36 + ca) * 4, B + (size_t)(bn + r) * K + k0 + ca);
        }
        CP_COMMIT();
    };

    issue(0, 0);
    issue(1, 32);
    for (int kt = 0; kt < KT; ++kt) {
        if (kt + 1 < KT) CP_WAIT(1);
        else CP_WAIT(0);
        __syncthreads();
        if (kt + 2 < KT) issue((kt + 2) % 3, (kt + 2) * 32);
        int stage = kt % 3;
        float* As = sm + stage * 4608;
        float* Bs = sm + 13824 + stage * 9216;
#pragma unroll
        for (int ks = 0; ks < 4; ++ks) {
            int kk = ks * 8;
            wmma::fragment<wmma::matrix_a, 16, 16, 8, wmma::precision::tf32, wmma::row_major> af[4];
            wmma::fragment<wmma::matrix_b, 16, 16, 8, wmma::precision::tf32, wmma::col_major> bf[4];
#pragma unroll
            for (int i = 0; i < 4; ++i)
                wmma::load_matrix_sync(af[i], &As[(warpRow * 64 + i * 16) * 36 + kk], 36);
#pragma unroll
            for (int j = 0; j < 4; ++j)
                wmma::load_matrix_sync(bf[j], &Bs[(warpCol * 64 + j * 16) * 36 + kk], 36);
#pragma unroll
            for (int i = 0; i < 4; ++i)
#pragma unroll
                for (int j = 0; j < 4; ++j) wmma::mma_sync(acc[i][j], af[i], bf[j], acc[i][j]);
        }
    }
    __syncthreads();

    float* st = &sm[wid * 384];
#pragma unroll
    for (int i = 0; i < 4; ++i) {
#pragma unroll
        for (int j = 0; j < 4; ++j) {
            wmma::store_matrix_sync(st, acc[i][j], 24, wmma::mem_row_major);
            __syncwarp();
            int r = lane >> 1, c8 = (lane & 1) * 8;
            int row_local = warpRow * 64 + i * 16 + r;
            int orig = idxs[row_local];
            int col0 = bn + warpCol * 64 + j * 16;
            if (orig >= 0) {
                float4 v0 = *(float4*)&st[r * 24 + c8];
                float4 v1 = *(float4*)&st[r * 24 + c8 + 4];
                const float* bp = bias + col0 + c8;
                v0.x = rtf(v0.x + bp[0]); v0.y = rtf(v0.y + bp[1]);
                v0.z = rtf(v0.z + bp[2]); v0.w = rtf(v0.w + bp[3]);
                v1.x = rtf(v1.x + bp[4]); v1.y = rtf(v1.y + bp[5]);
                v1.z = rtf(v1.z + bp[6]); v1.w = rtf(v1.w + bp[7]);
                float* cp = C + ((size_t)batch * 2048 + orig) * N + col0 + c8;
                *(float4*)cp = v0;
                *(float4*)(cp + 4) = v1;
            }
            __syncwarp();
        }
    }
}

// G1: masked kv GEMM + q projection
__global__ void __launch_bounds__(256, 1)
g1_kernel(const float* ctx_r, const float* Wkv, const float* bkv, float* kvb,
          const float* lat_r, const float* Wq, const float* bq, float* qh,
          const int* sidx, const int* scnt) {
    extern __shared__ float sm[];
    int bx = blockIdx.x;
    if (bx < 1024) {
        int batch = bx >> 7;
        int mt = (bx >> 3) & 15;
        if (mt * 128 >= scnt[batch]) return;
        kv_body_m(ctx_r, Wkv, bkv, kvb, batch, mt, (bx & 7) * 256, sidx, sm);
    } else {
        int idx = bx - 1024;
        small_body<0, 1, 1, 0>(lat_r, Wq, bq, qh, 1024, 1024, 1024,
                               (idx >> 3) * 64, (idx & 7) * 128, sm);
    }
}

// ==================== scores (COMPACTED columns) + chunk stats ========================
__global__ void __launch_bounds__(256)
scores_wmma(const float* __restrict__ qh, const float* __restrict__ kv,
            const int* __restrict__ sidx, const int* __restrict__ scnt,
            float* __restrict__ scores, float* __restrict__ cstat) {
    extern __shared__ float sm[];
    float* Qs = sm;
    float* Ks = sm + 4352;
    int* sx = (int*)(sm + 13056);
    int bh = blockIdx.y;
    int b = bh >> 4, h = bh & 15;
    int s0 = blockIdx.x * 128;
    if (s0 >= scnt[b]) return;
    int tid = threadIdx.x, wid = tid >> 5, lane = tid & 31;

#pragma unroll
    for (int it = 0; it < 4; ++it) {
        int v = tid + it * 256;
        int r = v >> 4, c = (v & 15) * 4;
        *(float4*)&Qs[r * 68 + c] = *(const float4*)(qh + (size_t)(b * 64 + r) * 1024 + h * 64 + c);
    }
#pragma unroll
    for (int it = 0; it < 8; ++it) {
        int v = tid + it * 256;
        int r = v >> 4, c = (v & 15) * 4;
        int orig = sidx[b * 2048 + s0 + r];
        if ((v & 15) == 0) sx[r] = orig;
        int og = orig < 0 ? 0 : orig;
        *(float4*)&Ks[r * 68 + c] =
            *(const float4*)(kv + (size_t)(b * 2048 + og) * 2048 + h * 64 + c);
    }
    __syncthreads();

    int warpRow = wid >> 2, warpCol = wid & 3;
    wmma::fragment<wmma::accumulator, 16, 16, 8, float> acc[2][2];
#pragma unroll
    for (int i = 0; i < 2; ++i)
#pragma unroll
        for (int j = 0; j < 2; ++j) wmma::fill_fragment(acc[i][j], 0.0f);

#pragma unroll
    for (int ks = 0; ks < 8; ++ks) {
        int kk = ks * 8;
        wmma::fragment<wmma::matrix_a, 16, 16, 8, wmma::precision::tf32, wmma::row_major> af[2];
        wmma::fragment<wmma::matrix_b, 16, 16, 8, wmma::precision::tf32, wmma::col_major> bf[2];
#pragma unroll
        for (int i = 0; i < 2; ++i)
            wmma::load_matrix_sync(af[i], &Qs[(warpRow * 32 + i * 16) * 68 + kk], 68);
#pragma unroll
        for (int j = 0; j < 2; ++j)
            wmma::load_matrix_sync(bf[j], &Ks[(warpCol * 32 + j * 16) * 68 + kk], 68);
#pragma unroll
        for (int i = 0; i < 2; ++i)
#pragma unroll
            for (int j = 0; j < 2; ++j) wmma::mma_sync(acc[i][j], af[i], bf[j], acc[i][j]);
    }
    __syncthreads();

    const float NEG = __int_as_float(0xff800000);
    float* st = &sm[wid * 384];
    float* pm = sm + 3072;
    float* ps = sm + 3328;
#pragma unroll
    for (int i = 0; i < 2; ++i) {
        int r = lane >> 1, c8 = (lane & 1) * 8;
        int l = warpRow * 32 + i * 16 + r;
        float4 v0, v1, v2, v3;
        wmma::store_matrix_sync(st, acc[i][0], 24, wmma::mem_row_major);
        __syncwarp();
        v0 = *(float4*)&st[r * 24 + c8];
        v1 = *(float4*)&st[r * 24 + c8 + 4];
        __syncwarp();
        wmma::store_matrix_sync(st, acc[i][1], 24, wmma::mem_row_major);
        __syncwarp();
        v2 = *(float4*)&st[r * 24 + c8];
        v3 = *(float4*)&st[r * 24 + c8 + 4];
        __syncwarp();
        int lc0 = warpCol * 32 + c8;
        int lc1 = lc0 + 16;
        v0.x = sx[lc0 + 0] >= 0 ? v0.x * 0.125f : NEG;
        v0.y = sx[lc0 + 1] >= 0 ? v0.y * 0.125f : NEG;
        v0.z = sx[lc0 + 2] >= 0 ? v0.z * 0.125f : NEG;
        v0.w = sx[lc0 + 3] >= 0 ? v0.w * 0.125f : NEG;
        v1.x = sx[lc0 + 4] >= 0 ? v1.x * 0.125f : NEG;
        v1.y = sx[lc0 + 5] >= 0 ? v1.y * 0.125f : NEG;
        v1.z = sx[lc0 + 6] >= 0 ? v1.z * 0.125f : NEG;
        v1.w = sx[lc0 + 7] >= 0 ? v1.w * 0.125f : NEG;
        v2.x = sx[lc1 + 0] >= 0 ? v2.x * 0.125f : NEG;
        v2.y = sx[lc1 + 1] >= 0 ? v2.y * 0.125f : NEG;
        v2.z = sx[lc1 + 2] >= 0 ? v2.z * 0.125f : NEG;
        v2.w = sx[lc1 + 3] >= 0 ? v2.w * 0.125f : NEG;
        v3.x = sx[lc1 + 4] >= 0 ? v3.x * 0.125f : NEG;
        v3.y = sx[lc1 + 5] >= 0 ? v3.y * 0.125f : NEG;
        v3.z = sx[lc1 + 6] >= 0 ? v3.z * 0.125f : NEG;
        v3.w = sx[lc1 + 7] >= 0 ? v3.w * 0.125f : NEG;
        float* pp = scores + ((size_t)bh * 64 + l) * 2048 + s0 + lc0;
        *(float4*)pp = v0;
        *(float4*)(pp + 4) = v1;
        *(float4*)(pp + 16) = v2;
        *(float4*)(pp + 20) = v3;
        float mx = fmaxf(fmaxf(fmaxf(v0.x, v0.y), fmaxf(v0.z, v0.w)),
                         fmaxf(fmaxf(v1.x, v1.y), fmaxf(v1.z, v1.w)));
        mx = fmaxf(mx, fmaxf(fmaxf(fmaxf(v2.x, v2.y), fmaxf(v2.z, v2.w)),
                             fmaxf(fmaxf(v3.x, v3.y), fmaxf(v3.z, v3.w))));
        float m2 = fmaxf(mx, __shfl_xor_sync(0xffffffffu, mx, 1));
        float m2c = fmaxf(m2, -1e30f);
        float s = expf(v0.x - m2c) + expf(v0.y - m2c) + expf(v0.z - m2c) + expf(v0.w - m2c) +
                  expf(v1.x - m2c) + expf(v1.y - m2c) + expf(v1.z - m2c) + expf(v1.w - m2c) +
                  expf(v2.x - m2c) + expf(v2.y - m2c) + expf(v2.z - m2c) + expf(v2.w - m2c) +
                  expf(v3.x - m2c) + expf(v3.y - m2c) + expf(v3.z - m2c) + expf(v3.w - m2c);
        s += __shfl_xor_sync(0xffffffffu, s, 1);
        if ((lane & 1) == 0) {
            pm[l * 4 + warpCol] = m2;
            ps[l * 4 + warpCol] = s;
        }
    }
    __syncthreads();
    if (tid < 64) {
        float m0 = pm[tid * 4], m1 = pm[tid * 4 + 1], m2 = pm[tid * 4 + 2], m3 = pm[tid * 4 + 3];
        float m = fmaxf(fmaxf(m0, m1), fmaxf(m2, m3));
        float mc = fmaxf(m, -1e30f);
        float S = ps[tid * 4] * expf(m0 - mc) + ps[tid * 4 + 1] * expf(m1 - mc) +
                  ps[tid * 4 + 2] * expf(m2 - mc) + ps[tid * 4 + 3] * expf(m3 - mc);
        float2 o;
        o.x = m;
        o.y = S;
        *(float2*)&cstat[(((size_t)bh * 64 + tid) * 16 + blockIdx.x) * 2] = o;
    }
}

// ---------------- rowstat ----------------
__global__ void rowstat_kernel(const float* __restrict__ cstat, const int* __restrict__ scnt,
                               float* __restrict__ rowstat) {
    int row = blockIdx.x * 256 + threadIdx.x;
    int b = row >> 10;
    int nch = scnt[b] >> 7;
    const float2* c = (const float2*)cstat + row * 16;
    float M = __int_as_float(0xff800000);
    for (int k = 0; k < nch; ++k) M = fmaxf(M, c[k].x);
    float Mc = fmaxf(M, -1e30f);
    float S = 0.f;
    for (int k = 0; k < nch; ++k) S += c[k].y * expf(c[k].x - Mc);
    float2 o;
    o.x = Mc;
    o.y = 1.0f / S;
    ((float2*)rowstat)[row] = o;
}

// ==================== attn split-K (COMPACTED): inline softmax, V gathered ============
__device__ __forceinline__ void attn_body(const float* __restrict__ scores,
                                          const float* __restrict__ kv,
                                          const float* __restrict__ rowstat,
                                          const int* __restrict__ sidx,
                                          float* __restrict__ part,
                                          int bh, int split, int cnt, float* sm) {
    int b = bh >> 4, h = bh & 15;
    int base_s = split * 512;
    int ktmax = cnt - base_s;
    ktmax = (ktmax > 512 ? 512 : ktmax) >> 6;
    int tid = threadIdx.x, wid = tid >> 5, lane = tid & 31;
    int warpRow = wid >> 1, warpCol = wid & 1;

    uint32_t s_base = (uint32_t)__cvta_generic_to_shared(sm);
    int ra = tid >> 4, ca = (tid & 15) * 4;
    float* rs_m = sm + 26112;
    float* rs_i = sm + 26176;
    if (tid < 64) {
        float2 v = ((const float2*)rowstat)[bh * 64 + tid];
        rs_m[tid] = v.x;
        rs_i[tid] = v.y;
    }

    wmma::fragment<wmma::accumulator, 16, 16, 8, float> acc[2];
    wmma::fill_fragment(acc[0], 0.0f);
    wmma::fill_fragment(acc[1], 0.0f);

    auto issue = [&](int stage, int s0) {
        uint32_t ps = s_base + (uint32_t)(stage * 4352) * 4;
        uint32_t vs = s_base + (uint32_t)(13056 + stage * 4352) * 4;
#pragma unroll
        for (int it = 0; it < 4; ++it) {
            int r = ra + it * 16;
            cp16(ps + (uint32_t)(r * 68 + ca) * 4,
                 scores + ((size_t)bh * 64 + r) * 2048 + s0 + ca);
            int orig = sidx[b * 2048 + s0 + r];
            orig = orig < 0 ? 0 : orig;
            cp16(vs + (uint32_t)(r * 68 + ca) * 4,
                 kv + (size_t)(b * 2048 + orig) * 2048 + 1024 + h * 64 + ca);
        }
        CP_COMMIT();
    };

    issue(0, base_s);
    if (ktmax > 1) issue(1, base_s + 64);
    for (int kt = 0; kt < ktmax; ++kt) {
        if (kt + 1 < ktmax) CP_WAIT(1);
        else CP_WAIT(0);
        __syncthreads();
        int stage = kt % 3;
        float* Ps = sm + stage * 4352;
#pragma unroll
        for (int it = 0; it < 4; ++it) {
            int rr = ra + it * 16;
            float M = rs_m[rr], I = rs_i[rr];
            float4 v = *(float4*)&Ps[rr * 68 + ca];
            v.x = rtf(expf(v.x - M) * I);
            v.y = rtf(expf(v.y - M) * I);
            v.z = rtf(expf(v.z - M) * I);
            v.w = rtf(expf(v.w - M) * I);
            *(float4*)&Ps[rr * 68 + ca] = v;
        }
        __syncthreads();
        if (kt + 2 < ktmax) issue((kt + 2) % 3, base_s + (kt + 2) * 64);
        float* Vs = sm + 13056 + stage * 4352;
#pragma unroll
        for (int ks = 0; ks < 8; ++ks) {
            int kk = ks * 8;
            wmma::fragment<wmma::matrix_a, 16, 16, 8, wmma::precision::tf32, wmma::row_major> af;
            wmma::fragment<wmma::matrix_b, 16, 16, 8, wmma::precision::tf32, wmma::row_major> bf[2];
            wmma::load_matrix_sync(af, &Ps[(warpRow * 16) * 68 + kk], 68);
#pragma unroll
            for (int j = 0; j < 2; ++j)
                wmma::load_matrix_sync(bf[j], &Vs[kk * 68 + warpCol * 32 + j * 16], 68);
            wmma::mma_sync(acc[0], af, bf[0], acc[0]);
            wmma::mma_sync(acc[1], af, bf[1], acc[1]);
        }
    }
    __syncthreads();

    float* pout = part + (size_t)split * 524288;
    float* st = &sm[wid * 384];
#pragma unroll
    for (int j = 0; j < 2; ++j) {
        wmma::store_matrix_sync(st, acc[j], 24, wmma::mem_row_major);
        __syncwarp();
        int r = lane >> 1, c8 = (lane & 1) * 8;
        int l = warpRow * 16 + r;
        int d0 = warpCol * 32 + j * 16 + c8;
        float4 v0 = *(float4*)&st[r * 24 + c8];
        float4 v1 = *(float4*)&st[r * 24 + c8 + 4];
        float* ap = pout + (size_t)(b * 64 + l) * 1024 + h * 64 + d0;
        *(float4*)ap = v0;
        *(float4*)(ap + 4) = v1;
        __syncwarp();
    }
}

// A1: attn_part + mean_heads scatter
__global__ void __launch_bounds__(256, 2)
a1_kernel(const float* __restrict__ scores, const float* __restrict__ kv,
          const float* __restrict__ rowstat, const int* __restrict__ sidx,
          const int* __restrict__ scnt, float* __restrict__ part,
          float* __restrict__ aw) {
    extern __shared__ float sm[];
    int bx = blockIdx.x;
    if (bx < 512) {
        int bh = bx >> 2, split = bx & 3;
        int cnt = scnt[bh >> 4];
        if (split * 512 >= cnt) return;
        attn_body(scores, kv, rowstat, sidx, part, bh, split, cnt, sm);
    } else {
        int i = (bx - 512) * 256 + threadIdx.x;
        int s4 = i & 511;
        int l = (i >> 9) & 63;
        int b = i >> 15;
        if (s4 * 4 >= scnt[b]) return;
        int4 orig = *(const int4*)&sidx[b * 2048 + s4 * 4];
        float4 acc = {0.f, 0.f, 0.f, 0.f};
#pragma unroll
        for (int h = 0; h < 16; ++h) {
            size_t row = (size_t)(b * 16 + h) * 64 + l;
            float2 stt = ((const float2*)rowstat)[row];
            float4 x = *(const float4*)(scores + row * 2048 + s4 * 4);
            acc.x += expf(x.x - stt.x) * stt.y;
            acc.y += expf(x.y - stt.x) * stt.y;
            acc.z += expf(x.z - stt.x) * stt.y;
            acc.w += expf(x.w - stt.x) * stt.y;
        }
        const float inv = 1.0f / 16.0f;
        float* arow = aw + (size_t)(b * 64 + l) * 2048;
        if (orig.x >= 0) arow[orig.x] = acc.x * inv;
        if (orig.y >= 0) arow[orig.y] = acc.y * inv;
        if (orig.z >= 0) arow[orig.z] = acc.z * inv;
        if (orig.w >= 0) arow[orig.w] = acc.w * inv;
    }
}

// reduce ACTIVE partials -> attn (tf32-rounded)
__global__ void attn_reduce_kernel(const float* __restrict__ part, const int* __restrict__ scnt,
                                   float* __restrict__ attn) {
    int i = blockIdx.x * 256 + threadIdx.x;
    int b = i >> 14;
    int ns = (scnt[b] + 511) >> 9;
    float4 o = ((const float4*)part)[i];
    if (ns > 1) {
        float4 v = ((const float4*)(part + 524288))[i];
        o.x += v.x; o.y += v.y; o.z += v.z; o.w += v.w;
    }
    if (ns > 2) {
        float4 v = ((const float4*)(part + 1048576))[i];
        o.x += v.x; o.y += v.y; o.z += v.z; o.w += v.w;
    }
    if (ns > 3) {
        float4 v = ((const float4*)(part + 1572864))[i];
        o.x += v.x; o.y += v.y; o.z += v.z; o.w += v.w;
    }
    o.x = rtf(o.x); o.y = rtf(o.y); o.z = rtf(o.z); o.w = rtf(o.w);
    ((float4*)attn)[i] = o;
}

// ---------------- launch ----------------
extern "C" void kernel_launch(void* const* d_in, const int* in_sizes, int n_in,
                              void* d_out, int out_size) {
    (void)in_sizes; (void)n_in; (void)out_size;
    const float* latents = (const float*)d_in[0];
    const float* context = (const float*)d_in[1];
    const int* cmask = (const int*)d_in[2];
    const float* q_w = (const float*)d_in[3];
    const float* q_b = (const float*)d_in[4];
    const float* k_w = (const float*)d_in[5];
    const float* k_b = (const float*)d_in[6];
    const float* v_w = (const float*)d_in[7];
    const float* v_b = (const float*)d_in[8];
    const float* in_wq = (const float*)d_in[9];
    const float* in_bq = (const float*)d_in[10];
    const float* in_wk = (const float*)d_in[11];
    const float* in_bk = (const float*)d_in[12];
    const float* in_wv = (const float*)d_in[13];
    const float* in_bv = (const float*)d_in[14];
    const float* out_w = (const float*)d_in[15];
    const float* out_b = (const float*)d_in[16];
    const float* ln1_g = (const float*)d_in[17];
    const float* ln1_b = (const float*)d_in[18];
    const float* ln2_g = (const float*)d_in[19];
    const float* ln2_b = (const float*)d_in[20];
    const float* ff_w1 = (const float*)d_in[21];
    const float* ff_b1 = (const float*)d_in[22];
    const float* ff_w2 = (const float*)d_in[23];
    const float* ff_b2 = (const float*)d_in[24];

    float* out = (float*)d_out;
    float* aw_out = out + 512 * 1024;

    void* p;
    cudaGetSymbolAddress(&p, g_ctx_r);   float* ctx_r = (float*)p;
    cudaGetSymbolAddress(&p, g_lat_r);   float* lat_r = (float*)p;
    cudaGetSymbolAddress(&p, g_Wq);      float* Wq = (float*)p;
    cudaGetSymbolAddress(&p, g_Wkv);     float* Wkv = (float*)p;
    cudaGetSymbolAddress(&p, g_bq);      float* bq = (float*)p;
    cudaGetSymbolAddress(&p, g_bkv);     float* bkv = (float*)p;
    cudaGetSymbolAddress(&p, g_qh);      float* qh = (float*)p;
    cudaGetSymbolAddress(&p, g_kv);      float* kvb = (float*)p;
    cudaGetSymbolAddress(&p, g_scores);  float* scores = (float*)p;
    cudaGetSymbolAddress(&p, g_cstat);   float* cstat = (float*)p;
    cudaGetSymbolAddress(&p, g_rowstat); float* rowstat = (float*)p;
    cudaGetSymbolAddress(&p, g_part);    float* part = (float*)p;
    cudaGetSymbolAddress(&p, g_attn);    float* attn = (float*)p;
    cudaGetSymbolAddress(&p, g_x);       float* xb = (float*)p;
    cudaGetSymbolAddress(&p, g_xr);      float* xr = (float*)p;
    cudaGetSymbolAddress(&p, g_h1);      float* h1 = (float*)p;
    cudaGetSymbolAddress(&p, g_sidx);    int* sidx = (int*)p;
    cudaGetSymbolAddress(&p, g_scnt);    int* scnt = (int*)p;

    cudaFuncSetAttribute(mega_prologue, cudaFuncAttributeMaxDynamicSharedMemorySize, 77824);
    cudaFuncSetAttribute(wmma_gemm_small<1, 1, 1, 1>, cudaFuncAttributeMaxDynamicSharedMemorySize, 82944);
    cudaFuncSetAttribute(wmma_gemm_splitk<1>, cudaFuncAttributeMaxDynamicSharedMemorySize, 82944);
    cudaFuncSetAttribute(g1_kernel, cudaFuncAttributeMaxDynamicSharedMemorySize, 166400);
    cudaFuncSetAttribute(scores_wmma, cudaFuncAttributeMaxDynamicSharedMemorySize, 52736);
    cudaFuncSetAttribute(a1_kernel, cudaFuncAttributeMaxDynamicSharedMemorySize, 104960);

    // ---- mega prologue: fuse GEMMs + rounding (8 f4/thread) + biases + compaction + aw zero
    mega_prologue<<<6408, 256, 77824>>>(
        in_wq, q_w, Wq,
        in_wk, k_w, Wkv,
        in_wv, v_w, Wkv + 1024 * 1024,
        (const float4*)context, (float4*)ctx_r,
        (const float4*)latents, (float4*)lat_r,
        q_b, in_bq, k_b, in_bk, v_b, in_bv,
        bq, bkv, cmask, sidx, scnt, (float4*)aw_out);

    // ---- G1: masked-compacted kv projection + q projection (merged) ----
    g1_kernel<<<1088, 256, 166400>>>(ctx_r, Wkv, bkv, kvb, lat_r, Wq, bq, qh, sidx, scnt);

    // ---- attention on compacted columns ----
    scores_wmma<<<dim3(16, 128), 256, 52736>>>(qh, kvb, sidx, scnt, scores, cstat);
    rowstat_kernel<<<32, 256>>>(cstat, scnt, rowstat);
    a1_kernel<<<1536, 256, 104960>>>(scores, kvb, rowstat, sidx, scnt, part, aw_out);
    attn_reduce_kernel<<<512, 256>>>(part, scnt, attn);

    // ---- out projection: split-K=2; fused reduce+bias+LN1 -> xb, xr ----
    wmma_gemm_splitk<1><<<dim3(8, 8, 2), 256, 82944>>>(attn, out_w, part, 1024, 512);
    reduce_ln_kernel<2, 1><<<512, 256>>>(part, out_b, latents, ln1_g, ln1_b, xb, xr);

    // ---- FFN: ff1 full; ff2 split-K=4; fused reduce+bias+LN2 -> out ----
    wmma_gemm_small<1, 1, 1, 1><<<dim3(32, 8), 256, 82944>>>(xr, ff_w1, ff_b1, h1, 4096, 1024, 1024);
    wmma_gemm_splitk<1><<<dim3(8, 8, 4), 256, 82944>>>(h1, ff_w2, part, 4096, 1024);
    reduce_ln_kernel<4, 0><<<512, 256>>>(part, ff_b2, xb, ln2_g, ln2_b, out, nullptr);
}

// round 16
// speedup vs baseline: 1.5440x; 1.0371x over previous
#include <cuda_runtime.h>
#include <mma.h>
#include <math.h>
#include <stdint.h>

using namespace nvcuda;

// Shapes: B=8, L=64, S=2048, D=1024, C=1024, H=16, HD=64

// ---------------- device scratch ----------------
__device__ float g_Wq[1024 * 1024];
__device__ float g_Wkv[2048 * 1024];
__device__ float g_bq[1024];
__device__ float g_bkv[2048];
__device__ float g_qh[512 * 1024];
__device__ float g_kv[16384 * 2048];        // masked rows stay 0 (never observed)
__device__ float g_scores[8192 * 2048];     // COMPACTED columns per batch
__device__ float g_cstat[8192 * 32];
__device__ float g_rowstat[8192 * 2];
__device__ float g_part[4 * 512 * 1024];
__device__ float g_attn[512 * 1024];
__device__ float g_x[512 * 1024];
__device__ float g_h1[512 * 4096];
__device__ int g_sidx[8 * 2048];
__device__ int g_scnt[8];

__device__ __forceinline__ float gelu_exact(float x) {
    return 0.5f * x * (1.0f + erff(x * 0.70710678118654752f));
}
__device__ __forceinline__ float rtf(float x) {
    float y;
    asm("cvt.rna.tf32.f32 %0, %1;" : "=f"(y) : "f"(x));
    return y;
}
__device__ __forceinline__ void cp16(uint32_t dst, const void* src) {
    asm volatile("cp.async.cg.shared.global [%0], [%1], 16;\n" ::"r"(dst), "l"(src));
}
#define CP_COMMIT() asm volatile("cp.async.commit_group;\n" ::)
#define CP_WAIT(n) asm volatile("cp.async.wait_group %0;\n" ::"n"(n))

// ==================== weight-fusion GEMM body 128x128 NN (in-fragment cvt) ===========
__device__ __forceinline__ void fuse_body(const float* __restrict__ A, const float* __restrict__ B,
                                          float* __restrict__ C, int bm, int bn, float* sm) {
    const int N = 1024, K = 1024;
    int tid = threadIdx.x;
    int wid = tid >> 5, lane = tid & 31;
    int warpRow = wid >> 2, warpCol = wid & 3;

    uint32_t s_base = (uint32_t)__cvta_generic_to_shared(sm);
    int ra = tid >> 3, ca = (tid & 7) * 4;
    int kb = tid >> 5, cb = (tid & 31) * 4;

    wmma::fragment<wmma::accumulator, 16, 16, 8, float> acc[4][2];
#pragma unroll
    for (int i = 0; i < 4; ++i)
#pragma unroll
        for (int j = 0; j < 2; ++j) wmma::fill_fragment(acc[i][j], 0.0f);

    const int KT = K >> 5;
    auto issue = [&](int stage, int k0) {
        uint32_t as = s_base + (uint32_t)(stage * 4608) * 4;
        uint32_t bs = s_base + (uint32_t)(9216 + stage * 5120) * 4;
#pragma unroll
        for (int it = 0; it < 4; ++it) {
            int r = ra + it * 32;
            cp16(as + (uint32_t)(r * 36 + ca) * 4, A + (size_t)(bm + r) * K + k0 + ca);
        }
#pragma unroll
        for (int it = 0; it < 4; ++it) {
            int kk = kb + it * 8;
            cp16(bs + (uint32_t)(kk * 136 + cb) * 4, B + (size_t)(k0 + kk) * N + bn + cb);
        }
        CP_COMMIT();
    };

    issue(0, 0);
    for (int kt = 0; kt < KT; ++kt) {
        int stage = kt & 1;
        if (kt + 1 < KT) {
            issue(stage ^ 1, (kt + 1) * 32);
            CP_WAIT(1);
        } else {
            CP_WAIT(0);
        }
        __syncthreads();
        float* As = sm + stage * 4608;
        float* Bs = sm + 9216 + stage * 5120;
#pragma unroll
        for (int ks = 0; ks < 4; ++ks) {
            int kk = ks * 8;
            wmma::fragment<wmma::matrix_a, 16, 16, 8, wmma::precision::tf32, wmma::row_major> af[4];
#pragma unroll
            for (int i = 0; i < 4; ++i) {
                wmma::load_matrix_sync(af[i], &As[(warpRow * 64 + i * 16) * 36 + kk], 36);
#pragma unroll
                for (int t = 0; t < af[i].num_elements; ++t)
                    af[i].x[t] = wmma::__float_to_tf32(af[i].x[t]);
            }
            wmma::fragment<wmma::matrix_b, 16, 16, 8, wmma::precision::tf32, wmma::row_major> bf[2];
#pragma unroll
            for (int j = 0; j < 2; ++j) {
                wmma::load_matrix_sync(bf[j], &Bs[kk * 136 + warpCol * 32 + j * 16], 136);
#pragma unroll
                for (int t = 0; t < bf[j].num_elements; ++t)
                    bf[j].x[t] = wmma::__float_to_tf32(bf[j].x[t]);
            }
#pragma unroll
            for (int i = 0; i < 4; ++i)
#pragma unroll
                for (int j = 0; j < 2; ++j) wmma::mma_sync(acc[i][j], af[i], bf[j], acc[i][j]);
        }
        __syncthreads();
    }

    float* st = &sm[wid * 384];
#pragma unroll
    for (int i = 0; i < 4; ++i) {
#pragma unroll
        for (int j = 0; j < 2; ++j) {
            wmma::store_matrix_sync(st, acc[i][j], 24, wmma::mem_row_major);
            __syncwarp();
            int row0 = bm + warpRow * 64 + i * 16;
            int col0 = bn + warpCol * 32 + j * 16;
            int r = lane >> 1, c8 = (lane & 1) * 8;
            float4 v0 = *(float4*)&st[r * 24 + c8];
            float4 v1 = *(float4*)&st[r * 24 + c8 + 4];
            v0.x = rtf(v0.x); v0.y = rtf(v0.y); v0.z = rtf(v0.z); v0.w = rtf(v0.w);
            v1.x = rtf(v1.x); v1.y = rtf(v1.y); v1.z = rtf(v1.z); v1.w = rtf(v1.w);
            float* cp = C + (size_t)(row0 + r) * N + col0 + c8;
            *(float4*)cp = v0;
            *(float4*)(cp + 4) = v1;
            __syncwarp();
        }
    }
}

// ==================== MEGA PROLOGUE ====================
// [0,192): weight-fusion GEMMs; [192,3264): fuse_bias; [3264,3272): compaction;
// [3272,4296): aw zero
__global__ void __launch_bounds__(256)
mega_prologue(
    const float* in_wq, const float* q_w, float* Wq,
    const float* in_wk, const float* k_w, float* Wkv0,
    const float* in_wv, const float* v_w, float* Wkv1,
    const float* q_b, const float* in_bq,
    const float* k_b, const float* in_bk,
    const float* v_b, const float* in_bv,
    float* bq, float* bkv, const int* cmask, int* sidx, int* scnt,
    float4* aw4) {
    extern __shared__ float sm[];
    __shared__ float red[256];
    __shared__ int sc[256];
    int bx = blockIdx.x, tid = threadIdx.x;
    if (bx < 192) {
        int z = bx >> 6, t = bx & 63;
        int bm = (t >> 3) * 128, bn = (t & 7) * 128;
        if (z == 0) fuse_body(in_wq, q_w, Wq, bm, bn, sm);
        else if (z == 1) fuse_body(in_wk, k_w, Wkv0, bm, bn, sm);
        else fuse_body(in_wv, v_w, Wkv1, bm, bn, sm);
    } else if (bx < 3264) {
        int idx = bx - 192;
        int z = idx >> 10, o = idx & 1023;
        const float* W = (z == 0) ? in_wq : (z == 1) ? in_wk : in_wv;
        const float* bin = (z == 0) ? q_b : (z == 1) ? k_b : v_b;
        const float* badd = (z == 0) ? in_bq : (z == 1) ? in_bk : in_bv;
        float* bout = (z == 0) ? bq : (z == 1) ? bkv : (bkv + 1024);
        float s = 0.f;
        for (int i = tid; i < 1024; i += 256) s += W[o * 1024 + i] * bin[i];
        red[tid] = s;
        __syncthreads();
        for (int st = 128; st > 0; st >>= 1) {
            if (tid < st) red[tid] += red[tid + st];
            __syncthreads();
        }
        if (tid == 0) bout[o] = red[0] + badd[o];
    } else if (bx < 3272) {
        int bb = bx - 3264;
        const int* m = cmask + bb * 2048;
        int base_s = tid * 8;
        int mv[8];
        int cnt = 0;
#pragma unroll
        for (int j = 0; j < 8; ++j) {
            mv[j] = m[base_s + j];
            cnt += (mv[j] != 0);
        }
        sc[tid] = cnt;
        __syncthreads();
        for (int off = 1; off < 256; off <<= 1) {
            int v = (tid >= off) ? sc[tid - off] : 0;
            __syncthreads();
            sc[tid] += v;
            __syncthreads();
        }
        int pos = sc[tid] - cnt;
        int total = sc[255];
#pragma unroll
        for (int j = 0; j < 8; ++j)
            if (mv[j]) sidx[bb * 2048 + pos++] = base_s + j;
        int padded = (total + 127) & ~127;
        for (int i = total + tid; i < padded; i += 256) sidx[bb * 2048 + i] = -1;
        if (tid == 0) scnt[bb] = padded;
    } else {
        int i = (bx - 3272) * 256 + tid;
        float4 z = {0.f, 0.f, 0.f, 0.f};
        aw4[i] = z;
    }
}

// ==================== small GEMM body: 64x128 NT, 3-stage, ld 36, generic K ==========
template <int EPI, int BIAS, int RND, int CVTA, int CVTB>
__device__ __forceinline__ void small_body(const float* __restrict__ A, const float* __restrict__ B,
                                           const float* __restrict__ bias, float* __restrict__ C,
                                           int N, int lda, int ksz, int bm, int bn, float* sm) {
    int tid = threadIdx.x;
    int wid = tid >> 5, lane = tid & 31;
    int warpRow = wid >> 2, warpCol = wid & 3;

    uint32_t s_base = (uint32_t)__cvta_generic_to_shared(sm);
    int ra = tid >> 3, ca = (tid & 7) * 4;

    wmma::fragment<wmma::accumulator, 16, 16, 8, float> acc[2][2];
#pragma unroll
    for (int i = 0; i < 2; ++i)
#pragma unroll
        for (int j = 0; j < 2; ++j) wmma::fill_fragment(acc[i][j], 0.0f);

    const int KT = ksz >> 5;
    auto issue = [&](int stage, int k0) {
        uint32_t as = s_base + (uint32_t)(stage * 2304) * 4;
        uint32_t bs = s_base + (uint32_t)(6912 + stage * 4608) * 4;
#pragma unroll
        for (int it = 0; it < 2; ++it) {
            int r = ra + it * 32;
            cp16(as + (uint32_t)(r * 36 + ca) * 4, A + (size_t)(bm + r) * lda + k0 + ca);
        }
#pragma unroll
        for (int it = 0; it < 4; ++it) {
            int r = ra + it * 32;
            cp16(bs + (uint32_t)(r * 36 + ca) * 4, B + (size_t)(bn + r) * lda + k0 + ca);
        }
        CP_COMMIT();
    };

    issue(0, 0);
    if (KT > 1) issue(1, 32);
    for (int kt = 0; kt < KT; ++kt) {
        if (kt + 1 < KT) CP_WAIT(1);
        else CP_WAIT(0);
        __syncthreads();
        if (kt + 2 < KT) issue((kt + 2) % 3, (kt + 2) * 32);
        int stage = kt % 3;
        float* As = sm + stage * 2304;
        float* Bs = sm + 6912 + stage * 4608;
#pragma unroll
        for (int ks = 0; ks < 4; ++ks) {
            int kk = ks * 8;
            wmma::fragment<wmma::matrix_a, 16, 16, 8, wmma::precision::tf32, wmma::row_major> af[2];
            wmma::fragment<wmma::matrix_b, 16, 16, 8, wmma::precision::tf32, wmma::col_major> bf[2];
#pragma unroll
            for (int i = 0; i < 2; ++i) {
                wmma::load_matrix_sync(af[i], &As[(warpRow * 32 + i * 16) * 36 + kk], 36);
                if (CVTA) {
#pragma unroll
                    for (int t = 0; t < af[i].num_elements; ++t)
                        af[i].x[t] = wmma::__float_to_tf32(af[i].x[t]);
                }
            }
#pragma unroll
            for (int j = 0; j < 2; ++j) {
                wmma::load_matrix_sync(bf[j], &Bs[(warpCol * 32 + j * 16) * 36 + kk], 36);
                if (CVTB) {
#pragma unroll
                    for (int t = 0; t < bf[j].num_elements; ++t)
                        bf[j].x[t] = wmma::__float_to_tf32(bf[j].x[t]);
                }
            }
#pragma unroll
            for (int i = 0; i < 2; ++i)
#pragma unroll
                for (int j = 0; j < 2; ++j) wmma::mma_sync(acc[i][j], af[i], bf[j], acc[i][j]);
        }
    }
    __syncthreads();

    float* st = &sm[wid * 384];
#pragma unroll
    for (int i = 0; i < 2; ++i) {
#pragma unroll
        for (int j = 0; j < 2; ++j) {
            wmma::store_matrix_sync(st, acc[i][j], 24, wmma::mem_row_major);
            __syncwarp();
            int row0 = bm + warpRow * 32 + i * 16;
            int col0 = bn + warpCol * 32 + j * 16;
            int r = lane >> 1, c8 = (lane & 1) * 8;
            float4 v0 = *(float4*)&st[r * 24 + c8];
            float4 v1 = *(float4*)&st[r * 24 + c8 + 4];
            if (BIAS) {
                const float* bp = bias + col0 + c8;
                v0.x += bp[0]; v0.y += bp[1]; v0.z += bp[2]; v0.w += bp[3];
                v1.x += bp[4]; v1.y += bp[5]; v1.z += bp[6]; v1.w += bp[7];
            }
            if (EPI) {
                v0.x = gelu_exact(v0.x); v0.y = gelu_exact(v0.y);
                v0.z = gelu_exact(v0.z); v0.w = gelu_exact(v0.w);
                v1.x = gelu_exact(v1.x); v1.y = gelu_exact(v1.y);
                v1.z = gelu_exact(v1.z); v1.w = gelu_exact(v1.w);
            }
            if (RND) {
                v0.x = rtf(v0.x); v0.y = rtf(v0.y); v0.z = rtf(v0.z); v0.w = rtf(v0.w);
                v1.x = rtf(v1.x); v1.y = rtf(v1.y); v1.z = rtf(v1.z); v1.w = rtf(v1.w);
            }
            float* cp = C + (size_t)(row0 + r) * N + col0 + c8;
            *(float4*)cp = v0;
            *(float4*)(cp + 4) = v1;
            __syncwarp();
        }
    }
}

template <int EPI, int BIAS, int RND, int CVTA, int CVTB>
__global__ void __launch_bounds__(256, 2)
wmma_gemm_small(const float* __restrict__ A, const float* __restrict__ B,
                const float* __restrict__ bias, float* __restrict__ C,
                int N, int lda, int ksz) {
    extern __shared__ float sm[];
    small_body<EPI, BIAS, RND, CVTA, CVTB>(A, B, bias, C, N, lda, ksz,
                                           blockIdx.y * 64, blockIdx.x * 128, sm);
}

// split-K partial GEMM
template <int CVTA, int CVTB>
__global__ void __launch_bounds__(256, 2)
wmma_gemm_splitk(const float* __restrict__ A, const float* __restrict__ B,
                 float* __restrict__ part, int lda, int ksz) {
    extern __shared__ float sm[];
    int z = blockIdx.z;
    small_body<0, 0, 0, CVTA, CVTB>(A + (size_t)z * ksz, B + (size_t)z * ksz, nullptr,
                                    part + (size_t)z * 524288, 1024, lda, ksz,
                                    blockIdx.y * 64, blockIdx.x * 128, sm);
}

// fused: reduce NS split-K partials + bias -> residual add + LayerNorm
template <int NS>
__global__ void reduce_ln_kernel(const float* __restrict__ part, const float* __restrict__ bias,
                                 const float* __restrict__ res, const float* __restrict__ g,
                                 const float* __restrict__ bet, float* __restrict__ out) {
    int row = blockIdx.x, tid = threadIdx.x;
    int i = row * 256 + tid;
    float4 o = ((const float4*)part)[i];
#pragma unroll
    for (int s = 1; s < NS; ++s) {
        float4 v = ((const float4*)(part + (size_t)s * 524288))[i];
        o.x += v.x; o.y += v.y; o.z += v.z; o.w += v.w;
    }
    const float* bp = bias + tid * 4;
    o.x += bp[0]; o.y += bp[1]; o.z += bp[2]; o.w += bp[3];
    float4 vr = ((const float4*)(res + (size_t)row * 1024))[tid];
    float4 x;
    x.x = vr.x + o.x; x.y = vr.y + o.y; x.z = vr.z + o.z; x.w = vr.w + o.w;
    float s = (x.x + x.y) + (x.z + x.w);
    float sq = x.x * x.x + x.y * x.y + x.z * x.z + x.w * x.w;
    __shared__ float r1[256], r2[256];
    r1[tid] = s; r2[tid] = sq;
    __syncthreads();
    for (int st = 128; st > 0; st >>= 1) {
        if (tid < st) { r1[tid] += r1[tid + st]; r2[tid] += r2[tid + st]; }
        __syncthreads();
    }
    float mean = r1[0] * (1.0f / 1024.0f);
    float var = r2[0] * (1.0f / 1024.0f) - mean * mean;
    float rstd = rsqrtf(var + 1e-5f);
    float4 gg = ((const float4*)g)[tid], bb = ((const float4*)bet)[tid];
    float4 oo;
    oo.x = (x.x - mean) * rstd * gg.x + bb.x;
    oo.y = (x.y - mean) * rstd * gg.y + bb.y;
    oo.z = (x.z - mean) * rstd * gg.z + bb.z;
    oo.w = (x.w - mean) * rstd * gg.w + bb.w;
    ((float4*)(out + (size_t)row * 1024))[tid] = oo;
}

// ==================== kv GEMM body: 128x256 NT, 3-stage, ld 36, ROW-GATHERED ==========
// A = RAW context, in-fragment tf32 cvt (identical to pre-rounding).
__device__ __forceinline__ void kv_body_m(const float* __restrict__ A, const float* __restrict__ B,
                                          const float* __restrict__ bias, float* __restrict__ C,
                                          int batch, int mt, int bn,
                                          const int* __restrict__ sidx, float* sm) {
    const int N = 2048, K = 1024;
    int tid = threadIdx.x;
    int wid = tid >> 5, lane = tid & 31;
    int warpRow = wid >> 2, warpCol = wid & 3;

    uint32_t s_base = (uint32_t)__cvta_generic_to_shared(sm);
    int ra = tid >> 3, ca = (tid & 7) * 4;
    int* idxs = (int*)(sm + 41472);
    if (tid < 128) idxs[tid] = sidx[batch * 2048 + mt * 128 + tid];
    __syncthreads();

    wmma::fragment<wmma::accumulator, 16, 16, 8, float> acc[4][4];
#pragma unroll
    for (int i = 0; i < 4; ++i)
#pragma unroll
        for (int j = 0; j < 4; ++j) wmma::fill_fragment(acc[i][j], 0.0f);

    const int KT = K >> 5;
    auto issue = [&](int stage, int k0) {
        uint32_t as = s_base + (uint32_t)(stage * 4608) * 4;
        uint32_t bs = s_base + (uint32_t)(13824 + stage * 9216) * 4;
#pragma unroll
        for (int it = 0; it < 4; ++it) {
            int r = ra + it * 32;
            int orig = idxs[r];
            orig = orig < 0 ? 0 : orig;
            cp16(as + (uint32_t)(r * 36 + ca) * 4,
                 A + ((size_t)batch * 2048 + orig) * 1024 + k0 + ca);
        }
#pragma unroll
        for (int it = 0; it < 8; ++it) {
            int r = ra + it * 32;
            cp16(bs + (uint32_t)(r * 36 + ca) * 4, B + (size_t)(bn + r) * K + k0 + ca);
        }
        CP_COMMIT();
    };

    issue(0, 0);
    issue(1, 32);
    for (int kt = 0; kt < KT; ++kt) {
        if (kt + 1 < KT) CP_WAIT(1);
        else CP_WAIT(0);
        __syncthreads();
        if (kt + 2 < KT) issue((kt + 2) % 3, (kt + 2) * 32);
        int stage = kt % 3;
        float* As = sm + stage * 4608;
        float* Bs = sm + 13824 + stage * 9216;
#pragma unroll
        for (int ks = 0; ks < 4; ++ks) {
            int kk = ks * 8;
            wmma::fragment<wmma::matrix_a, 16, 16, 8, wmma::precision::tf32, wmma::row_major> af[4];
            wmma::fragment<wmma::matrix_b, 16, 16, 8, wmma::precision::tf32, wmma::col_major> bf[4];
#pragma unroll
            for (int i = 0; i < 4; ++i) {
                wmma::load_matrix_sync(af[i], &As[(warpRow * 64 + i * 16) * 36 + kk], 36);
#pragma unroll
                for (int t = 0; t < af[i].num_elements; ++t)
                    af[i].x[t] = wmma::__float_to_tf32(af[i].x[t]);
            }
#pragma unroll
            for (int j = 0; j < 4; ++j)
                wmma::load_matrix_sync(bf[j], &Bs[(warpCol * 64 + j * 16) * 36 + kk], 36);
#pragma unroll
            for (int i = 0; i < 4; ++i)
#pragma unroll
                for (int j = 0; j < 4; ++j) wmma::mma_sync(acc[i][j], af[i], bf[j], acc[i][j]);
        }
    }
    __syncthreads();

    float* st = &sm[wid * 384];
#pragma unroll
    for (int i = 0; i < 4; ++i) {
#pragma unroll
        for (int j = 0; j < 4; ++j) {
            wmma::store_matrix_sync(st, acc[i][j], 24, wmma::mem_row_major);
            __syncwarp();
            int r = lane >> 1, c8 = (lane & 1) * 8;
            int row_local = warpRow * 64 + i * 16 + r;
            int orig = idxs[row_local];
            int col0 = bn + warpCol * 64 + j * 16;
            if (orig >= 0) {
                float4 v0 = *(float4*)&st[r * 24 + c8];
                float4 v1 = *(float4*)&st[r * 24 + c8 + 4];
                const float* bp = bias + col0 + c8;
                v0.x = rtf(v0.x + bp[0]); v0.y = rtf(v0.y + bp[1]);
                v0.z = rtf(v0.z + bp[2]); v0.w = rtf(v0.w + bp[3]);
                v1.x = rtf(v1.x + bp[4]); v1.y = rtf(v1.y + bp[5]);
                v1.z = rtf(v1.z + bp[6]); v1.w = rtf(v1.w + bp[7]);
                float* cp = C + ((size_t)batch * 2048 + orig) * N + col0 + c8;
                *(float4*)cp = v0;
                *(float4*)(cp + 4) = v1;
            }
            __syncwarp();
        }
    }
}

// G1: masked kv GEMM (raw context, CVTA) + q projection (raw latents, CVTA)
__global__ void __launch_bounds__(256, 1)
g1_kernel(const float* context, const float* Wkv, const float* bkv, float* kvb,
          const float* latents, const float* Wq, const float* bq, float* qh,
          const int* sidx, const int* scnt) {
    extern __shared__ float sm[];
    int bx = blockIdx.x;
    if (bx < 1024) {
        int batch = bx >> 7;
        int mt = (bx >> 3) & 15;
        if (mt * 128 >= scnt[batch]) return;
        kv_body_m(context, Wkv, bkv, kvb, batch, mt, (bx & 7) * 256, sidx, sm);
    } else {
        int idx = bx - 1024;
        small_body<0, 1, 1, 1, 0>(latents, Wq, bq, qh, 1024, 1024, 1024,
                                  (idx >> 3) * 64, (idx & 7) * 128, sm);
    }
}

// ==================== scores (COMPACTED columns) + chunk stats ========================
__global__ void __launch_bounds__(256)
scores_wmma(const float* __restrict__ qh, const float* __restrict__ kv,
            const int* __restrict__ sidx, const int* __restrict__ scnt,
            float* __restrict__ scores, float* __restrict__ cstat) {
    extern __shared__ float sm[];
    float* Qs = sm;
    float* Ks = sm + 4352;
    int* sx = (int*)(sm + 13056);
    int bh = blockIdx.y;
    int b = bh >> 4, h = bh & 15;
    int s0 = blockIdx.x * 128;
    if (s0 >= scnt[b]) return;
    int tid = threadIdx.x, wid = tid >> 5, lane = tid & 31;

#pragma unroll
    for (int it = 0; it < 4; ++it) {
        int v = tid + it * 256;
        int r = v >> 4, c = (v & 15) * 4;
        *(float4*)&Qs[r * 68 + c] = *(const float4*)(qh + (size_t)(b * 64 + r) * 1024 + h * 64 + c);
    }
#pragma unroll
    for (int it = 0; it < 8; ++it) {
        int v = tid + it * 256;
        int r = v >> 4, c = (v & 15) * 4;
        int orig = sidx[b * 2048 + s0 + r];
        if ((v & 15) == 0) sx[r] = orig;
        int og = orig < 0 ? 0 : orig;
        *(float4*)&Ks[r * 68 + c] =
            *(const float4*)(kv + (size_t)(b * 2048 + og) * 2048 + h * 64 + c);
    }
    __syncthreads();

    int warpRow = wid >> 2, warpCol = wid & 3;
    wmma::fragment<wmma::accumulator, 16, 16, 8, float> acc[2][2];
#pragma unroll
    for (int i = 0; i < 2; ++i)
#pragma unroll
        for (int j = 0; j < 2; ++j) wmma::fill_fragment(acc[i][j], 0.0f);

#pragma unroll
    for (int ks = 0; ks < 8; ++ks) {
        int kk = ks * 8;
        wmma::fragment<wmma::matrix_a, 16, 16, 8, wmma::precision::tf32, wmma::row_major> af[2];
        wmma::fragment<wmma::matrix_b, 16, 16, 8, wmma::precision::tf32, wmma::col_major> bf[2];
#pragma unroll
        for (int i = 0; i < 2; ++i)
            wmma::load_matrix_sync(af[i], &Qs[(warpRow * 32 + i * 16) * 68 + kk], 68);
#pragma unroll
        for (int j = 0; j < 2; ++j)
            wmma::load_matrix_sync(bf[j], &Ks[(warpCol * 32 + j * 16) * 68 + kk], 68);
#pragma unroll
        for (int i = 0; i < 2; ++i)
#pragma unroll
            for (int j = 0; j < 2; ++j) wmma::mma_sync(acc[i][j], af[i], bf[j], acc[i][j]);
    }
    __syncthreads();

    const float NEG = __int_as_float(0xff800000);
    float* st = &sm[wid * 384];
    float* pm = sm + 3072;
    float* ps = sm + 3328;
#pragma unroll
    for (int i = 0; i < 2; ++i) {
        int r = lane >> 1, c8 = (lane & 1) * 8;
        int l = warpRow * 32 + i * 16 + r;
        float4 v0, v1, v2, v3;
        wmma::store_matrix_sync(st, acc[i][0], 24, wmma::mem_row_major);
        __syncwarp();
        v0 = *(float4*)&st[r * 24 + c8];
        v1 = *(float4*)&st[r * 24 + c8 + 4];
        __syncwarp();
        wmma::store_matrix_sync(st, acc[i][1], 24, wmma::mem_row_major);
        __syncwarp();
        v2 = *(float4*)&st[r * 24 + c8];
        v3 = *(float4*)&st[r * 24 + c8 + 4];
        __syncwarp();
        int lc0 = warpCol * 32 + c8;
        int lc1 = lc0 + 16;
        v0.x = sx[lc0 + 0] >= 0 ? v0.x * 0.125f : NEG;
        v0.y = sx[lc0 + 1] >= 0 ? v0.y * 0.125f : NEG;
        v0.z = sx[lc0 + 2] >= 0 ? v0.z * 0.125f : NEG;
        v0.w = sx[lc0 + 3] >= 0 ? v0.w * 0.125f : NEG;
        v1.x = sx[lc0 + 4] >= 0 ? v1.x * 0.125f : NEG;
        v1.y = sx[lc0 + 5] >= 0 ? v1.y * 0.125f : NEG;
        v1.z = sx[lc0 + 6] >= 0 ? v1.z * 0.125f : NEG;
        v1.w = sx[lc0 + 7] >= 0 ? v1.w * 0.125f : NEG;
        v2.x = sx[lc1 + 0] >= 0 ? v2.x * 0.125f : NEG;
        v2.y = sx[lc1 + 1] >= 0 ? v2.y * 0.125f : NEG;
        v2.z = sx[lc1 + 2] >= 0 ? v2.z * 0.125f : NEG;
        v2.w = sx[lc1 + 3] >= 0 ? v2.w * 0.125f : NEG;
        v3.x = sx[lc1 + 4] >= 0 ? v3.x * 0.125f : NEG;
        v3.y = sx[lc1 + 5] >= 0 ? v3.y * 0.125f : NEG;
        v3.z = sx[lc1 + 6] >= 0 ? v3.z * 0.125f : NEG;
        v3.w = sx[lc1 + 7] >= 0 ? v3.w * 0.125f : NEG;
        float* pp = scores + ((size_t)bh * 64 + l) * 2048 + s0 + lc0;
        *(float4*)pp = v0;
        *(float4*)(pp + 4) = v1;
        *(float4*)(pp + 16) = v2;
        *(float4*)(pp + 20) = v3;
        float mx = fmaxf(fmaxf(fmaxf(v0.x, v0.y), fmaxf(v0.z, v0.w)),
                         fmaxf(fmaxf(v1.x, v1.y), fmaxf(v1.z, v1.w)));
        mx = fmaxf(mx, fmaxf(fmaxf(fmaxf(v2.x, v2.y), fmaxf(v2.z, v2.w)),
                             fmaxf(fmaxf(v3.x, v3.y), fmaxf(v3.z, v3.w))));
        float m2 = fmaxf(mx, __shfl_xor_sync(0xffffffffu, mx, 1));
        float m2c = fmaxf(m2, -1e30f);
        float s = expf(v0.x - m2c) + expf(v0.y - m2c) + expf(v0.z - m2c) + expf(v0.w - m2c) +
                  expf(v1.x - m2c) + expf(v1.y - m2c) + expf(v1.z - m2c) + expf(v1.w - m2c) +
                  expf(v2.x - m2c) + expf(v2.y - m2c) + expf(v2.z - m2c) + expf(v2.w - m2c) +
                  expf(v3.x - m2c) + expf(v3.y - m2c) + expf(v3.z - m2c) + expf(v3.w - m2c);
        s += __shfl_xor_sync(0xffffffffu, s, 1);
        if ((lane & 1) == 0) {
            pm[l * 4 + warpCol] = m2;
            ps[l * 4 + warpCol] = s;
        }
    }
    __syncthreads();
    if (tid < 64) {
        float m0 = pm[tid * 4], m1 = pm[tid * 4 + 1], m2 = pm[tid * 4 + 2], m3 = pm[tid * 4 + 3];
        float m = fmaxf(fmaxf(m0, m1), fmaxf(m2, m3));
        float mc = fmaxf(m, -1e30f);
        float S = ps[tid * 4] * expf(m0 - mc) + ps[tid * 4 + 1] * expf(m1 - mc) +
                  ps[tid * 4 + 2] * expf(m2 - mc) + ps[tid * 4 + 3] * expf(m3 - mc);
        float2 o;
        o.x = m;
        o.y = S;
        *(float2*)&cstat[(((size_t)bh * 64 + tid) * 16 + blockIdx.x) * 2] = o;
    }
}

// ---------------- rowstat ----------------
__global__ void rowstat_kernel(const float* __restrict__ cstat, const int* __restrict__ scnt,
                               float* __restrict__ rowstat) {
    int row = blockIdx.x * 256 + threadIdx.x;
    int b = row >> 10;
    int nch = scnt[b] >> 7;
    const float2* c = (const float2*)cstat + row * 16;
    float M = __int_as_float(0xff800000);
    for (int k = 0; k < nch; ++k) M = fmaxf(M, c[k].x);
    float Mc = fmaxf(M, -1e30f);
    float S = 0.f;
    for (int k = 0; k < nch; ++k) S += c[k].y * expf(c[k].x - Mc);
    float2 o;
    o.x = Mc;
    o.y = 1.0f / S;
    ((float2*)rowstat)[row] = o;
}

// ==================== attn split-K (COMPACTED): inline softmax, V gathered ============
__device__ __forceinline__ void attn_body(const float* __restrict__ scores,
                                          const float* __restrict__ kv,
                                          const float* __restrict__ rowstat,
                                          const int* __restrict__ sidx,
                                          float* __restrict__ part,
                                          int bh, int split, int cnt, float* sm) {
    int b = bh >> 4, h = bh & 15;
    int base_s = split * 512;
    int ktmax = cnt - base_s;
    ktmax = (ktmax > 512 ? 512 : ktmax) >> 6;
    int tid = threadIdx.x, wid = tid >> 5, lane = tid & 31;
    int warpRow = wid >> 1, warpCol = wid & 1;

    uint32_t s_base = (uint32_t)__cvta_generic_to_shared(sm);
    int ra = tid >> 4, ca = (tid & 15) * 4;
    float* rs_m = sm + 26112;
    float* rs_i = sm + 26176;
    if (tid < 64) {
        float2 v = ((const float2*)rowstat)[bh * 64 + tid];
        rs_m[tid] = v.x;
        rs_i[tid] = v.y;
    }

    wmma::fragment<wmma::accumulator, 16, 16, 8, float> acc[2];
    wmma::fill_fragment(acc[0], 0.0f);
    wmma::fill_fragment(acc[1], 0.0f);

    auto issue = [&](int stage, int s0) {
        uint32_t ps = s_base + (uint32_t)(stage * 4352) * 4;
        uint32_t vs = s_base + (uint32_t)(13056 + stage * 4352) * 4;
#pragma unroll
        for (int it = 0; it < 4; ++it) {
            int r = ra + it * 16;
            cp16(ps + (uint32_t)(r * 68 + ca) * 4,
                 scores + ((size_t)bh * 64 + r) * 2048 + s0 + ca);
            int orig = sidx[b * 2048 + s0 + r];
            orig = orig < 0 ? 0 : orig;
            cp16(vs + (uint32_t)(r * 68 + ca) * 4,
                 kv + (size_t)(b * 2048 + orig) * 2048 + 1024 + h * 64 + ca);
        }
        CP_COMMIT();
    };

    issue(0, base_s);
    if (ktmax > 1) issue(1, base_s + 64);
    for (int kt = 0; kt < ktmax; ++kt) {
        if (kt + 1 < ktmax) CP_WAIT(1);
        else CP_WAIT(0);
        __syncthreads();
        int stage = kt % 3;
        float* Ps = sm + stage * 4352;
#pragma unroll
        for (int it = 0; it < 4; ++it) {
            int rr = ra + it * 16;
            float M = rs_m[rr], I = rs_i[rr];
            float4 v = *(float4*)&Ps[rr * 68 + ca];
            v.x = rtf(expf(v.x - M) * I);
            v.y = rtf(expf(v.y - M) * I);
            v.z = rtf(expf(v.z - M) * I);
            v.w = rtf(expf(v.w - M) * I);
            *(float4*)&Ps[rr * 68 + ca] = v;
        }
        __syncthreads();
        if (kt + 2 < ktmax) issue((kt + 2) % 3, base_s + (kt + 2) * 64);
        float* Vs = sm + 13056 + stage * 4352;
#pragma unroll
        for (int ks = 0; ks < 8; ++ks) {
            int kk = ks * 8;
            wmma::fragment<wmma::matrix_a, 16, 16, 8, wmma::precision::tf32, wmma::row_major> af;
            wmma::fragment<wmma::matrix_b, 16, 16, 8, wmma::precision::tf32, wmma::row_major> bf[2];
            wmma::load_matrix_sync(af, &Ps[(warpRow * 16) * 68 + kk], 68);
#pragma unroll
            for (int j = 0; j < 2; ++j)
                wmma::load_matrix_sync(bf[j], &Vs[kk * 68 + warpCol * 32 + j * 16], 68);
            wmma::mma_sync(acc[0], af, bf[0], acc[0]);
            wmma::mma_sync(acc[1], af, bf[1], acc[1]);
        }
    }
    __syncthreads();

    float* pout = part + (size_t)split * 524288;
    float* st = &sm[wid * 384];
#pragma unroll
    for (int j = 0; j < 2; ++j) {
        wmma::store_matrix_sync(st, acc[j], 24, wmma::mem_row_major);
        __syncwarp();
        int r = lane >> 1, c8 = (lane & 1) * 8;
        int l = warpRow * 16 + r;
        int d0 = warpCol * 32 + j * 16 + c8;
        float4 v0 = *(float4*)&st[r * 24 + c8];
        float4 v1 = *(float4*)&st[r * 24 + c8 + 4];
        float* ap = pout + (size_t)(b * 64 + l) * 1024 + h * 64 + d0;
        *(float4*)ap = v0;
        *(float4*)(ap + 4) = v1;
        __syncwarp();
    }
}

// A1: attn_part + mean_heads scatter
__global__ void __launch_bounds__(256, 2)
a1_kernel(const float* __restrict__ scores, const float* __restrict__ kv,
          const float* __restrict__ rowstat, const int* __restrict__ sidx,
          const int* __restrict__ scnt, float* __restrict__ part,
          float* __restrict__ aw) {
    extern __shared__ float sm[];
    int bx = blockIdx.x;
    if (bx < 512) {
        int bh = bx >> 2, split = bx & 3;
        int cnt = scnt[bh >> 4];
        if (split * 512 >= cnt) return;
        attn_body(scores, kv, rowstat, sidx, part, bh, split, cnt, sm);
    } else {
        int i = (bx - 512) * 256 + threadIdx.x;
        int s4 = i & 511;
        int l = (i >> 9) & 63;
        int b = i >> 15;
        if (s4 * 4 >= scnt[b]) return;
        int4 orig = *(const int4*)&sidx[b * 2048 + s4 * 4];
        float4 acc = {0.f, 0.f, 0.f, 0.f};
#pragma unroll
        for (int h = 0; h < 16; ++h) {
            size_t row = (size_t)(b * 16 + h) * 64 + l;
            float2 stt = ((const float2*)rowstat)[row];
            float4 x = *(const float4*)(scores + row * 2048 + s4 * 4);
            acc.x += expf(x.x - stt.x) * stt.y;
            acc.y += expf(x.y - stt.x) * stt.y;
            acc.z += expf(x.z - stt.x) * stt.y;
            acc.w += expf(x.w - stt.x) * stt.y;
        }
        const float inv = 1.0f / 16.0f;
        float* arow = aw + (size_t)(b * 64 + l) * 2048;
        if (orig.x >= 0) arow[orig.x] = acc.x * inv;
        if (orig.y >= 0) arow[orig.y] = acc.y * inv;
        if (orig.z >= 0) arow[orig.z] = acc.z * inv;
        if (orig.w >= 0) arow[orig.w] = acc.w * inv;
    }
}

// reduce ACTIVE partials -> attn (unrounded; out-proj cvts in-fragment)
__global__ void attn_reduce_kernel(const float* __restrict__ part, const int* __restrict__ scnt,
                                   float* __restrict__ attn) {
    int i = blockIdx.x * 256 + threadIdx.x;
    int b = i >> 14;
    int ns = (scnt[b] + 511) >> 9;
    float4 o = ((const float4*)part)[i];
    if (ns > 1) {
        float4 v = ((const float4*)(part + 524288))[i];
        o.x += v.x; o.y += v.y; o.z += v.z; o.w += v.w;
    }
    if (ns > 2) {
        float4 v = ((const float4*)(part + 1048576))[i];
        o.x += v.x; o.y += v.y; o.z += v.z; o.w += v.w;
    }
    if (ns > 3) {
        float4 v = ((const float4*)(part + 1572864))[i];
        o.x += v.x; o.y += v.y; o.z += v.z; o.w += v.w;
    }
    ((float4*)attn)[i] = o;
}

// ---------------- launch ----------------
extern "C" void kernel_launch(void* const* d_in, const int* in_sizes, int n_in,
                              void* d_out, int out_size) {
    (void)in_sizes; (void)n_in; (void)out_size;
    const float* latents = (const float*)d_in[0];
    const float* context = (const float*)d_in[1];
    const int* cmask = (const int*)d_in[2];
    const float* q_w = (const float*)d_in[3];
    const float* q_b = (const float*)d_in[4];
    const float* k_w = (const float*)d_in[5];
    const float* k_b = (const float*)d_in[6];
    const float* v_w = (const float*)d_in[7];
    const float* v_b = (const float*)d_in[8];
    const float* in_wq = (const float*)d_in[9];
    const float* in_bq = (const float*)d_in[10];
    const float* in_wk = (const float*)d_in[11];
    const float* in_bk = (const float*)d_in[12];
    const float* in_wv = (const float*)d_in[13];
    const float* in_bv = (const float*)d_in[14];
    const float* out_w = (const float*)d_in[15];
    const float* out_b = (const float*)d_in[16];
    const float* ln1_g = (const float*)d_in[17];
    const float* ln1_b = (const float*)d_in[18];
    const float* ln2_g = (const float*)d_in[19];
    const float* ln2_b = (const float*)d_in[20];
    const float* ff_w1 = (const float*)d_in[21];
    const float* ff_b1 = (const float*)d_in[22];
    const float* ff_w2 = (const float*)d_in[23];
    const float* ff_b2 = (const float*)d_in[24];

    float* out = (float*)d_out;
    float* aw_out = out + 512 * 1024;

    void* p;
    cudaGetSymbolAddress(&p, g_Wq);      float* Wq = (float*)p;
    cudaGetSymbolAddress(&p, g_Wkv);     float* Wkv = (float*)p;
    cudaGetSymbolAddress(&p, g_bq);      float* bq = (float*)p;
    cudaGetSymbolAddress(&p, g_bkv);     float* bkv = (float*)p;
    cudaGetSymbolAddress(&p, g_qh);      float* qh = (float*)p;
    cudaGetSymbolAddress(&p, g_kv);      float* kvb = (float*)p;
    cudaGetSymbolAddress(&p, g_scores);  float* scores = (float*)p;
    cudaGetSymbolAddress(&p, g_cstat);   float* cstat = (float*)p;
    cudaGetSymbolAddress(&p, g_rowstat); float* rowstat = (float*)p;
    cudaGetSymbolAddress(&p, g_part);    float* part = (float*)p;
    cudaGetSymbolAddress(&p, g_attn);    float* attn = (float*)p;
    cudaGetSymbolAddress(&p, g_x);       float* xb = (float*)p;
    cudaGetSymbolAddress(&p, g_h1);      float* h1 = (float*)p;
    cudaGetSymbolAddress(&p, g_sidx);    int* sidx = (int*)p;
    cudaGetSymbolAddress(&p, g_scnt);    int* scnt = (int*)p;

    cudaFuncSetAttribute(mega_prologue, cudaFuncAttributeMaxDynamicSharedMemorySize, 77824);
    cudaFuncSetAttribute(wmma_gemm_small<1, 1, 0, 1, 1>, cudaFuncAttributeMaxDynamicSharedMemorySize, 82944);
    cudaFuncSetAttribute(wmma_gemm_splitk<1, 1>, cudaFuncAttributeMaxDynamicSharedMemorySize, 82944);
    cudaFuncSetAttribute(g1_kernel, cudaFuncAttributeMaxDynamicSharedMemorySize, 166400);
    cudaFuncSetAttribute(scores_wmma, cudaFuncAttributeMaxDynamicSharedMemorySize, 52736);
    cudaFuncSetAttribute(a1_kernel, cudaFuncAttributeMaxDynamicSharedMemorySize, 104960);

    // ---- mega prologue: fuse GEMMs + biases + compaction + aw zero ----
    mega_prologue<<<4296, 256, 77824>>>(
        in_wq, q_w, Wq,
        in_wk, k_w, Wkv,
        in_wv, v_w, Wkv + 1024 * 1024,
        q_b, in_bq, k_b, in_bk, v_b, in_bv,
        bq, bkv, cmask, sidx, scnt, (float4*)aw_out);

    // ---- G1: masked kv projection (raw ctx, CVTA) + q projection (raw latents, CVTA) ----
    g1_kernel<<<1088, 256, 166400>>>(context, Wkv, bkv, kvb, latents, Wq, bq, qh, sidx, scnt);

    // ---- attention on compacted columns ----
    scores_wmma<<<dim3(16, 128), 256, 52736>>>(qh, kvb, sidx, scnt, scores, cstat);
    rowstat_kernel<<<32, 256>>>(cstat, scnt, rowstat);
    a1_kernel<<<1536, 256, 104960>>>(scores, kvb, rowstat, sidx, scnt, part, aw_out);
    attn_reduce_kernel<<<512, 256>>>(part, scnt, attn);

    // ---- out projection: split-K=2 (A=attn CVTA, B=out_w CVTB); reduce+bias+LN1 -> xb --
    wmma_gemm_splitk<1, 1><<<dim3(8, 8, 2), 256, 82944>>>(attn, out_w, part, 1024, 512);
    reduce_ln_kernel<2><<<512, 256>>>(part, out_b, latents, ln1_g, ln1_b, xb);

    // ---- FFN: ff1 (A=xb CVTA, B=ff_w1 CVTB, GELU); ff2 split-K=4; reduce+bias+LN2 -> out
    wmma_gemm_small<1, 1, 0, 1, 1><<<dim3(32, 8), 256, 82944>>>(xb, ff_w1, ff_b1, h1, 4096, 1024, 1024);
    wmma_gemm_splitk<1, 1><<<dim3(8, 8, 4), 256, 82944>>>(h1, ff_w2, part, 4096, 1024);
    reduce_ln_kernel<4><<<512, 256>>>(part, ff_b2, xb, ln2_g, ln2_b, out);
}

// round 17
// speedup vs baseline: 1.5522x; 1.0053x over previous
#include <cuda_runtime.h>
#include <mma.h>
#include <math.h>
#include <stdint.h>

using namespace nvcuda;

// Shapes: B=8, L=64, S=2048, D=1024, C=1024, H=16, HD=64

// ---------------- device scratch ----------------
__device__ float g_Wq[1024 * 1024];
__device__ float g_Wkv[2048 * 1024];
__device__ float g_bq[1024];
__device__ float g_bkv[2048];
__device__ float g_qh[512 * 1024];
__device__ float g_kv[16384 * 2048];        // masked rows stay 0 (never observed)
__device__ float g_scores[8192 * 2048];     // COMPACTED columns per batch
__device__ float g_cstat[8192 * 32];
__device__ float g_part[4 * 512 * 1024];
__device__ float g_attn[512 * 1024];
__device__ float g_x[512 * 1024];
__device__ float g_h1[512 * 4096];
__device__ int g_sidx[8 * 2048];            // per-batch compacted indices (local, -1 pad)
__device__ int g_scnt[8];                   // per-batch padded count
__device__ int g_gidx[16384 + 128];         // GLOBAL compacted row list (kv GEMM)
__device__ int g_gcnt[1];                   // global padded count

__device__ __forceinline__ float gelu_exact(float x) {
    return 0.5f * x * (1.0f + erff(x * 0.70710678118654752f));
}
__device__ __forceinline__ float rtf(float x) {
    float y;
    asm("cvt.rna.tf32.f32 %0, %1;" : "=f"(y) : "f"(x));
    return y;
}
__device__ __forceinline__ void cp16(uint32_t dst, const void* src) {
    asm volatile("cp.async.cg.shared.global [%0], [%1], 16;\n" ::"r"(dst), "l"(src));
}
#define CP_COMMIT() asm volatile("cp.async.commit_group;\n" ::)
#define CP_WAIT(n) asm volatile("cp.async.wait_group %0;\n" ::"n"(n))

// ==================== weight-fusion GEMM body 128x128 NN (in-fragment cvt) ===========
__device__ __forceinline__ void fuse_body(const float* __restrict__ A, const float* __restrict__ B,
                                          float* __restrict__ C, int bm, int bn, float* sm) {
    const int N = 1024, K = 1024;
    int tid = threadIdx.x;
    int wid = tid >> 5, lane = tid & 31;
    int warpRow = wid >> 2, warpCol = wid & 3;

    uint32_t s_base = (uint32_t)__cvta_generic_to_shared(sm);
    int ra = tid >> 3, ca = (tid & 7) * 4;
    int kb = tid >> 5, cb = (tid & 31) * 4;

    wmma::fragment<wmma::accumulator, 16, 16, 8, float> acc[4][2];
#pragma unroll
    for (int i = 0; i < 4; ++i)
#pragma unroll
        for (int j = 0; j < 2; ++j) wmma::fill_fragment(acc[i][j], 0.0f);

    const int KT = K >> 5;
    auto issue = [&](int stage, int k0) {
        uint32_t as = s_base + (uint32_t)(stage * 4608) * 4;
        uint32_t bs = s_base + (uint32_t)(9216 + stage * 5120) * 4;
#pragma unroll
        for (int it = 0; it < 4; ++it) {
            int r = ra + it * 32;
            cp16(as + (uint32_t)(r * 36 + ca) * 4, A + (size_t)(bm + r) * K + k0 + ca);
        }
#pragma unroll
        for (int it = 0; it < 4; ++it) {
            int kk = kb + it * 8;
            cp16(bs + (uint32_t)(kk * 136 + cb) * 4, B + (size_t)(k0 + kk) * N + bn + cb);
        }
        CP_COMMIT();
    };

    issue(0, 0);
    for (int kt = 0; kt < KT; ++kt) {
        int stage = kt & 1;
        if (kt + 1 < KT) {
            issue(stage ^ 1, (kt + 1) * 32);
            CP_WAIT(1);
        } else {
            CP_WAIT(0);
        }
        __syncthreads();
        float* As = sm + stage * 4608;
        float* Bs = sm + 9216 + stage * 5120;
#pragma unroll
        for (int ks = 0; ks < 4; ++ks) {
            int kk = ks * 8;
            wmma::fragment<wmma::matrix_a, 16, 16, 8, wmma::precision::tf32, wmma::row_major> af[4];
#pragma unroll
            for (int i = 0; i < 4; ++i) {
                wmma::load_matrix_sync(af[i], &As[(warpRow * 64 + i * 16) * 36 + kk], 36);
#pragma unroll
                for (int t = 0; t < af[i].num_elements; ++t)
                    af[i].x[t] = wmma::__float_to_tf32(af[i].x[t]);
            }
            wmma::fragment<wmma::matrix_b, 16, 16, 8, wmma::precision::tf32, wmma::row_major> bf[2];
#pragma unroll
            for (int j = 0; j < 2; ++j) {
                wmma::load_matrix_sync(bf[j], &Bs[kk * 136 + warpCol * 32 + j * 16], 136);
#pragma unroll
                for (int t = 0; t < bf[j].num_elements; ++t)
                    bf[j].x[t] = wmma::__float_to_tf32(bf[j].x[t]);
            }
#pragma unroll
            for (int i = 0; i < 4; ++i)
#pragma unroll
                for (int j = 0; j < 2; ++j) wmma::mma_sync(acc[i][j], af[i], bf[j], acc[i][j]);
        }
        __syncthreads();
    }

    float* st = &sm[wid * 384];
#pragma unroll
    for (int i = 0; i < 4; ++i) {
#pragma unroll
        for (int j = 0; j < 2; ++j) {
            wmma::store_matrix_sync(st, acc[i][j], 24, wmma::mem_row_major);
            __syncwarp();
            int row0 = bm + warpRow * 64 + i * 16;
            int col0 = bn + warpCol * 32 + j * 16;
            int r = lane >> 1, c8 = (lane & 1) * 8;
            float4 v0 = *(float4*)&st[r * 24 + c8];
            float4 v1 = *(float4*)&st[r * 24 + c8 + 4];
            v0.x = rtf(v0.x); v0.y = rtf(v0.y); v0.z = rtf(v0.z); v0.w = rtf(v0.w);
            v1.x = rtf(v1.x); v1.y = rtf(v1.y); v1.z = rtf(v1.z); v1.w = rtf(v1.w);
            float* cp = C + (size_t)(row0 + r) * N + col0 + c8;
            *(float4*)cp = v0;
            *(float4*)(cp + 4) = v1;
            __syncwarp();
        }
    }
}

// ==================== MEGA PROLOGUE ====================
// [0,192): fuse GEMMs; [192,3264): fuse_bias; [3264,3272): per-batch compaction;
// [3272]: global compaction; [3273,4297): aw zero
__global__ void __launch_bounds__(256)
mega_prologue(
    const float* in_wq, const float* q_w, float* Wq,
    const float* in_wk, const float* k_w, float* Wkv0,
    const float* in_wv, const float* v_w, float* Wkv1,
    const float* q_b, const float* in_bq,
    const float* k_b, const float* in_bk,
    const float* v_b, const float* in_bv,
    float* bq, float* bkv, const int* cmask, int* sidx, int* scnt,
    int* gidx, int* gcnt, float4* aw4) {
    extern __shared__ float sm[];
    __shared__ float red[256];
    __shared__ int sc[256];
    int bx = blockIdx.x, tid = threadIdx.x;
    if (bx < 192) {
        int z = bx >> 6, t = bx & 63;
        int bm = (t >> 3) * 128, bn = (t & 7) * 128;
        if (z == 0) fuse_body(in_wq, q_w, Wq, bm, bn, sm);
        else if (z == 1) fuse_body(in_wk, k_w, Wkv0, bm, bn, sm);
        else fuse_body(in_wv, v_w, Wkv1, bm, bn, sm);
    } else if (bx < 3264) {
        int idx = bx - 192;
        int z = idx >> 10, o = idx & 1023;
        const float* W = (z == 0) ? in_wq : (z == 1) ? in_wk : in_wv;
        const float* bin = (z == 0) ? q_b : (z == 1) ? k_b : v_b;
        const float* badd = (z == 0) ? in_bq : (z == 1) ? in_bk : in_bv;
        float* bout = (z == 0) ? bq : (z == 1) ? bkv : (bkv + 1024);
        float s = 0.f;
        for (int i = tid; i < 1024; i += 256) s += W[o * 1024 + i] * bin[i];
        red[tid] = s;
        __syncthreads();
        for (int st = 128; st > 0; st >>= 1) {
            if (tid < st) red[tid] += red[tid + st];
            __syncthreads();
        }
        if (tid == 0) bout[o] = red[0] + badd[o];
    } else if (bx < 3272) {
        int bb = bx - 3264;
        const int* m = cmask + bb * 2048;
        int base_s = tid * 8;
        int mv[8];
        int cnt = 0;
#pragma unroll
        for (int j = 0; j < 8; ++j) {
            mv[j] = m[base_s + j];
            cnt += (mv[j] != 0);
        }
        sc[tid] = cnt;
        __syncthreads();
        for (int off = 1; off < 256; off <<= 1) {
            int v = (tid >= off) ? sc[tid - off] : 0;
            __syncthreads();
            sc[tid] += v;
            __syncthreads();
        }
        int pos = sc[tid] - cnt;
        int total = sc[255];
#pragma unroll
        for (int j = 0; j < 8; ++j)
            if (mv[j]) sidx[bb * 2048 + pos++] = base_s + j;
        int padded = (total + 127) & ~127;
        for (int i = total + tid; i < padded; i += 256) sidx[bb * 2048 + i] = -1;
        if (tid == 0) scnt[bb] = padded;
    } else if (bx == 3272) {
        // GLOBAL compaction over all 16384 rows (strided per-thread for coalescing)
        int mv[64];
        int cnt = 0;
#pragma unroll
        for (int j = 0; j < 64; ++j) {
            mv[j] = cmask[j * 256 + tid];
            cnt += (mv[j] != 0);
        }
        sc[tid] = cnt;
        __syncthreads();
        for (int off = 1; off < 256; off <<= 1) {
            int v = (tid >= off) ? sc[tid - off] : 0;
            __syncthreads();
            sc[tid] += v;
            __syncthreads();
        }
        int pos = sc[tid] - cnt;
        int total = sc[255];
#pragma unroll
        for (int j = 0; j < 64; ++j)
            if (mv[j]) gidx[pos++] = j * 256 + tid;
        int padded = (total + 127) & ~127;
        for (int i = total + tid; i < padded; i += 256) gidx[i] = -1;
        if (tid == 0) gcnt[0] = padded;
    } else {
        int i = (bx - 3273) * 256 + tid;
        float4 z = {0.f, 0.f, 0.f, 0.f};
        aw4[i] = z;
    }
}

// ==================== small GEMM body: 64x128 NT, 3-stage, ld 36, generic K ==========
template <int EPI, int BIAS, int RND, int CVTA, int CVTB>
__device__ __forceinline__ void small_body(const float* __restrict__ A, const float* __restrict__ B,
                                           const float* __restrict__ bias, float* __restrict__ C,
                                           int N, int lda, int ksz, int bm, int bn, float* sm) {
    int tid = threadIdx.x;
    int wid = tid >> 5, lane = tid & 31;
    int warpRow = wid >> 2, warpCol = wid & 3;

    uint32_t s_base = (uint32_t)__cvta_generic_to_shared(sm);
    int ra = tid >> 3, ca = (tid & 7) * 4;

    wmma::fragment<wmma::accumulator, 16, 16, 8, float> acc[2][2];
#pragma unroll
    for (int i = 0; i < 2; ++i)
#pragma unroll
        for (int j = 0; j < 2; ++j) wmma::fill_fragment(acc[i][j], 0.0f);

    const int KT = ksz >> 5;
    auto issue = [&](int stage, int k0) {
        uint32_t as = s_base + (uint32_t)(stage * 2304) * 4;
        uint32_t bs = s_base + (uint32_t)(6912 + stage * 4608) * 4;
#pragma unroll
        for (int it = 0; it < 2; ++it) {
            int r = ra + it * 32;
            cp16(as + (uint32_t)(r * 36 + ca) * 4, A + (size_t)(bm + r) * lda + k0 + ca);
        }
#pragma unroll
        for (int it = 0; it < 4; ++it) {
            int r = ra + it * 32;
            cp16(bs + (uint32_t)(r * 36 + ca) * 4, B + (size_t)(bn + r) * lda + k0 + ca);
        }
        CP_COMMIT();
    };

    issue(0, 0);
    if (KT > 1) issue(1, 32);
    for (int kt = 0; kt < KT; ++kt) {
        if (kt + 1 < KT) CP_WAIT(1);
        else CP_WAIT(0);
        __syncthreads();
        if (kt + 2 < KT) issue((kt + 2) % 3, (kt + 2) * 32);
        int stage = kt % 3;
        float* As = sm + stage * 2304;
        float* Bs = sm + 6912 + stage * 4608;
#pragma unroll
        for (int ks = 0; ks < 4; ++ks) {
            int kk = ks * 8;
            wmma::fragment<wmma::matrix_a, 16, 16, 8, wmma::precision::tf32, wmma::row_major> af[2];
            wmma::fragment<wmma::matrix_b, 16, 16, 8, wmma::precision::tf32, wmma::col_major> bf[2];
#pragma unroll
            for (int i = 0; i < 2; ++i) {
                wmma::load_matrix_sync(af[i], &As[(warpRow * 32 + i * 16) * 36 + kk], 36);
                if (CVTA) {
#pragma unroll
                    for (int t = 0; t < af[i].num_elements; ++t)
                        af[i].x[t] = wmma::__float_to_tf32(af[i].x[t]);
                }
            }
#pragma unroll
            for (int j = 0; j < 2; ++j) {
                wmma::load_matrix_sync(bf[j], &Bs[(warpCol * 32 + j * 16) * 36 + kk], 36);
                if (CVTB) {
#pragma unroll
                    for (int t = 0; t < bf[j].num_elements; ++t)
                        bf[j].x[t] = wmma::__float_to_tf32(bf[j].x[t]);
                }
            }
#pragma unroll
            for (int i = 0; i < 2; ++i)
#pragma unroll
                for (int j = 0; j < 2; ++j) wmma::mma_sync(acc[i][j], af[i], bf[j], acc[i][j]);
        }
    }
    __syncthreads();

    float* st = &sm[wid * 384];
#pragma unroll
    for (int i = 0; i < 2; ++i) {
#pragma unroll
        for (int j = 0; j < 2; ++j) {
            wmma::store_matrix_sync(st, acc[i][j], 24, wmma::mem_row_major);
            __syncwarp();
            int row0 = bm + warpRow * 32 + i * 16;
            int col0 = bn + warpCol * 32 + j * 16;
            int r = lane >> 1, c8 = (lane & 1) * 8;
            float4 v0 = *(float4*)&st[r * 24 + c8];
            float4 v1 = *(float4*)&st[r * 24 + c8 + 4];
            if (BIAS) {
                const float* bp = bias + col0 + c8;
                v0.x += bp[0]; v0.y += bp[1]; v0.z += bp[2]; v0.w += bp[3];
                v1.x += bp[4]; v1.y += bp[5]; v1.z += bp[6]; v1.w += bp[7];
            }
            if (EPI) {
                v0.x = gelu_exact(v0.x); v0.y = gelu_exact(v0.y);
                v0.z = gelu_exact(v0.z); v0.w = gelu_exact(v0.w);
                v1.x = gelu_exact(v1.x); v1.y = gelu_exact(v1.y);
                v1.z = gelu_exact(v1.z); v1.w = gelu_exact(v1.w);
            }
            if (RND) {
                v0.x = rtf(v0.x); v0.y = rtf(v0.y); v0.z = rtf(v0.z); v0.w = rtf(v0.w);
                v1.x = rtf(v1.x); v1.y = rtf(v1.y); v1.z = rtf(v1.z); v1.w = rtf(v1.w);
            }
            float* cp = C + (size_t)(row0 + r) * N + col0 + c8;
            *(float4*)cp = v0;
            *(float4*)(cp + 4) = v1;
            __syncwarp();
        }
    }
}

template <int EPI, int BIAS, int RND, int CVTA, int CVTB>
__global__ void __launch_bounds__(256, 2)
wmma_gemm_small(const float* __restrict__ A, const float* __restrict__ B,
                const float* __restrict__ bias, float* __restrict__ C,
                int N, int lda, int ksz) {
    extern __shared__ float sm[];
    small_body<EPI, BIAS, RND, CVTA, CVTB>(A, B, bias, C, N, lda, ksz,
                                           blockIdx.y * 64, blockIdx.x * 128, sm);
}

// split-K partial GEMM
template <int CVTA, int CVTB>
__global__ void __launch_bounds__(256, 2)
wmma_gemm_splitk(const float* __restrict__ A, const float* __restrict__ B,
                 float* __restrict__ part, int lda, int ksz) {
    extern __shared__ float sm[];
    int z = blockIdx.z;
    small_body<0, 0, 0, CVTA, CVTB>(A + (size_t)z * ksz, B + (size_t)z * ksz, nullptr,
                                    part + (size_t)z * 524288, 1024, lda, ksz,
                                    blockIdx.y * 64, blockIdx.x * 128, sm);
}

// fused: reduce NS split-K partials + bias -> residual add + LayerNorm
template <int NS>
__global__ void reduce_ln_kernel(const float* __restrict__ part, const float* __restrict__ bias,
                                 const float* __restrict__ res, const float* __restrict__ g,
                                 const float* __restrict__ bet, float* __restrict__ out) {
    int row = blockIdx.x, tid = threadIdx.x;
    int i = row * 256 + tid;
    float4 o = ((const float4*)part)[i];
#pragma unroll
    for (int s = 1; s < NS; ++s) {
        float4 v = ((const float4*)(part + (size_t)s * 524288))[i];
        o.x += v.x; o.y += v.y; o.z += v.z; o.w += v.w;
    }
    const float* bp = bias + tid * 4;
    o.x += bp[0]; o.y += bp[1]; o.z += bp[2]; o.w += bp[3];
    float4 vr = ((const float4*)(res + (size_t)row * 1024))[tid];
    float4 x;
    x.x = vr.x + o.x; x.y = vr.y + o.y; x.z = vr.z + o.z; x.w = vr.w + o.w;
    float s = (x.x + x.y) + (x.z + x.w);
    float sq = x.x * x.x + x.y * x.y + x.z * x.z + x.w * x.w;
    __shared__ float r1[256], r2[256];
    r1[tid] = s; r2[tid] = sq;
    __syncthreads();
    for (int st = 128; st > 0; st >>= 1) {
        if (tid < st) { r1[tid] += r1[tid + st]; r2[tid] += r2[tid + st]; }
        __syncthreads();
    }
    float mean = r1[0] * (1.0f / 1024.0f);
    float var = r2[0] * (1.0f / 1024.0f) - mean * mean;
    float rstd = rsqrtf(var + 1e-5f);
    float4 gg = ((const float4*)g)[tid], bb = ((const float4*)bet)[tid];
    float4 oo;
    oo.x = (x.x - mean) * rstd * gg.x + bb.x;
    oo.y = (x.y - mean) * rstd * gg.y + bb.y;
    oo.z = (x.z - mean) * rstd * gg.z + bb.z;
    oo.w = (x.w - mean) * rstd * gg.w + bb.w;
    ((float4*)(out + (size_t)row * 1024))[tid] = oo;
}

// ==================== kv GEMM body: 128x256 NT, GLOBAL row-gathered ==================
__device__ __forceinline__ void kv_body_g(const float* __restrict__ A, const float* __restrict__ B,
                                          const float* __restrict__ bias, float* __restrict__ C,
                                          int tile, int bn,
                                          const int* __restrict__ gidx, float* sm) {
    const int N = 2048, K = 1024;
    int tid = threadIdx.x;
    int wid = tid >> 5, lane = tid & 31;
    int warpRow = wid >> 2, warpCol = wid & 3;

    uint32_t s_base = (uint32_t)__cvta_generic_to_shared(sm);
    int ra = tid >> 3, ca = (tid & 7) * 4;
    int* idxs = (int*)(sm + 41472);
    if (tid < 128) idxs[tid] = gidx[tile * 128 + tid];
    __syncthreads();

    wmma::fragment<wmma::accumulator, 16, 16, 8, float> acc[4][4];
#pragma unroll
    for (int i = 0; i < 4; ++i)
#pragma unroll
        for (int j = 0; j < 4; ++j) wmma::fill_fragment(acc[i][j], 0.0f);

    const int KT = K >> 5;
    auto issue = [&](int stage, int k0) {
        uint32_t as = s_base + (uint32_t)(stage * 4608) * 4;
        uint32_t bs = s_base + (uint32_t)(13824 + stage * 9216) * 4;
#pragma unroll
        for (int it = 0; it < 4; ++it) {
            int r = ra + it * 32;
            int orig = idxs[r];
            orig = orig < 0 ? 0 : orig;
            cp16(as + (uint32_t)(r * 36 + ca) * 4, A + (size_t)orig * 1024 + k0 + ca);
        }
#pragma unroll
        for (int it = 0; it < 8; ++it) {
            int r = ra + it * 32;
            cp16(bs + (uint32_t)(r * 36 + ca) * 4, B + (size_t)(bn + r) * K + k0 + ca);
        }
        CP_COMMIT();
    };

    issue(0, 0);
    issue(1, 32);
    for (int kt = 0; kt < KT; ++kt) {
        if (kt + 1 < KT) CP_WAIT(1);
        else CP_WAIT(0);
        __syncthreads();
        if (kt + 2 < KT) issue((kt + 2) % 3, (kt + 2) * 32);
        int stage = kt % 3;
        float* As = sm + stage * 4608;
        float* Bs = sm + 13824 + stage * 9216;
#pragma unroll
        for (int ks = 0; ks < 4; ++ks) {
            int kk = ks * 8;
            wmma::fragment<wmma::matrix_a, 16, 16, 8, wmma::precision::tf32, wmma::row_major> af[4];
            wmma::fragment<wmma::matrix_b, 16, 16, 8, wmma::precision::tf32, wmma::col_major> bf[4];
#pragma unroll
            for (int i = 0; i < 4; ++i) {
                wmma::load_matrix_sync(af[i], &As[(warpRow * 64 + i * 16) * 36 + kk], 36);
#pragma unroll
                for (int t = 0; t < af[i].num_elements; ++t)
                    af[i].x[t] = wmma::__float_to_tf32(af[i].x[t]);
            }
#pragma unroll
            for (int j = 0; j < 4; ++j)
                wmma::load_matrix_sync(bf[j], &Bs[(warpCol * 64 + j * 16) * 36 + kk], 36);
#pragma unroll
            for (int i = 0; i < 4; ++i)
#pragma unroll
                for (int j = 0; j < 4; ++j) wmma::mma_sync(acc[i][j], af[i], bf[j], acc[i][j]);
        }
    }
    __syncthreads();

    float* st = &sm[wid * 384];
#pragma unroll
    for (int i = 0; i < 4; ++i) {
#pragma unroll
        for (int j = 0; j < 4; ++j) {
            wmma::store_matrix_sync(st, acc[i][j], 24, wmma::mem_row_major);
            __syncwarp();
            int r = lane >> 1, c8 = (lane & 1) * 8;
            int row_local = warpRow * 64 + i * 16 + r;
            int orig = idxs[row_local];
            int col0 = bn + warpCol * 64 + j * 16;
            if (orig >= 0) {
                float4 v0 = *(float4*)&st[r * 24 + c8];
                float4 v1 = *(float4*)&st[r * 24 + c8 + 4];
                const float* bp = bias + col0 + c8;
                v0.x = rtf(v0.x + bp[0]); v0.y = rtf(v0.y + bp[1]);
                v0.z = rtf(v0.z + bp[2]); v0.w = rtf(v0.w + bp[3]);
                v1.x = rtf(v1.x + bp[4]); v1.y = rtf(v1.y + bp[5]);
                v1.z = rtf(v1.z + bp[6]); v1.w = rtf(v1.w + bp[7]);
                float* cp = C + (size_t)orig * N + col0 + c8;
                *(float4*)cp = v0;
                *(float4*)(cp + 4) = v1;
            }
            __syncwarp();
        }
    }
}

// G1: globally-compacted kv GEMM + q projection
__global__ void __launch_bounds__(256, 1)
g1_kernel(const float* context, const float* Wkv, const float* bkv, float* kvb,
          const float* latents, const float* Wq, const float* bq, float* qh,
          const int* gidx, const int* gcnt) {
    extern __shared__ float sm[];
    int bx = blockIdx.x;
    if (bx < 1024) {
        int tile = bx >> 3;
        if (tile * 128 >= gcnt[0]) return;
        kv_body_g(context, Wkv, bkv, kvb, tile, (bx & 7) * 256, gidx, sm);
    } else {
        int idx = bx - 1024;
        small_body<0, 1, 1, 1, 0>(latents, Wq, bq, qh, 1024, 1024, 1024,
                                  (idx >> 3) * 64, (idx & 7) * 128, sm);
    }
}

// ==================== scores (COMPACTED columns) + chunk stats ========================
__global__ void __launch_bounds__(256)
scores_wmma(const float* __restrict__ qh, const float* __restrict__ kv,
            const int* __restrict__ sidx, const int* __restrict__ scnt,
            float* __restrict__ scores, float* __restrict__ cstat) {
    extern __shared__ float sm[];
    float* Qs = sm;
    float* Ks = sm + 4352;
    int* sx = (int*)(sm + 13056);
    int bh = blockIdx.y;
    int b = bh >> 4, h = bh & 15;
    int s0 = blockIdx.x * 128;
    if (s0 >= scnt[b]) return;
    int tid = threadIdx.x, wid = tid >> 5, lane = tid & 31;

#pragma unroll
    for (int it = 0; it < 4; ++it) {
        int v = tid + it * 256;
        int r = v >> 4, c = (v & 15) * 4;
        *(float4*)&Qs[r * 68 + c] = *(const float4*)(qh + (size_t)(b * 64 + r) * 1024 + h * 64 + c);
    }
#pragma unroll
    for (int it = 0; it < 8; ++it) {
        int v = tid + it * 256;
        int r = v >> 4, c = (v & 15) * 4;
        int orig = sidx[b * 2048 + s0 + r];
        if ((v & 15) == 0) sx[r] = orig;
        int og = orig < 0 ? 0 : orig;
        *(float4*)&Ks[r * 68 + c] =
            *(const float4*)(kv + (size_t)(b * 2048 + og) * 2048 + h * 64 + c);
    }
    __syncthreads();

    int warpRow = wid >> 2, warpCol = wid & 3;
    wmma::fragment<wmma::accumulator, 16, 16, 8, float> acc[2][2];
#pragma unroll
    for (int i = 0; i < 2; ++i)
#pragma unroll
        for (int j = 0; j < 2; ++j) wmma::fill_fragment(acc[i][j], 0.0f);

#pragma unroll
    for (int ks = 0; ks < 8; ++ks) {
        int kk = ks * 8;
        wmma::fragment<wmma::matrix_a, 16, 16, 8, wmma::precision::tf32, wmma::row_major> af[2];
        wmma::fragment<wmma::matrix_b, 16, 16, 8, wmma::precision::tf32, wmma::col_major> bf[2];
#pragma unroll
        for (int i = 0; i < 2; ++i)
            wmma::load_matrix_sync(af[i], &Qs[(warpRow * 32 + i * 16) * 68 + kk], 68);
#pragma unroll
        for (int j = 0; j < 2; ++j)
            wmma::load_matrix_sync(bf[j], &Ks[(warpCol * 32 + j * 16) * 68 + kk], 68);
#pragma unroll
        for (int i = 0; i < 2; ++i)
#pragma unroll
            for (int j = 0; j < 2; ++j) wmma::mma_sync(acc[i][j], af[i], bf[j], acc[i][j]);
    }
    __syncthreads();

    const float NEG = __int_as_float(0xff800000);
    float* st = &sm[wid * 384];
    float* pm = sm + 3072;
    float* ps = sm + 3328;
#pragma unroll
    for (int i = 0; i < 2; ++i) {
        int r = lane >> 1, c8 = (lane & 1) * 8;
        int l = warpRow * 32 + i * 16 + r;
        float4 v0, v1, v2, v3;
        wmma::store_matrix_sync(st, acc[i][0], 24, wmma::mem_row_major);
        __syncwarp();
        v0 = *(float4*)&st[r * 24 + c8];
        v1 = *(float4*)&st[r * 24 + c8 + 4];
        __syncwarp();
        wmma::store_matrix_sync(st, acc[i][1], 24, wmma::mem_row_major);
        __syncwarp();
        v2 = *(float4*)&st[r * 24 + c8];
        v3 = *(float4*)&st[r * 24 + c8 + 4];
        __syncwarp();
        int lc0 = warpCol * 32 + c8;
        int lc1 = lc0 + 16;
        v0.x = sx[lc0 + 0] >= 0 ? v0.x * 0.125f : NEG;
        v0.y = sx[lc0 + 1] >= 0 ? v0.y * 0.125f : NEG;
        v0.z = sx[lc0 + 2] >= 0 ? v0.z * 0.125f : NEG;
        v0.w = sx[lc0 + 3] >= 0 ? v0.w * 0.125f : NEG;
        v1.x = sx[lc0 + 4] >= 0 ? v1.x * 0.125f : NEG;
        v1.y = sx[lc0 + 5] >= 0 ? v1.y * 0.125f : NEG;
        v1.z = sx[lc0 + 6] >= 0 ? v1.z * 0.125f : NEG;
        v1.w = sx[lc0 + 7] >= 0 ? v1.w * 0.125f : NEG;
        v2.x = sx[lc1 + 0] >= 0 ? v2.x * 0.125f : NEG;
        v2.y = sx[lc1 + 1] >= 0 ? v2.y * 0.125f : NEG;
        v2.z = sx[lc1 + 2] >= 0 ? v2.z * 0.125f : NEG;
        v2.w = sx[lc1 + 3] >= 0 ? v2.w * 0.125f : NEG;
        v3.x = sx[lc1 + 4] >= 0 ? v3.x * 0.125f : NEG;
        v3.y = sx[lc1 + 5] >= 0 ? v3.y * 0.125f : NEG;
        v3.z = sx[lc1 + 6] >= 0 ? v3.z * 0.125f : NEG;
        v3.w = sx[lc1 + 7] >= 0 ? v3.w * 0.125f : NEG;
        float* pp = scores + ((size_t)bh * 64 + l) * 2048 + s0 + lc0;
        *(float4*)pp = v0;
        *(float4*)(pp + 4) = v1;
        *(float4*)(pp + 16) = v2;
        *(float4*)(pp + 20) = v3;
        float mx = fmaxf(fmaxf(fmaxf(v0.x, v0.y), fmaxf(v0.z, v0.w)),
                         fmaxf(fmaxf(v1.x, v1.y), fmaxf(v1.z, v1.w)));
        mx = fmaxf(mx, fmaxf(fmaxf(fmaxf(v2.x, v2.y), fmaxf(v2.z, v2.w)),
                             fmaxf(fmaxf(v3.x, v3.y), fmaxf(v3.z, v3.w))));
        float m2 = fmaxf(mx, __shfl_xor_sync(0xffffffffu, mx, 1));
        float m2c = fmaxf(m2, -1e30f);
        float s = expf(v0.x - m2c) + expf(v0.y - m2c) + expf(v0.z - m2c) + expf(v0.w - m2c) +
                  expf(v1.x - m2c) + expf(v1.y - m2c) + expf(v1.z - m2c) + expf(v1.w - m2c) +
                  expf(v2.x - m2c) + expf(v2.y - m2c) + expf(v2.z - m2c) + expf(v2.w - m2c) +
                  expf(v3.x - m2c) + expf(v3.y - m2c) + expf(v3.z - m2c) + expf(v3.w - m2c);
        s += __shfl_xor_sync(0xffffffffu, s, 1);
        if ((lane & 1) == 0) {
            pm[l * 4 + warpCol] = m2;
            ps[l * 4 + warpCol] = s;
        }
    }
    __syncthreads();
    if (tid < 64) {
        float m0 = pm[tid * 4], m1 = pm[tid * 4 + 1], m2 = pm[tid * 4 + 2], m3 = pm[tid * 4 + 3];
        float m = fmaxf(fmaxf(m0, m1), fmaxf(m2, m3));
        float mc = fmaxf(m, -1e30f);
        float S = ps[tid * 4] * expf(m0 - mc) + ps[tid * 4 + 1] * expf(m1 - mc) +
                  ps[tid * 4 + 2] * expf(m2 - mc) + ps[tid * 4 + 3] * expf(m3 - mc);
        float2 o;
        o.x = m;
        o.y = S;
        *(float2*)&cstat[(((size_t)bh * 64 + tid) * 16 + blockIdx.x) * 2] = o;
    }
}

// ---- inline rowstat fold (identical arithmetic to old rowstat_kernel) ----
__device__ __forceinline__ float2 fold_rowstat(const float* __restrict__ cstat,
                                               size_t row, int nch) {
    const float2* c = (const float2*)cstat + row * 16;
    float M = __int_as_float(0xff800000);
    for (int k = 0; k < nch; ++k) M = fmaxf(M, c[k].x);
    float Mc = fmaxf(M, -1e30f);
    float S = 0.f;
    for (int k = 0; k < nch; ++k) S += c[k].y * expf(c[k].x - Mc);
    float2 o;
    o.x = Mc;
    o.y = 1.0f / S;
    return o;
}

// ==================== attn split-K (COMPACTED): inline softmax + inline rowstat =======
__device__ __forceinline__ void attn_body(const float* __restrict__ scores,
                                          const float* __restrict__ kv,
                                          const float* __restrict__ cstat,
                                          const int* __restrict__ sidx,
                                          float* __restrict__ part,
                                          int bh, int split, int cnt, float* sm) {
    int b = bh >> 4, h = bh & 15;
    int base_s = split * 512;
    int ktmax = cnt - base_s;
    ktmax = (ktmax > 512 ? 512 : ktmax) >> 6;
    int tid = threadIdx.x, wid = tid >> 5, lane = tid & 31;
    int warpRow = wid >> 1, warpCol = wid & 1;

    uint32_t s_base = (uint32_t)__cvta_generic_to_shared(sm);
    int ra = tid >> 4, ca = (tid & 15) * 4;
    float* rs_m = sm + 26112;
    float* rs_i = sm + 26176;
    if (tid < 64) {
        float2 v = fold_rowstat(cstat, (size_t)bh * 64 + tid, cnt >> 7);
        rs_m[tid] = v.x;
        rs_i[tid] = v.y;
    }

    wmma::fragment<wmma::accumulator, 16, 16, 8, float> acc[2];
    wmma::fill_fragment(acc[0], 0.0f);
    wmma::fill_fragment(acc[1], 0.0f);

    auto issue = [&](int stage, int s0) {
        uint32_t ps = s_base + (uint32_t)(stage * 4352) * 4;
        uint32_t vs = s_base + (uint32_t)(13056 + stage * 4352) * 4;
#pragma unroll
        for (int it = 0; it < 4; ++it) {
            int r = ra + it * 16;
            cp16(ps + (uint32_t)(r * 68 + ca) * 4,
                 scores + ((size_t)bh * 64 + r) * 2048 + s0 + ca);
            int orig = sidx[b * 2048 + s0 + r];
            orig = orig < 0 ? 0 : orig;
            cp16(vs + (uint32_t)(r * 68 + ca) * 4,
                 kv + (size_t)(b * 2048 + orig) * 2048 + 1024 + h * 64 + ca);
        }
        CP_COMMIT();
    };

    issue(0, base_s);
    if (ktmax > 1) issue(1, base_s + 64);
    for (int kt = 0; kt < ktmax; ++kt) {
        if (kt + 1 < ktmax) CP_WAIT(1);
        else CP_WAIT(0);
        __syncthreads();
        int stage = kt % 3;
        float* Ps = sm + stage * 4352;
#pragma unroll
        for (int it = 0; it < 4; ++it) {
            int rr = ra + it * 16;
            float M = rs_m[rr], I = rs_i[rr];
            float4 v = *(float4*)&Ps[rr * 68 + ca];
            v.x = rtf(expf(v.x - M) * I);
            v.y = rtf(expf(v.y - M) * I);
            v.z = rtf(expf(v.z - M) * I);
            v.w = rtf(expf(v.w - M) * I);
            *(float4*)&Ps[rr * 68 + ca] = v;
        }
        __syncthreads();
        if (kt + 2 < ktmax) issue((kt + 2) % 3, base_s + (kt + 2) * 64);
        float* Vs = sm + 13056 + stage * 4352;
#pragma unroll
        for (int ks = 0; ks < 8; ++ks) {
            int kk = ks * 8;
            wmma::fragment<wmma::matrix_a, 16, 16, 8, wmma::precision::tf32, wmma::row_major> af;
            wmma::fragment<wmma::matrix_b, 16, 16, 8, wmma::precision::tf32, wmma::row_major> bf[2];
            wmma::load_matrix_sync(af, &Ps[(warpRow * 16) * 68 + kk], 68);
#pragma unroll
            for (int j = 0; j < 2; ++j)
                wmma::load_matrix_sync(bf[j], &Vs[kk * 68 + warpCol * 32 + j * 16], 68);
            wmma::mma_sync(acc[0], af, bf[0], acc[0]);
            wmma::mma_sync(acc[1], af, bf[1], acc[1]);
        }
    }
    __syncthreads();

    float* pout = part + (size_t)split * 524288;
    float* st = &sm[wid * 384];
#pragma unroll
    for (int j = 0; j < 2; ++j) {
        wmma::store_matrix_sync(st, acc[j], 24, wmma::mem_row_major);
        __syncwarp();
        int r = lane >> 1, c8 = (lane & 1) * 8;
        int l = warpRow * 16 + r;
        int d0 = warpCol * 32 + j * 16 + c8;
        float4 v0 = *(float4*)&st[r * 24 + c8];
        float4 v1 = *(float4*)&st[r * 24 + c8 + 4];
        float* ap = pout + (size_t)(b * 64 + l) * 1024 + h * 64 + d0;
        *(float4*)ap = v0;
        *(float4*)(ap + 4) = v1;
        __syncwarp();
    }
}

// A1: attn_part (blocks 0..511) + mean_heads scatter w/ inline rowstat (512..1535)
__global__ void __launch_bounds__(256, 2)
a1_kernel(const float* __restrict__ scores, const float* __restrict__ kv,
          const float* __restrict__ cstat, const int* __restrict__ sidx,
          const int* __restrict__ scnt, float* __restrict__ part,
          float* __restrict__ aw) {
    extern __shared__ float sm[];
    __shared__ float2 rs[16];
    int bx = blockIdx.x;
    if (bx < 512) {
        int bh = bx >> 2, split = bx & 3;
        int cnt = scnt[bh >> 4];
        if (split * 512 >= cnt) return;
        attn_body(scores, kv, cstat, sidx, part, bh, split, cnt, sm);
    } else {
        int i = (bx - 512) * 256 + threadIdx.x;
        int s4 = i & 511;
        int l = (i >> 9) & 63;
        int b = i >> 15;
        int cnt = scnt[b];
        if (threadIdx.x < 16)
            rs[threadIdx.x] = fold_rowstat(cstat, (size_t)(b * 16 + threadIdx.x) * 64 + l,
                                           cnt >> 7);
        __syncthreads();
        if (s4 * 4 >= cnt) return;
        int4 orig = *(const int4*)&sidx[b * 2048 + s4 * 4];
        float4 acc = {0.f, 0.f, 0.f, 0.f};
#pragma unroll
        for (int h = 0; h < 16; ++h) {
            size_t row = (size_t)(b * 16 + h) * 64 + l;
            float2 stt = rs[h];
            float4 x = *(const float4*)(scores + row * 2048 + s4 * 4);
            acc.x += expf(x.x - stt.x) * stt.y;
            acc.y += expf(x.y - stt.x) * stt.y;
            acc.z += expf(x.z - stt.x) * stt.y;
            acc.w += expf(x.w - stt.x) * stt.y;
        }
        const float inv = 1.0f / 16.0f;
        float* arow = aw + (size_t)(b * 64 + l) * 2048;
        if (orig.x >= 0) arow[orig.x] = acc.x * inv;
        if (orig.y >= 0) arow[orig.y] = acc.y * inv;
        if (orig.z >= 0) arow[orig.z] = acc.z * inv;
        if (orig.w >= 0) arow[orig.w] = acc.w * inv;
    }
}

// reduce ACTIVE partials -> attn (unrounded; out-proj cvts in-fragment)
__global__ void attn_reduce_kernel(const float* __restrict__ part, const int* __restrict__ scnt,
                                   float* __restrict__ attn) {
    int i = blockIdx.x * 256 + threadIdx.x;
    int b = i >> 14;
    int ns = (scnt[b] + 511) >> 9;
    float4 o = ((const float4*)part)[i];
    if (ns > 1) {
        float4 v = ((const float4*)(part + 524288))[i];
        o.x += v.x; o.y += v.y; o.z += v.z; o.w += v.w;
    }
    if (ns > 2) {
        float4 v = ((const float4*)(part + 1048576))[i];
        o.x += v.x; o.y += v.y; o.z += v.z; o.w += v.w;
    }
    if (ns > 3) {
        float4 v = ((const float4*)(part + 1572864))[i];
        o.x += v.x; o.y += v.y; o.z += v.z; o.w += v.w;
    }
    ((float4*)attn)[i] = o;
}

// ---------------- launch ----------------
extern "C" void kernel_launch(void* const* d_in, const int* in_sizes, int n_in,
                              void* d_out, int out_size) {
    (void)in_sizes; (void)n_in; (void)out_size;
    const float* latents = (const float*)d_in[0];
    const float* context = (const float*)d_in[1];
    const int* cmask = (const int*)d_in[2];
    const float* q_w = (const float*)d_in[3];
    const float* q_b = (const float*)d_in[4];
    const float* k_w = (const float*)d_in[5];
    const float* k_b = (const float*)d_in[6];
    const float* v_w = (const float*)d_in[7];
    const float* v_b = (const float*)d_in[8];
    const float* in_wq = (const float*)d_in[9];
    const float* in_bq = (const float*)d_in[10];
    const float* in_wk = (const float*)d_in[11];
    const float* in_bk = (const float*)d_in[12];
    const float* in_wv = (const float*)d_in[13];
    const float* in_bv = (const float*)d_in[14];
    const float* out_w = (const float*)d_in[15];
    const float* out_b = (const float*)d_in[16];
    const float* ln1_g = (const float*)d_in[17];
    const float* ln1_b = (const float*)d_in[18];
    const float* ln2_g = (const float*)d_in[19];
    const float* ln2_b = (const float*)d_in[20];
    const float* ff_w1 = (const float*)d_in[21];
    const float* ff_b1 = (const float*)d_in[22];
    const float* ff_w2 = (const float*)d_in[23];
    const float* ff_b2 = (const float*)d_in[24];

    float* out = (float*)d_out;
    float* aw_out = out + 512 * 1024;

    void* p;
    cudaGetSymbolAddress(&p, g_Wq);      float* Wq = (float*)p;
    cudaGetSymbolAddress(&p, g_Wkv);     float* Wkv = (float*)p;
    cudaGetSymbolAddress(&p, g_bq);      float* bq = (float*)p;
    cudaGetSymbolAddress(&p, g_bkv);     float* bkv = (float*)p;
    cudaGetSymbolAddress(&p, g_qh);      float* qh = (float*)p;
    cudaGetSymbolAddress(&p, g_kv);      float* kvb = (float*)p;
    cudaGetSymbolAddress(&p, g_scores);  float* scores = (float*)p;
    cudaGetSymbolAddress(&p, g_cstat);   float* cstat = (float*)p;
    cudaGetSymbolAddress(&p, g_part);    float* part = (float*)p;
    cudaGetSymbolAddress(&p, g_attn);    float* attn = (float*)p;
    cudaGetSymbolAddress(&p, g_x);       float* xb = (float*)p;
    cudaGetSymbolAddress(&p, g_h1);      float* h1 = (float*)p;
    cudaGetSymbolAddress(&p, g_sidx);    int* sidx = (int*)p;
    cudaGetSymbolAddress(&p, g_scnt);    int* scnt = (int*)p;
    cudaGetSymbolAddress(&p, g_gidx);    int* gidx = (int*)p;
    cudaGetSymbolAddress(&p, g_gcnt);    int* gcnt = (int*)p;

    cudaFuncSetAttribute(mega_prologue, cudaFuncAttributeMaxDynamicSharedMemorySize, 77824);
    cudaFuncSetAttribute(wmma_gemm_small<1, 1, 0, 1, 1>, cudaFuncAttributeMaxDynamicSharedMemorySize, 82944);
    cudaFuncSetAttribute(wmma_gemm_splitk<1, 1>, cudaFuncAttributeMaxDynamicSharedMemorySize, 82944);
    cudaFuncSetAttribute(g1_kernel, cudaFuncAttributeMaxDynamicSharedMemorySize, 166400);
    cudaFuncSetAttribute(scores_wmma, cudaFuncAttributeMaxDynamicSharedMemorySize, 52736);
    cudaFuncSetAttribute(a1_kernel, cudaFuncAttributeMaxDynamicSharedMemorySize, 104960);

    // ---- mega prologue: fuse GEMMs + biases + compactions + aw zero ----
    mega_prologue<<<4297, 256, 77824>>>(
        in_wq, q_w, Wq,
        in_wk, k_w, Wkv,
        in_wv, v_w, Wkv + 1024 * 1024,
        q_b, in_bq, k_b, in_bk, v_b, in_bv,
        bq, bkv, cmask, sidx, scnt, gidx, gcnt, (float4*)aw_out);

    // ---- G1: globally-compacted kv projection + q projection (merged) ----
    g1_kernel<<<1088, 256, 166400>>>(context, Wkv, bkv, kvb, latents, Wq, bq, qh, gidx, gcnt);

    // ---- attention on compacted columns (rowstat folded inline) ----
    scores_wmma<<<dim3(16, 128), 256, 52736>>>(qh, kvb, sidx, scnt, scores, cstat);
    a1_kernel<<<1536, 256, 104960>>>(scores, kvb, cstat, sidx, scnt, part, aw_out);
    attn_reduce_kernel<<<512, 256>>>(part, scnt, attn);

    // ---- out projection: split-K=2; reduce+bias+LN1 -> xb ----
    wmma_gemm_splitk<1, 1><<<dim3(8, 8, 2), 256, 82944>>>(attn, out_w, part, 1024, 512);
    reduce_ln_kernel<2><<<512, 256>>>(part, out_b, latents, ln1_g, ln1_b, xb);

    // ---- FFN: ff1 (GELU); ff2 split-K=4; reduce+bias+LN2 -> out ----
    wmma_gemm_small<1, 1, 0, 1, 1><<<dim3(32, 8), 256, 82944>>>(xb, ff_w1, ff_b1, h1, 4096, 1024, 1024);
    wmma_gemm_splitk<1, 1><<<dim3(8, 8, 4), 256, 82944>>>(h1, ff_w2, part, 4096, 1024);
    reduce_ln_kernel<4><<<512, 256>>>(part, ff_b2, xb, ln2_g, ln2_b, out);
}